// round 7
// baseline (speedup 1.0000x reference)
#include <cuda_runtime.h>
#include <cuda_bf16.h>
#include <cstdint>
#include <string.h>
#include <math.h>

#define B_SZ 2
#define P_SZ 2048
#define M_SZ 1024
#define H_SZ 16
#define D_SZ 64
#define N3_SZ 3072
#define R_SZ (B_SZ * P_SZ)      // 4096
#define K_SZ M_SZ               // 1024
#define BH_SZ (B_SZ * H_SZ)     // 32

// ---------------- scratch (__device__ globals) -----------------------------
__device__ __nv_bfloat16 g_xhi[(size_t)R_SZ * K_SZ];
__device__ __nv_bfloat16 g_xlo[(size_t)R_SZ * K_SZ];
__device__ __nv_bfloat16 g_wah[(size_t)N3_SZ * K_SZ];
__device__ __nv_bfloat16 g_wal[(size_t)N3_SZ * K_SZ];
__device__ __nv_bfloat16 g_wph[(size_t)M_SZ * K_SZ];
__device__ __nv_bfloat16 g_wpl[(size_t)M_SZ * K_SZ];
__device__ __nv_bfloat16 g_qh[(size_t)BH_SZ * P_SZ * D_SZ];
__device__ __nv_bfloat16 g_ql[(size_t)BH_SZ * P_SZ * D_SZ];
__device__ __nv_bfloat16 g_kh[(size_t)BH_SZ * P_SZ * D_SZ];
__device__ __nv_bfloat16 g_kl[(size_t)BH_SZ * P_SZ * D_SZ];
__device__ __nv_bfloat16 g_vh[(size_t)BH_SZ * P_SZ * D_SZ];
__device__ __nv_bfloat16 g_vl[(size_t)BH_SZ * P_SZ * D_SZ];
__device__ __nv_bfloat16 g_zh[(size_t)R_SZ * K_SZ];
__device__ __nv_bfloat16 g_zl[(size_t)R_SZ * K_SZ];

// ---------------- PTX helpers (base ISA) -----------------------------------
__device__ __forceinline__ uint32_t smem_u32(const void* p) {
    uint32_t a;
    asm("{ .reg .u64 t; cvta.to.shared.u64 t, %1; cvt.u32.u64 %0, t; }" : "=r"(a) : "l"(p));
    return a;
}
__device__ __forceinline__ void ldsm4(uint32_t* r, uint32_t addr) {
    asm volatile("ldmatrix.sync.aligned.m8n8.x4.shared.b16 {%0,%1,%2,%3}, [%4];"
                 : "=r"(r[0]), "=r"(r[1]), "=r"(r[2]), "=r"(r[3]) : "r"(addr));
}
__device__ __forceinline__ void ldsm4t(uint32_t* r, uint32_t addr) {
    asm volatile("ldmatrix.sync.aligned.m8n8.x4.trans.shared.b16 {%0,%1,%2,%3}, [%4];"
                 : "=r"(r[0]), "=r"(r[1]), "=r"(r[2]), "=r"(r[3]) : "r"(addr));
}
__device__ __forceinline__ void mma16816(float* c, const uint32_t* a, const uint32_t* b) {
    asm volatile(
        "mma.sync.aligned.m16n8k16.row.col.f32.bf16.bf16.f32 "
        "{%0,%1,%2,%3}, {%4,%5,%6,%7}, {%8,%9}, {%0,%1,%2,%3};"
        : "+f"(c[0]), "+f"(c[1]), "+f"(c[2]), "+f"(c[3])
        : "r"(a[0]), "r"(a[1]), "r"(a[2]), "r"(a[3]), "r"(b[0]), "r"(b[1]));
}
__device__ __forceinline__ void cpasync16(uint32_t saddr, const void* gaddr) {
    asm volatile("cp.async.cg.shared.global [%0], [%1], 16;" :: "r"(saddr), "l"(gaddr) : "memory");
}
__device__ __forceinline__ void sts32(uint32_t addr, uint32_t v) {
    asm volatile("st.shared.b32 [%0], %1;" :: "r"(addr), "r"(v) : "memory");
}
__device__ __forceinline__ void sts64(uint32_t addr, float a, float b) {
    asm volatile("st.shared.v2.f32 [%0], {%1,%2};" :: "r"(addr), "f"(a), "f"(b) : "memory");
}
__device__ __forceinline__ uint4 lds128(uint32_t addr) {
    uint4 v;
    asm volatile("ld.shared.v4.b32 {%0,%1,%2,%3}, [%4];"
                 : "=r"(v.x), "=r"(v.y), "=r"(v.z), "=r"(v.w) : "r"(addr));
    return v;
}
__device__ __forceinline__ void split2(float a, float b, uint32_t& hu, uint32_t& lu) {
    __nv_bfloat16 ha = __float2bfloat16(a), hb = __float2bfloat16(b);
    float ra = a - __bfloat162float(ha), rb = b - __bfloat162float(hb);
    __nv_bfloat162 H = __halves2bfloat162(ha, hb);
    __nv_bfloat162 L = __floats2bfloat162_rn(ra, rb);
    memcpy(&hu, &H, 4); memcpy(&lu, &L, 4);
}

// ---------------- fp32 -> bf16 hi/lo split ---------------------------------
struct alignas(8) bf16x4 { __nv_bfloat162 a, b; };

__global__ __launch_bounds__(256) void split_kernel(
    const float* __restrict__ in, __nv_bfloat16* __restrict__ hi,
    __nv_bfloat16* __restrict__ lo, int n4)
{
    int i = blockIdx.x * 256 + threadIdx.x;
    if (i >= n4) return;
    float4 v = ((const float4*)in)[i];
    float h0 = __bfloat162float(__float2bfloat16(v.x));
    float h1 = __bfloat162float(__float2bfloat16(v.y));
    float h2 = __bfloat162float(__float2bfloat16(v.z));
    float h3 = __bfloat162float(__float2bfloat16(v.w));
    bf16x4 H, L;
    H.a = __floats2bfloat162_rn(h0, h1);
    H.b = __floats2bfloat162_rn(h2, h3);
    L.a = __floats2bfloat162_rn(v.x - h0, v.y - h1);
    L.b = __floats2bfloat162_rn(v.z - h2, v.w - h3);
    ((bf16x4*)hi)[i] = H;
    ((bf16x4*)lo)[i] = L;
}

__global__ __launch_bounds__(256) void tsplit_kernel(
    const float* __restrict__ W, __nv_bfloat16* __restrict__ hi,
    __nv_bfloat16* __restrict__ lo, int K, int N)
{
    __shared__ float s[32][33];
    const int n0 = blockIdx.x * 32, k0 = blockIdx.y * 32;
    const int tx = threadIdx.x & 31, ty = threadIdx.x >> 5;
    #pragma unroll
    for (int i = 0; i < 4; i++)
        s[ty + 8 * i][tx] = W[(size_t)(k0 + ty + 8 * i) * N + n0 + tx];
    __syncthreads();
    #pragma unroll
    for (int i = 0; i < 4; i++) {
        int r = ty + 8 * i;
        float v = s[tx][r];
        float h = __bfloat162float(__float2bfloat16(v));
        size_t o = (size_t)(n0 + r) * K + k0 + tx;
        hi[o] = __float2bfloat16(h);
        lo[o] = __float2bfloat16(v - h);
    }
}

// ---------------- split-bf16 mma GEMM: 4 warps, 64x64 warp tile ------------
#define GK_CH   (K_SZ / 32)          // 32 chunks
#define GT_TILE 10240                // 128 rows * 80 B
#define GT_STG  (4 * GT_TILE)
#define GT_SMEM (2 * GT_STG)         // 81920 B (2-stage; reused by epilogue)

// Q pre-scale: 1/sqrt(64) * log2(e)  (softmax runs base-2)
#define QSCALE (0.125f * 1.44269504088896f)

template<int MODE>
__global__ __launch_bounds__(128) void gemm_mma_kernel(
    const __nv_bfloat16* __restrict__ Ah, const __nv_bfloat16* __restrict__ Al,
    const __nv_bfloat16* __restrict__ Bh, const __nv_bfloat16* __restrict__ Bl,
    const float* __restrict__ bias, float* __restrict__ C, int N,
    __nv_bfloat16* __restrict__ qh, __nv_bfloat16* __restrict__ ql,
    __nv_bfloat16* __restrict__ kh, __nv_bfloat16* __restrict__ kl,
    __nv_bfloat16* __restrict__ vh, __nv_bfloat16* __restrict__ vl)
{
    extern __shared__ char smraw[];
    const uint32_t sbase = smem_u32(smraw);

    const int tid = threadIdx.x;
    const int wid = tid >> 5, lane = tid & 31;
    const int wm = wid & 1, wn = wid >> 1;          // wn in {0,1}: 64 cols
    const int g = lane >> 2, t = lane & 3;
    const int row0 = blockIdx.y << 7;
    const int col0 = blockIdx.x << 7;

    const __nv_bfloat16* srcs[4] = {Ah, Al, Bh, Bl};

    auto load_chunk = [&](int c, int s) {
        const int k0 = c << 5;
        const uint32_t stg = sbase + (uint32_t)s * GT_STG;
        #pragma unroll
        for (int arr = 0; arr < 4; arr++) {
            const __nv_bfloat16* src = srcs[arr];
            const int rbase = (arr < 2) ? row0 : col0;
            const uint32_t tb = stg + (uint32_t)arr * GT_TILE;
            #pragma unroll
            for (int it = 0; it < 4; it++) {
                int id = it * 128 + tid, r = id >> 2, q = id & 3;
                cpasync16(tb + (uint32_t)(r * 80 + q * 16),
                          src + (size_t)(rbase + r) * K_SZ + k0 + q * 8);
            }
        }
    };

    float acc[4][8][4] = {};
    const int a_row = lane & 15;
    const int a_cb  = (lane >> 4) << 4;
    const int b2_row = (lane & 7) + ((lane >> 4) << 3);
    const int b2_cb  = ((lane >> 3) & 1) << 4;

    load_chunk(0, 0);
    asm volatile("cp.async.commit_group;" ::: "memory");

    for (int c = 0; c < GK_CH; c++) {
        const int s = c & 1;
        if (c + 1 < GK_CH) {
            load_chunk(c + 1, s ^ 1);
            asm volatile("cp.async.commit_group;" ::: "memory");
            asm volatile("cp.async.wait_group 1;" ::: "memory");
        } else {
            asm volatile("cp.async.wait_group 0;" ::: "memory");
        }
        __syncthreads();

        const uint32_t stg = sbase + (uint32_t)s * GT_STG;
        const uint32_t tAh = stg, tAl = stg + GT_TILE;
        const uint32_t tBh = stg + 2 * GT_TILE, tBl = stg + 3 * GT_TILE;

        #pragma unroll
        for (int ks = 0; ks < 2; ks++) {
            const int kb = ks << 5;
            uint32_t ah[4][4], al[4][4];
            #pragma unroll
            for (int mt = 0; mt < 4; mt++) {
                const uint32_t ro = (uint32_t)((wm * 64 + mt * 16 + a_row) * 80 + kb + a_cb);
                ldsm4(ah[mt], tAh + ro);
                ldsm4(al[mt], tAl + ro);
            }
            #pragma unroll
            for (int np = 0; np < 4; np++) {
                uint32_t bh4[4], bl4[4];
                const uint32_t ro = (uint32_t)((wn * 64 + np * 16 + b2_row) * 80 + kb + b2_cb);
                ldsm4(bh4, tBh + ro);
                ldsm4(bl4, tBl + ro);
                #pragma unroll
                for (int mt = 0; mt < 4; mt++) {
                    mma16816(acc[mt][2 * np],     ah[mt], &bh4[0]);
                    mma16816(acc[mt][2 * np],     ah[mt], &bl4[0]);
                    mma16816(acc[mt][2 * np],     al[mt], &bh4[0]);
                    mma16816(acc[mt][2 * np + 1], ah[mt], &bh4[2]);
                    mma16816(acc[mt][2 * np + 1], ah[mt], &bl4[2]);
                    mma16816(acc[mt][2 * np + 1], al[mt], &bh4[2]);
                }
            }
        }
        __syncthreads();
    }

    if (MODE == 1) {
        // ---- stage bf16 hi/lo in smem (272 B rows, bank-conflict-free) ----
        const uint32_t hi0 = sbase, lo0 = sbase + 128 * 272;   // 69632 <= 81920
        #pragma unroll
        for (int mt = 0; mt < 4; mt++) {
            const int rl = wm * 64 + mt * 16 + g;
            #pragma unroll
            for (int nt = 0; nt < 8; nt++) {
                const int cl = wn * 64 + nt * 8 + 2 * t;
                const int col = col0 + cl;
                const float b0 = bias[col], b1 = bias[col + 1];
                float v0 = acc[mt][nt][0] + b0, v1 = acc[mt][nt][1] + b1;
                float v2 = acc[mt][nt][2] + b0, v3 = acc[mt][nt][3] + b1;
                if (col < M_SZ) { v0 *= QSCALE; v1 *= QSCALE; v2 *= QSCALE; v3 *= QSCALE; }
                uint32_t hu, lu;
                split2(v0, v1, hu, lu);
                sts32(hi0 + (uint32_t)(rl * 272 + cl * 2), hu);
                sts32(lo0 + (uint32_t)(rl * 272 + cl * 2), lu);
                split2(v2, v3, hu, lu);
                sts32(hi0 + (uint32_t)((rl + 8) * 272 + cl * 2), hu);
                sts32(lo0 + (uint32_t)((rl + 8) * 272 + cl * 2), lu);
            }
        }
        __syncthreads();
        // ---- coalesced copy out (uint4 along contiguous head rows) ----
        #pragma unroll
        for (int it = 0; it < 16; it++) {
            const int id = it * 128 + tid, r = id >> 4, s = id & 15;
            const int col = col0 + s * 8;
            const int slice = col >> 10, hh = (col >> 6) & 15, dd = col & 63;
            __nv_bfloat16* oh = (slice == 0) ? qh : (slice == 1) ? kh : vh;
            __nv_bfloat16* ol = (slice == 0) ? ql : (slice == 1) ? kl : vl;
            const int row = row0 + r;
            const int ba = row >> 11, pa = row & 2047;
            const size_t oa = ((size_t)(ba * H_SZ + hh) * P_SZ + pa) * 64 + dd;
            uint4 vh4 = lds128(hi0 + (uint32_t)(r * 272 + s * 16));
            uint4 vl4 = lds128(lo0 + (uint32_t)(r * 272 + s * 16));
            *(uint4*)(oh + oa) = vh4;
            *(uint4*)(ol + oa) = vl4;
        }
    } else {
        // ---- stage fp32 in smem (528 B rows), then coalesced stores ----
        #pragma unroll
        for (int mt = 0; mt < 4; mt++) {
            const int rl = wm * 64 + mt * 16 + g;
            #pragma unroll
            for (int nt = 0; nt < 8; nt++) {
                const int cl = wn * 64 + nt * 8 + 2 * t;
                const int col = col0 + cl;
                const float b0 = bias[col], b1 = bias[col + 1];
                sts64(sbase + (uint32_t)(rl * 528 + cl * 4),
                      acc[mt][nt][0] + b0, acc[mt][nt][1] + b1);
                sts64(sbase + (uint32_t)((rl + 8) * 528 + cl * 4),
                      acc[mt][nt][2] + b0, acc[mt][nt][3] + b1);
            }
        }
        __syncthreads();
        #pragma unroll
        for (int it = 0; it < 32; it++) {
            const int id = it * 128 + tid, r = id >> 5, s = id & 31;
            uint4 v = lds128(sbase + (uint32_t)(r * 528 + s * 16));
            *(uint4*)(C + (size_t)(row0 + r) * N + col0 + s * 4) = v;
        }
    }
}

// ---------------- tensor-core flash attention: 4 warps x 32 q-rows ---------
#define AT_ROWB 144
#define AT_QTILE (128 * AT_ROWB)        // 18432
#define AT_KTILE (64 * AT_ROWB)         // 9216
#define AT_KV0   (2 * AT_QTILE)         // 36864
#define AT_STG   (4 * AT_KTILE)         // 36864
#define AT_SMEM  (AT_KV0 + 2 * AT_STG)  // 110592

__global__ __launch_bounds__(128) void attn_mma_kernel(
    const __nv_bfloat16* __restrict__ qh, const __nv_bfloat16* __restrict__ ql,
    const __nv_bfloat16* __restrict__ kh, const __nv_bfloat16* __restrict__ kl,
    const __nv_bfloat16* __restrict__ vh, const __nv_bfloat16* __restrict__ vl,
    __nv_bfloat16* __restrict__ zh, __nv_bfloat16* __restrict__ zl)
{
    extern __shared__ char smraw[];
    const uint32_t sb = smem_u32(smraw);
    const int tid = threadIdx.x, w = tid >> 5, lane = tid & 31;
    const int g = lane >> 2, t = lane & 3;
    const int qt = blockIdx.x, bh = blockIdx.y;
    const int q0 = qt << 7;
    const size_t hb = (size_t)bh * P_SZ * 64;

    {   // Q hi/lo tile: 128 rows x 64 cols
        const __nv_bfloat16* Qh = qh + hb + (size_t)q0 * 64;
        const __nv_bfloat16* Ql = ql + hb + (size_t)q0 * 64;
        #pragma unroll
        for (int it = 0; it < 8; it++) {
            int id = it * 128 + tid, r = id >> 3, c = id & 7;
            cpasync16(sb + (uint32_t)(r * AT_ROWB + c * 16), Qh + r * 64 + c * 8);
            cpasync16(sb + AT_QTILE + (uint32_t)(r * AT_ROWB + c * 16), Ql + r * 64 + c * 8);
        }
    }
    const __nv_bfloat16* kvsrc[4] = {kh + hb, kl + hb, vh + hb, vl + hb};
    auto load_kv = [&](int kvt, int s) {
        const uint32_t stg = sb + AT_KV0 + (uint32_t)s * AT_STG;
        const size_t rb = (size_t)(kvt << 6) * 64;
        #pragma unroll
        for (int a = 0; a < 4; a++)
            #pragma unroll
            for (int it = 0; it < 4; it++) {
                int id = it * 128 + tid, r = id >> 3, c = id & 7;
                cpasync16(stg + (uint32_t)(a * AT_KTILE + r * AT_ROWB + c * 16),
                          kvsrc[a] + rb + r * 64 + c * 8);
            }
    };
    const int ntiles = 2 * qt + 2;
    load_kv(0, 0);
    asm volatile("cp.async.commit_group;" ::: "memory");

    uint32_t qhf[2][4][4], qlf[2][4][4];
    float oacc[2][8][4] = {};
    float mrow[2][2], lrow[2][2];
    #pragma unroll
    for (int mt = 0; mt < 2; mt++) {
        mrow[mt][0] = -1e30f; mrow[mt][1] = -1e30f;
        lrow[mt][0] = 0.f;    lrow[mt][1] = 0.f;
    }
    const int arow = (lane & 7) + ((lane >> 3) & 1) * 8;
    const int achk = lane >> 4;
    const int wrow_min = q0 + 32 * w;
    const int wrow_max = wrow_min + 31;

    for (int kvt = 0; kvt < ntiles; kvt++) {
        const int s = kvt & 1;
        if (kvt + 1 < ntiles) {
            load_kv(kvt + 1, s ^ 1);
            asm volatile("cp.async.commit_group;" ::: "memory");
            asm volatile("cp.async.wait_group 1;" ::: "memory");
        } else {
            asm volatile("cp.async.wait_group 0;" ::: "memory");
        }
        __syncthreads();
        if (kvt == 0) {
            #pragma unroll
            for (int mt = 0; mt < 2; mt++)
                #pragma unroll
                for (int ks = 0; ks < 4; ks++) {
                    uint32_t ad = sb + (uint32_t)((32 * w + 16 * mt + arow) * AT_ROWB +
                                                  (2 * ks + achk) * 16);
                    ldsm4(qhf[mt][ks], ad);
                    ldsm4(qlf[mt][ks], ad + AT_QTILE);
                }
        }
        const int c_base = kvt << 6;
        if (c_base <= wrow_max) {
            const uint32_t kb = sb + AT_KV0 + (uint32_t)s * AT_STG;

            float sacc[2][8][4] = {};
            #pragma unroll
            for (int j = 0; j < 8; j++) {
                #pragma unroll
                for (int cp = 0; cp < 2; cp++) {
                    uint32_t khf[4], klf[4];
                    uint32_t ad = kb + (uint32_t)((8 * j + (lane & 7)) * AT_ROWB +
                                                  (4 * cp + (lane >> 3)) * 16);
                    ldsm4(khf, ad);
                    ldsm4(klf, ad + AT_KTILE);
                    #pragma unroll
                    for (int mt = 0; mt < 2; mt++) {
                        mma16816(sacc[mt][j], qhf[mt][2 * cp], &khf[0]);
                        mma16816(sacc[mt][j], qhf[mt][2 * cp], &klf[0]);
                        mma16816(sacc[mt][j], qlf[mt][2 * cp], &khf[0]);
                        mma16816(sacc[mt][j], qhf[mt][2 * cp + 1], &khf[2]);
                        mma16816(sacc[mt][j], qhf[mt][2 * cp + 1], &klf[2]);
                        mma16816(sacc[mt][j], qlf[mt][2 * cp + 1], &khf[2]);
                    }
                }
            }

            if (c_base + 63 > wrow_min) {
                #pragma unroll
                for (int mt = 0; mt < 2; mt++) {
                    const int lr0 = wrow_min + 16 * mt + g;
                    #pragma unroll
                    for (int j = 0; j < 8; j++) {
                        const int c0 = c_base + 8 * j + 2 * t;
                        if (c0     > lr0)     sacc[mt][j][0] = -1e30f;
                        if (c0 + 1 > lr0)     sacc[mt][j][1] = -1e30f;
                        if (c0     > lr0 + 8) sacc[mt][j][2] = -1e30f;
                        if (c0 + 1 > lr0 + 8) sacc[mt][j][3] = -1e30f;
                    }
                }
            }

            #pragma unroll
            for (int mt = 0; mt < 2; mt++) {
                float mx0 = -1e30f, mx1 = -1e30f;
                #pragma unroll
                for (int j = 0; j < 8; j++) {
                    mx0 = fmaxf(mx0, fmaxf(sacc[mt][j][0], sacc[mt][j][1]));
                    mx1 = fmaxf(mx1, fmaxf(sacc[mt][j][2], sacc[mt][j][3]));
                }
                mx0 = fmaxf(mx0, __shfl_xor_sync(0xffffffffu, mx0, 1));
                mx0 = fmaxf(mx0, __shfl_xor_sync(0xffffffffu, mx0, 2));
                mx1 = fmaxf(mx1, __shfl_xor_sync(0xffffffffu, mx1, 1));
                mx1 = fmaxf(mx1, __shfl_xor_sync(0xffffffffu, mx1, 2));
                const float mn0 = fmaxf(mrow[mt][0], mx0), mn1 = fmaxf(mrow[mt][1], mx1);
                const float al0 = exp2f(mrow[mt][0] - mn0), al1 = exp2f(mrow[mt][1] - mn1);
                float sum0 = 0.f, sum1 = 0.f;
                #pragma unroll
                for (int j = 0; j < 8; j++) {
                    sacc[mt][j][0] = exp2f(sacc[mt][j][0] - mn0);
                    sacc[mt][j][1] = exp2f(sacc[mt][j][1] - mn0);
                    sacc[mt][j][2] = exp2f(sacc[mt][j][2] - mn1);
                    sacc[mt][j][3] = exp2f(sacc[mt][j][3] - mn1);
                    sum0 += sacc[mt][j][0] + sacc[mt][j][1];
                    sum1 += sacc[mt][j][2] + sacc[mt][j][3];
                }
                sum0 += __shfl_xor_sync(0xffffffffu, sum0, 1);
                sum0 += __shfl_xor_sync(0xffffffffu, sum0, 2);
                sum1 += __shfl_xor_sync(0xffffffffu, sum1, 1);
                sum1 += __shfl_xor_sync(0xffffffffu, sum1, 2);
                lrow[mt][0] = lrow[mt][0] * al0 + sum0; mrow[mt][0] = mn0;
                lrow[mt][1] = lrow[mt][1] * al1 + sum1; mrow[mt][1] = mn1;
                #pragma unroll
                for (int j = 0; j < 8; j++) {
                    oacc[mt][j][0] *= al0; oacc[mt][j][1] *= al0;
                    oacc[mt][j][2] *= al1; oacc[mt][j][3] *= al1;
                }
            }

            #pragma unroll
            for (int s2 = 0; s2 < 4; s2++) {
                uint32_t pah[2][4], pal[2][4];
                #pragma unroll
                for (int mt = 0; mt < 2; mt++) {
                    split2(sacc[mt][2 * s2][0],     sacc[mt][2 * s2][1],     pah[mt][0], pal[mt][0]);
                    split2(sacc[mt][2 * s2][2],     sacc[mt][2 * s2][3],     pah[mt][1], pal[mt][1]);
                    split2(sacc[mt][2 * s2 + 1][0], sacc[mt][2 * s2 + 1][1], pah[mt][2], pal[mt][2]);
                    split2(sacc[mt][2 * s2 + 1][2], sacc[mt][2 * s2 + 1][3], pah[mt][3], pal[mt][3]);
                }
                #pragma unroll
                for (int jp = 0; jp < 4; jp++) {
                    uint32_t vhf[4], vlf[4];
                    uint32_t ad = kb + 2 * AT_KTILE +
                        (uint32_t)((16 * s2 + (lane & 15)) * AT_ROWB + (2 * jp + (lane >> 4)) * 16);
                    ldsm4t(vhf, ad);
                    ldsm4t(vlf, ad + AT_KTILE);
                    #pragma unroll
                    for (int mt = 0; mt < 2; mt++) {
                        mma16816(oacc[mt][2 * jp],     pah[mt], &vhf[0]);
                        mma16816(oacc[mt][2 * jp],     pah[mt], &vlf[0]);
                        mma16816(oacc[mt][2 * jp],     pal[mt], &vhf[0]);
                        mma16816(oacc[mt][2 * jp + 1], pah[mt], &vhf[2]);
                        mma16816(oacc[mt][2 * jp + 1], pah[mt], &vlf[2]);
                        mma16816(oacc[mt][2 * jp + 1], pal[mt], &vhf[2]);
                    }
                }
            }
        }
        __syncthreads();
    }

    // ---- epilogue: stage O hi/lo in smem, then coalesced 16B stores ----
    const uint32_t oh0 = sb + AT_KV0, ol0 = oh0 + 128 * AT_ROWB;
    #pragma unroll
    for (int mt = 0; mt < 2; mt++) {
        const float i0 = 1.f / lrow[mt][0], i1 = 1.f / lrow[mt][1];
        const int rl = 32 * w + 16 * mt + g;
        #pragma unroll
        for (int j = 0; j < 8; j++) {
            const int cl = 8 * j + 2 * t;
            uint32_t hu, lu;
            split2(oacc[mt][j][0] * i0, oacc[mt][j][1] * i0, hu, lu);
            sts32(oh0 + (uint32_t)(rl * AT_ROWB + cl * 2), hu);
            sts32(ol0 + (uint32_t)(rl * AT_ROWB + cl * 2), lu);
            split2(oacc[mt][j][2] * i1, oacc[mt][j][3] * i1, hu, lu);
            sts32(oh0 + (uint32_t)((rl + 8) * AT_ROWB + cl * 2), hu);
            sts32(ol0 + (uint32_t)((rl + 8) * AT_ROWB + cl * 2), lu);
        }
    }
    __syncthreads();
    const int b = bh >> 4, h = bh & 15;
    #pragma unroll
    for (int it = 0; it < 8; it++) {
        const int id = it * 128 + tid, r = id >> 3, s = id & 7;
        const size_t dst = ((size_t)b * P_SZ + q0 + r) * K_SZ + h * 64 + s * 8;
        uint4 vh4 = lds128(oh0 + (uint32_t)(r * AT_ROWB + s * 16));
        uint4 vl4 = lds128(ol0 + (uint32_t)(r * AT_ROWB + s * 16));
        *(uint4*)(zh + dst) = vh4;
        *(uint4*)(zl + dst) = vl4;
    }
}

// ---------------------------------------------------------------------------
extern "C" void kernel_launch(void* const* d_in, const int* in_sizes, int n_in,
                              void* d_out, int out_size)
{
    (void)in_sizes; (void)n_in; (void)out_size;
    const float* x      = (const float*)d_in[0];
    const float* W_attn = (const float*)d_in[1];
    const float* b_attn = (const float*)d_in[2];
    const float* W_proj = (const float*)d_in[3];
    const float* b_proj = (const float*)d_in[4];
    float* out = (float*)d_out;

    __nv_bfloat16 *xhi, *xlo, *wah, *wal, *wph, *wpl;
    __nv_bfloat16 *qh, *ql, *kh, *kl, *vh, *vl, *zh, *zl;
    cudaGetSymbolAddress((void**)&xhi, g_xhi);
    cudaGetSymbolAddress((void**)&xlo, g_xlo);
    cudaGetSymbolAddress((void**)&wah, g_wah);
    cudaGetSymbolAddress((void**)&wal, g_wal);
    cudaGetSymbolAddress((void**)&wph, g_wph);
    cudaGetSymbolAddress((void**)&wpl, g_wpl);
    cudaGetSymbolAddress((void**)&qh,  g_qh);
    cudaGetSymbolAddress((void**)&ql,  g_ql);
    cudaGetSymbolAddress((void**)&kh,  g_kh);
    cudaGetSymbolAddress((void**)&kl,  g_kl);
    cudaGetSymbolAddress((void**)&vh,  g_vh);
    cudaGetSymbolAddress((void**)&vl,  g_vl);
    cudaGetSymbolAddress((void**)&zh,  g_zh);
    cudaGetSymbolAddress((void**)&zl,  g_zl);

    cudaFuncSetAttribute(gemm_mma_kernel<0>,
                         cudaFuncAttributeMaxDynamicSharedMemorySize, GT_SMEM);
    cudaFuncSetAttribute(gemm_mma_kernel<1>,
                         cudaFuncAttributeMaxDynamicSharedMemorySize, GT_SMEM);
    cudaFuncSetAttribute(attn_mma_kernel,
                         cudaFuncAttributeMaxDynamicSharedMemorySize, AT_SMEM);

    split_kernel<<<(R_SZ * K_SZ / 4 + 255) / 256, 256>>>(x, xhi, xlo, R_SZ * K_SZ / 4);
    tsplit_kernel<<<dim3(N3_SZ / 32, K_SZ / 32), 256>>>(W_attn, wah, wal, K_SZ, N3_SZ);
    tsplit_kernel<<<dim3(M_SZ / 32, K_SZ / 32), 256>>>(W_proj, wph, wpl, K_SZ, M_SZ);

    gemm_mma_kernel<1><<<dim3(N3_SZ / 128, R_SZ / 128), 128, GT_SMEM>>>(
        xhi, xlo, wah, wal, b_attn, nullptr, N3_SZ, qh, ql, kh, kl, vh, vl);

    attn_mma_kernel<<<dim3(P_SZ / 128, BH_SZ), 128, AT_SMEM>>>(
        qh, ql, kh, kl, vh, vl, zh, zl);

    gemm_mma_kernel<0><<<dim3(M_SZ / 128, R_SZ / 128), 128, GT_SMEM>>>(
        zh, zl, wph, wpl, b_proj, out, M_SZ,
        nullptr, nullptr, nullptr, nullptr, nullptr, nullptr);
}

// round 8
// speedup vs baseline: 1.0232x; 1.0232x over previous
#include <cuda_runtime.h>
#include <cuda_bf16.h>
#include <cstdint>
#include <string.h>
#include <math.h>

#define B_SZ 2
#define P_SZ 2048
#define M_SZ 1024
#define H_SZ 16
#define D_SZ 64
#define N3_SZ 3072
#define R_SZ (B_SZ * P_SZ)      // 4096
#define K_SZ M_SZ               // 1024
#define BH_SZ (B_SZ * H_SZ)     // 32

// ---------------- scratch (__device__ globals) -----------------------------
__device__ __nv_bfloat16 g_xhi[(size_t)R_SZ * K_SZ];
__device__ __nv_bfloat16 g_xlo[(size_t)R_SZ * K_SZ];
__device__ __nv_bfloat16 g_wah[(size_t)N3_SZ * K_SZ];
__device__ __nv_bfloat16 g_wal[(size_t)N3_SZ * K_SZ];
__device__ __nv_bfloat16 g_wph[(size_t)M_SZ * K_SZ];
__device__ __nv_bfloat16 g_wpl[(size_t)M_SZ * K_SZ];
__device__ __nv_bfloat16 g_qh[(size_t)BH_SZ * P_SZ * D_SZ];
__device__ __nv_bfloat16 g_ql[(size_t)BH_SZ * P_SZ * D_SZ];
__device__ __nv_bfloat16 g_kh[(size_t)BH_SZ * P_SZ * D_SZ];
__device__ __nv_bfloat16 g_kl[(size_t)BH_SZ * P_SZ * D_SZ];
__device__ __nv_bfloat16 g_vh[(size_t)BH_SZ * P_SZ * D_SZ];
__device__ __nv_bfloat16 g_vl[(size_t)BH_SZ * P_SZ * D_SZ];
__device__ __nv_bfloat16 g_zh[(size_t)R_SZ * K_SZ];
__device__ __nv_bfloat16 g_zl[(size_t)R_SZ * K_SZ];

// ---------------- PTX helpers (base ISA) -----------------------------------
__device__ __forceinline__ uint32_t smem_u32(const void* p) {
    uint32_t a;
    asm("{ .reg .u64 t; cvta.to.shared.u64 t, %1; cvt.u32.u64 %0, t; }" : "=r"(a) : "l"(p));
    return a;
}
__device__ __forceinline__ void ldsm4(uint32_t* r, uint32_t addr) {
    asm volatile("ldmatrix.sync.aligned.m8n8.x4.shared.b16 {%0,%1,%2,%3}, [%4];"
                 : "=r"(r[0]), "=r"(r[1]), "=r"(r[2]), "=r"(r[3]) : "r"(addr));
}
__device__ __forceinline__ void ldsm4t(uint32_t* r, uint32_t addr) {
    asm volatile("ldmatrix.sync.aligned.m8n8.x4.trans.shared.b16 {%0,%1,%2,%3}, [%4];"
                 : "=r"(r[0]), "=r"(r[1]), "=r"(r[2]), "=r"(r[3]) : "r"(addr));
}
__device__ __forceinline__ void mma16816(float* c, const uint32_t* a, const uint32_t* b) {
    asm volatile(
        "mma.sync.aligned.m16n8k16.row.col.f32.bf16.bf16.f32 "
        "{%0,%1,%2,%3}, {%4,%5,%6,%7}, {%8,%9}, {%0,%1,%2,%3};"
        : "+f"(c[0]), "+f"(c[1]), "+f"(c[2]), "+f"(c[3])
        : "r"(a[0]), "r"(a[1]), "r"(a[2]), "r"(a[3]), "r"(b[0]), "r"(b[1]));
}
__device__ __forceinline__ void cpasync16(uint32_t saddr, const void* gaddr) {
    asm volatile("cp.async.cg.shared.global [%0], [%1], 16;" :: "r"(saddr), "l"(gaddr) : "memory");
}
__device__ __forceinline__ void sts32(uint32_t addr, uint32_t v) {
    asm volatile("st.shared.b32 [%0], %1;" :: "r"(addr), "r"(v) : "memory");
}
__device__ __forceinline__ void sts64(uint32_t addr, float a, float b) {
    asm volatile("st.shared.v2.f32 [%0], {%1,%2};" :: "r"(addr), "f"(a), "f"(b) : "memory");
}
__device__ __forceinline__ uint4 lds128(uint32_t addr) {
    uint4 v;
    asm volatile("ld.shared.v4.b32 {%0,%1,%2,%3}, [%4];"
                 : "=r"(v.x), "=r"(v.y), "=r"(v.z), "=r"(v.w) : "r"(addr));
    return v;
}
__device__ __forceinline__ void split2(float a, float b, uint32_t& hu, uint32_t& lu) {
    __nv_bfloat16 ha = __float2bfloat16(a), hb = __float2bfloat16(b);
    float ra = a - __bfloat162float(ha), rb = b - __bfloat162float(hb);
    __nv_bfloat162 H = __halves2bfloat162(ha, hb);
    __nv_bfloat162 L = __floats2bfloat162_rn(ra, rb);
    memcpy(&hu, &H, 4); memcpy(&lu, &L, 4);
}

// ---------------- fp32 -> bf16 hi/lo split ---------------------------------
struct alignas(8) bf16x4 { __nv_bfloat162 a, b; };

__global__ __launch_bounds__(256) void split_kernel(
    const float* __restrict__ in, __nv_bfloat16* __restrict__ hi,
    __nv_bfloat16* __restrict__ lo, int n4)
{
    int i = blockIdx.x * 256 + threadIdx.x;
    if (i >= n4) return;
    float4 v = ((const float4*)in)[i];
    float h0 = __bfloat162float(__float2bfloat16(v.x));
    float h1 = __bfloat162float(__float2bfloat16(v.y));
    float h2 = __bfloat162float(__float2bfloat16(v.z));
    float h3 = __bfloat162float(__float2bfloat16(v.w));
    bf16x4 H, L;
    H.a = __floats2bfloat162_rn(h0, h1);
    H.b = __floats2bfloat162_rn(h2, h3);
    L.a = __floats2bfloat162_rn(v.x - h0, v.y - h1);
    L.b = __floats2bfloat162_rn(v.z - h2, v.w - h3);
    ((bf16x4*)hi)[i] = H;
    ((bf16x4*)lo)[i] = L;
}

__global__ __launch_bounds__(256) void tsplit_kernel(
    const float* __restrict__ W, __nv_bfloat16* __restrict__ hi,
    __nv_bfloat16* __restrict__ lo, int K, int N)
{
    __shared__ float s[32][33];
    const int n0 = blockIdx.x * 32, k0 = blockIdx.y * 32;
    const int tx = threadIdx.x & 31, ty = threadIdx.x >> 5;
    #pragma unroll
    for (int i = 0; i < 4; i++)
        s[ty + 8 * i][tx] = W[(size_t)(k0 + ty + 8 * i) * N + n0 + tx];
    __syncthreads();
    #pragma unroll
    for (int i = 0; i < 4; i++) {
        int r = ty + 8 * i;
        float v = s[tx][r];
        float h = __bfloat162float(__float2bfloat16(v));
        size_t o = (size_t)(n0 + r) * K + k0 + tx;
        hi[o] = __float2bfloat16(h);
        lo[o] = __float2bfloat16(v - h);
    }
}

// ---------------- split-bf16 mma GEMM: 4 warps, 64x64 warp tile ------------
#define GK_CH   (K_SZ / 32)          // 32 chunks
#define GT_TILE 10240                // 128 rows * 80 B
#define GT_STG  (4 * GT_TILE)
#define GT_SMEM (2 * GT_STG)         // 81920 B (2-stage; reused by epilogue)

// Q pre-scale: 1/sqrt(64) * log2(e)  (softmax runs base-2)
#define QSCALE (0.125f * 1.44269504088896f)

template<int MODE>
__global__ __launch_bounds__(128) void gemm_mma_kernel(
    const __nv_bfloat16* __restrict__ Ah, const __nv_bfloat16* __restrict__ Al,
    const __nv_bfloat16* __restrict__ Bh, const __nv_bfloat16* __restrict__ Bl,
    const float* __restrict__ bias, float* __restrict__ C, int N,
    __nv_bfloat16* __restrict__ qh, __nv_bfloat16* __restrict__ ql,
    __nv_bfloat16* __restrict__ kh, __nv_bfloat16* __restrict__ kl,
    __nv_bfloat16* __restrict__ vh, __nv_bfloat16* __restrict__ vl)
{
    extern __shared__ char smraw[];
    const uint32_t sbase = smem_u32(smraw);

    const int tid = threadIdx.x;
    const int wid = tid >> 5, lane = tid & 31;
    const int wm = wid & 1, wn = wid >> 1;
    const int g = lane >> 2, t = lane & 3;
    const int row0 = blockIdx.y << 7;
    const int col0 = blockIdx.x << 7;

    const __nv_bfloat16* srcs[4] = {Ah, Al, Bh, Bl};

    auto load_chunk = [&](int c, int s) {
        const int k0 = c << 5;
        const uint32_t stg = sbase + (uint32_t)s * GT_STG;
        #pragma unroll
        for (int arr = 0; arr < 4; arr++) {
            const __nv_bfloat16* src = srcs[arr];
            const int rbase = (arr < 2) ? row0 : col0;
            const uint32_t tb = stg + (uint32_t)arr * GT_TILE;
            #pragma unroll
            for (int it = 0; it < 4; it++) {
                int id = it * 128 + tid, r = id >> 2, q = id & 3;
                cpasync16(tb + (uint32_t)(r * 80 + q * 16),
                          src + (size_t)(rbase + r) * K_SZ + k0 + q * 8);
            }
        }
    };

    float acc[4][8][4] = {};
    const int a_row = lane & 15;
    const int a_cb  = (lane >> 4) << 4;
    const int b2_row = (lane & 7) + ((lane >> 4) << 3);
    const int b2_cb  = ((lane >> 3) & 1) << 4;

    load_chunk(0, 0);
    asm volatile("cp.async.commit_group;" ::: "memory");

    for (int c = 0; c < GK_CH; c++) {
        const int s = c & 1;
        if (c + 1 < GK_CH) {
            load_chunk(c + 1, s ^ 1);
            asm volatile("cp.async.commit_group;" ::: "memory");
            asm volatile("cp.async.wait_group 1;" ::: "memory");
        } else {
            asm volatile("cp.async.wait_group 0;" ::: "memory");
        }
        __syncthreads();

        const uint32_t stg = sbase + (uint32_t)s * GT_STG;
        const uint32_t tAh = stg, tAl = stg + GT_TILE;
        const uint32_t tBh = stg + 2 * GT_TILE, tBl = stg + 3 * GT_TILE;

        #pragma unroll
        for (int ks = 0; ks < 2; ks++) {
            const int kb = ks << 5;
            uint32_t ah[4][4], al[4][4], bh[4][4], bl[4][4];
            #pragma unroll
            for (int mt = 0; mt < 4; mt++) {
                const uint32_t ro = (uint32_t)((wm * 64 + mt * 16 + a_row) * 80 + kb + a_cb);
                ldsm4(ah[mt], tAh + ro);
                ldsm4(al[mt], tAl + ro);
            }
            #pragma unroll
            for (int np = 0; np < 4; np++) {
                const uint32_t ro = (uint32_t)((wn * 64 + np * 16 + b2_row) * 80 + kb + b2_cb);
                ldsm4(bh[np], tBh + ro);
                ldsm4(bl[np], tBl + ro);
            }
            // term-major passes: each acc touched once per pass (RAW distance 32)
            #pragma unroll
            for (int np = 0; np < 4; np++)
                #pragma unroll
                for (int mt = 0; mt < 4; mt++) {
                    mma16816(acc[mt][2 * np],     ah[mt], &bh[np][0]);
                    mma16816(acc[mt][2 * np + 1], ah[mt], &bh[np][2]);
                }
            #pragma unroll
            for (int np = 0; np < 4; np++)
                #pragma unroll
                for (int mt = 0; mt < 4; mt++) {
                    mma16816(acc[mt][2 * np],     ah[mt], &bl[np][0]);
                    mma16816(acc[mt][2 * np + 1], ah[mt], &bl[np][2]);
                }
            #pragma unroll
            for (int np = 0; np < 4; np++)
                #pragma unroll
                for (int mt = 0; mt < 4; mt++) {
                    mma16816(acc[mt][2 * np],     al[mt], &bh[np][0]);
                    mma16816(acc[mt][2 * np + 1], al[mt], &bh[np][2]);
                }
        }
        __syncthreads();
    }

    if (MODE == 1) {
        const uint32_t hi0 = sbase, lo0 = sbase + 128 * 272;
        #pragma unroll
        for (int mt = 0; mt < 4; mt++) {
            const int rl = wm * 64 + mt * 16 + g;
            #pragma unroll
            for (int nt = 0; nt < 8; nt++) {
                const int cl = wn * 64 + nt * 8 + 2 * t;
                const int col = col0 + cl;
                const float b0 = bias[col], b1 = bias[col + 1];
                float v0 = acc[mt][nt][0] + b0, v1 = acc[mt][nt][1] + b1;
                float v2 = acc[mt][nt][2] + b0, v3 = acc[mt][nt][3] + b1;
                if (col < M_SZ) { v0 *= QSCALE; v1 *= QSCALE; v2 *= QSCALE; v3 *= QSCALE; }
                uint32_t hu, lu;
                split2(v0, v1, hu, lu);
                sts32(hi0 + (uint32_t)(rl * 272 + cl * 2), hu);
                sts32(lo0 + (uint32_t)(rl * 272 + cl * 2), lu);
                split2(v2, v3, hu, lu);
                sts32(hi0 + (uint32_t)((rl + 8) * 272 + cl * 2), hu);
                sts32(lo0 + (uint32_t)((rl + 8) * 272 + cl * 2), lu);
            }
        }
        __syncthreads();
        #pragma unroll
        for (int it = 0; it < 16; it++) {
            const int id = it * 128 + tid, r = id >> 4, s = id & 15;
            const int col = col0 + s * 8;
            const int slice = col >> 10, hh = (col >> 6) & 15, dd = col & 63;
            __nv_bfloat16* oh = (slice == 0) ? qh : (slice == 1) ? kh : vh;
            __nv_bfloat16* ol = (slice == 0) ? ql : (slice == 1) ? kl : vl;
            const int row = row0 + r;
            const int ba = row >> 11, pa = row & 2047;
            const size_t oa = ((size_t)(ba * H_SZ + hh) * P_SZ + pa) * 64 + dd;
            uint4 vh4 = lds128(hi0 + (uint32_t)(r * 272 + s * 16));
            uint4 vl4 = lds128(lo0 + (uint32_t)(r * 272 + s * 16));
            *(uint4*)(oh + oa) = vh4;
            *(uint4*)(ol + oa) = vl4;
        }
    } else {
        #pragma unroll
        for (int mt = 0; mt < 4; mt++) {
            const int rl = wm * 64 + mt * 16 + g;
            #pragma unroll
            for (int nt = 0; nt < 8; nt++) {
                const int cl = wn * 64 + nt * 8 + 2 * t;
                const int col = col0 + cl;
                const float b0 = bias[col], b1 = bias[col + 1];
                sts64(sbase + (uint32_t)(rl * 528 + cl * 4),
                      acc[mt][nt][0] + b0, acc[mt][nt][1] + b1);
                sts64(sbase + (uint32_t)((rl + 8) * 528 + cl * 4),
                      acc[mt][nt][2] + b0, acc[mt][nt][3] + b1);
            }
        }
        __syncthreads();
        #pragma unroll
        for (int it = 0; it < 32; it++) {
            const int id = it * 128 + tid, r = id >> 5, s = id & 31;
            uint4 v = lds128(sbase + (uint32_t)(r * 528 + s * 16));
            *(uint4*)(C + (size_t)(row0 + r) * N + col0 + s * 4) = v;
        }
    }
}

// ---------------- tensor-core flash attention: 4 warps x 32 q-rows ---------
#define AT_ROWB 144
#define AT_QTILE (128 * AT_ROWB)        // 18432
#define AT_KTILE (64 * AT_ROWB)         // 9216
#define AT_KV0   (2 * AT_QTILE)         // 36864
#define AT_STG   (4 * AT_KTILE)         // 36864
#define AT_SMEM  (AT_KV0 + 2 * AT_STG)  // 110592

__global__ __launch_bounds__(128) void attn_mma_kernel(
    const __nv_bfloat16* __restrict__ qh, const __nv_bfloat16* __restrict__ ql,
    const __nv_bfloat16* __restrict__ kh, const __nv_bfloat16* __restrict__ kl,
    const __nv_bfloat16* __restrict__ vh, const __nv_bfloat16* __restrict__ vl,
    __nv_bfloat16* __restrict__ zh, __nv_bfloat16* __restrict__ zl)
{
    extern __shared__ char smraw[];
    const uint32_t sb = smem_u32(smraw);
    const int tid = threadIdx.x, w = tid >> 5, lane = tid & 31;
    const int g = lane >> 2, t = lane & 3;
    const int qt = blockIdx.x, bh = blockIdx.y;
    const int q0 = qt << 7;
    const size_t hb = (size_t)bh * P_SZ * 64;

    {
        const __nv_bfloat16* Qh = qh + hb + (size_t)q0 * 64;
        const __nv_bfloat16* Ql = ql + hb + (size_t)q0 * 64;
        #pragma unroll
        for (int it = 0; it < 8; it++) {
            int id = it * 128 + tid, r = id >> 3, c = id & 7;
            cpasync16(sb + (uint32_t)(r * AT_ROWB + c * 16), Qh + r * 64 + c * 8);
            cpasync16(sb + AT_QTILE + (uint32_t)(r * AT_ROWB + c * 16), Ql + r * 64 + c * 8);
        }
    }
    const __nv_bfloat16* kvsrc[4] = {kh + hb, kl + hb, vh + hb, vl + hb};
    auto load_kv = [&](int kvt, int s) {
        const uint32_t stg = sb + AT_KV0 + (uint32_t)s * AT_STG;
        const size_t rb = (size_t)(kvt << 6) * 64;
        #pragma unroll
        for (int a = 0; a < 4; a++)
            #pragma unroll
            for (int it = 0; it < 4; it++) {
                int id = it * 128 + tid, r = id >> 3, c = id & 7;
                cpasync16(stg + (uint32_t)(a * AT_KTILE + r * AT_ROWB + c * 16),
                          kvsrc[a] + rb + r * 64 + c * 8);
            }
    };
    const int ntiles = 2 * qt + 2;
    load_kv(0, 0);
    asm volatile("cp.async.commit_group;" ::: "memory");

    uint32_t qhf[2][4][4], qlf[2][4][4];
    float oacc[2][8][4] = {};
    float mrow[2][2], lrow[2][2];
    #pragma unroll
    for (int mt = 0; mt < 2; mt++) {
        mrow[mt][0] = -1e30f; mrow[mt][1] = -1e30f;
        lrow[mt][0] = 0.f;    lrow[mt][1] = 0.f;
    }
    const int arow = (lane & 7) + ((lane >> 3) & 1) * 8;
    const int achk = lane >> 4;
    const int wrow_min = q0 + 32 * w;
    const int wrow_max = wrow_min + 31;

    for (int kvt = 0; kvt < ntiles; kvt++) {
        const int s = kvt & 1;
        if (kvt + 1 < ntiles) {
            load_kv(kvt + 1, s ^ 1);
            asm volatile("cp.async.commit_group;" ::: "memory");
            asm volatile("cp.async.wait_group 1;" ::: "memory");
        } else {
            asm volatile("cp.async.wait_group 0;" ::: "memory");
        }
        __syncthreads();
        if (kvt == 0) {
            #pragma unroll
            for (int mt = 0; mt < 2; mt++)
                #pragma unroll
                for (int ks = 0; ks < 4; ks++) {
                    uint32_t ad = sb + (uint32_t)((32 * w + 16 * mt + arow) * AT_ROWB +
                                                  (2 * ks + achk) * 16);
                    ldsm4(qhf[mt][ks], ad);
                    ldsm4(qlf[mt][ks], ad + AT_QTILE);
                }
        }
        const int c_base = kvt << 6;
        if (c_base <= wrow_max) {
            const uint32_t kb = sb + AT_KV0 + (uint32_t)s * AT_STG;

            // ---- S = Q K^T: hoist both k16 chunks, term-major passes ----
            float sacc[2][8][4] = {};
            #pragma unroll
            for (int j = 0; j < 8; j++) {
                uint32_t khf[2][4], klf[2][4];
                #pragma unroll
                for (int cp = 0; cp < 2; cp++) {
                    uint32_t ad = kb + (uint32_t)((8 * j + (lane & 7)) * AT_ROWB +
                                                  (4 * cp + (lane >> 3)) * 16);
                    ldsm4(khf[cp], ad);
                    ldsm4(klf[cp], ad + AT_KTILE);
                }
                #pragma unroll
                for (int cp = 0; cp < 2; cp++)
                    #pragma unroll
                    for (int mt = 0; mt < 2; mt++) {
                        mma16816(sacc[mt][j], qhf[mt][2 * cp],     &khf[cp][0]);
                        mma16816(sacc[mt][j], qhf[mt][2 * cp + 1], &khf[cp][2]);
                    }
                #pragma unroll
                for (int cp = 0; cp < 2; cp++)
                    #pragma unroll
                    for (int mt = 0; mt < 2; mt++) {
                        mma16816(sacc[mt][j], qhf[mt][2 * cp],     &klf[cp][0]);
                        mma16816(sacc[mt][j], qhf[mt][2 * cp + 1], &klf[cp][2]);
                    }
                #pragma unroll
                for (int cp = 0; cp < 2; cp++)
                    #pragma unroll
                    for (int mt = 0; mt < 2; mt++) {
                        mma16816(sacc[mt][j], qlf[mt][2 * cp],     &khf[cp][0]);
                        mma16816(sacc[mt][j], qlf[mt][2 * cp + 1], &khf[cp][2]);
                    }
            }

            if (c_base + 63 > wrow_min) {
                #pragma unroll
                for (int mt = 0; mt < 2; mt++) {
                    const int lr0 = wrow_min + 16 * mt + g;
                    #pragma unroll
                    for (int j = 0; j < 8; j++) {
                        const int c0 = c_base + 8 * j + 2 * t;
                        if (c0     > lr0)     sacc[mt][j][0] = -1e30f;
                        if (c0 + 1 > lr0)     sacc[mt][j][1] = -1e30f;
                        if (c0     > lr0 + 8) sacc[mt][j][2] = -1e30f;
                        if (c0 + 1 > lr0 + 8) sacc[mt][j][3] = -1e30f;
                    }
                }
            }

            #pragma unroll
            for (int mt = 0; mt < 2; mt++) {
                float mx0 = -1e30f, mx1 = -1e30f;
                #pragma unroll
                for (int j = 0; j < 8; j++) {
                    mx0 = fmaxf(mx0, fmaxf(sacc[mt][j][0], sacc[mt][j][1]));
                    mx1 = fmaxf(mx1, fmaxf(sacc[mt][j][2], sacc[mt][j][3]));
                }
                mx0 = fmaxf(mx0, __shfl_xor_sync(0xffffffffu, mx0, 1));
                mx0 = fmaxf(mx0, __shfl_xor_sync(0xffffffffu, mx0, 2));
                mx1 = fmaxf(mx1, __shfl_xor_sync(0xffffffffu, mx1, 1));
                mx1 = fmaxf(mx1, __shfl_xor_sync(0xffffffffu, mx1, 2));
                const float mn0 = fmaxf(mrow[mt][0], mx0), mn1 = fmaxf(mrow[mt][1], mx1);
                const float al0 = exp2f(mrow[mt][0] - mn0), al1 = exp2f(mrow[mt][1] - mn1);
                float sum0 = 0.f, sum1 = 0.f;
                #pragma unroll
                for (int j = 0; j < 8; j++) {
                    sacc[mt][j][0] = exp2f(sacc[mt][j][0] - mn0);
                    sacc[mt][j][1] = exp2f(sacc[mt][j][1] - mn0);
                    sacc[mt][j][2] = exp2f(sacc[mt][j][2] - mn1);
                    sacc[mt][j][3] = exp2f(sacc[mt][j][3] - mn1);
                    sum0 += sacc[mt][j][0] + sacc[mt][j][1];
                    sum1 += sacc[mt][j][2] + sacc[mt][j][3];
                }
                sum0 += __shfl_xor_sync(0xffffffffu, sum0, 1);
                sum0 += __shfl_xor_sync(0xffffffffu, sum0, 2);
                sum1 += __shfl_xor_sync(0xffffffffu, sum1, 1);
                sum1 += __shfl_xor_sync(0xffffffffu, sum1, 2);
                lrow[mt][0] = lrow[mt][0] * al0 + sum0; mrow[mt][0] = mn0;
                lrow[mt][1] = lrow[mt][1] * al1 + sum1; mrow[mt][1] = mn1;
                #pragma unroll
                for (int j = 0; j < 8; j++) {
                    oacc[mt][j][0] *= al0; oacc[mt][j][1] *= al0;
                    oacc[mt][j][2] *= al1; oacc[mt][j][3] *= al1;
                }
            }

            // ---- O += P V: hoist all V frags per s2, term-major passes ----
            #pragma unroll
            for (int s2 = 0; s2 < 4; s2++) {
                uint32_t pah[2][4], pal[2][4];
                #pragma unroll
                for (int mt = 0; mt < 2; mt++) {
                    split2(sacc[mt][2 * s2][0],     sacc[mt][2 * s2][1],     pah[mt][0], pal[mt][0]);
                    split2(sacc[mt][2 * s2][2],     sacc[mt][2 * s2][3],     pah[mt][1], pal[mt][1]);
                    split2(sacc[mt][2 * s2 + 1][0], sacc[mt][2 * s2 + 1][1], pah[mt][2], pal[mt][2]);
                    split2(sacc[mt][2 * s2 + 1][2], sacc[mt][2 * s2 + 1][3], pah[mt][3], pal[mt][3]);
                }
                uint32_t vhf[4][4], vlf[4][4];
                #pragma unroll
                for (int jp = 0; jp < 4; jp++) {
                    uint32_t ad = kb + 2 * AT_KTILE +
                        (uint32_t)((16 * s2 + (lane & 15)) * AT_ROWB + (2 * jp + (lane >> 4)) * 16);
                    ldsm4t(vhf[jp], ad);
                    ldsm4t(vlf[jp], ad + AT_KTILE);
                }
                #pragma unroll
                for (int jp = 0; jp < 4; jp++)
                    #pragma unroll
                    for (int mt = 0; mt < 2; mt++) {
                        mma16816(oacc[mt][2 * jp],     pah[mt], &vhf[jp][0]);
                        mma16816(oacc[mt][2 * jp + 1], pah[mt], &vhf[jp][2]);
                    }
                #pragma unroll
                for (int jp = 0; jp < 4; jp++)
                    #pragma unroll
                    for (int mt = 0; mt < 2; mt++) {
                        mma16816(oacc[mt][2 * jp],     pah[mt], &vlf[jp][0]);
                        mma16816(oacc[mt][2 * jp + 1], pah[mt], &vlf[jp][2]);
                    }
                #pragma unroll
                for (int jp = 0; jp < 4; jp++)
                    #pragma unroll
                    for (int mt = 0; mt < 2; mt++) {
                        mma16816(oacc[mt][2 * jp],     pal[mt], &vhf[jp][0]);
                        mma16816(oacc[mt][2 * jp + 1], pal[mt], &vhf[jp][2]);
                    }
            }
        }
        __syncthreads();
    }

    const uint32_t oh0 = sb + AT_KV0, ol0 = oh0 + 128 * AT_ROWB;
    #pragma unroll
    for (int mt = 0; mt < 2; mt++) {
        const float i0 = 1.f / lrow[mt][0], i1 = 1.f / lrow[mt][1];
        const int rl = 32 * w + 16 * mt + g;
        #pragma unroll
        for (int j = 0; j < 8; j++) {
            const int cl = 8 * j + 2 * t;
            uint32_t hu, lu;
            split2(oacc[mt][j][0] * i0, oacc[mt][j][1] * i0, hu, lu);
            sts32(oh0 + (uint32_t)(rl * AT_ROWB + cl * 2), hu);
            sts32(ol0 + (uint32_t)(rl * AT_ROWB + cl * 2), lu);
            split2(oacc[mt][j][2] * i1, oacc[mt][j][3] * i1, hu, lu);
            sts32(oh0 + (uint32_t)((rl + 8) * AT_ROWB + cl * 2), hu);
            sts32(ol0 + (uint32_t)((rl + 8) * AT_ROWB + cl * 2), lu);
        }
    }
    __syncthreads();
    const int b = bh >> 4, h = bh & 15;
    #pragma unroll
    for (int it = 0; it < 8; it++) {
        const int id = it * 128 + tid, r = id >> 3, s = id & 7;
        const size_t dst = ((size_t)b * P_SZ + q0 + r) * K_SZ + h * 64 + s * 8;
        uint4 vh4 = lds128(oh0 + (uint32_t)(r * AT_ROWB + s * 16));
        uint4 vl4 = lds128(ol0 + (uint32_t)(r * AT_ROWB + s * 16));
        *(uint4*)(zh + dst) = vh4;
        *(uint4*)(zl + dst) = vl4;
    }
}

// ---------------------------------------------------------------------------
extern "C" void kernel_launch(void* const* d_in, const int* in_sizes, int n_in,
                              void* d_out, int out_size)
{
    (void)in_sizes; (void)n_in; (void)out_size;
    const float* x      = (const float*)d_in[0];
    const float* W_attn = (const float*)d_in[1];
    const float* b_attn = (const float*)d_in[2];
    const float* W_proj = (const float*)d_in[3];
    const float* b_proj = (const float*)d_in[4];
    float* out = (float*)d_out;

    __nv_bfloat16 *xhi, *xlo, *wah, *wal, *wph, *wpl;
    __nv_bfloat16 *qh, *ql, *kh, *kl, *vh, *vl, *zh, *zl;
    cudaGetSymbolAddress((void**)&xhi, g_xhi);
    cudaGetSymbolAddress((void**)&xlo, g_xlo);
    cudaGetSymbolAddress((void**)&wah, g_wah);
    cudaGetSymbolAddress((void**)&wal, g_wal);
    cudaGetSymbolAddress((void**)&wph, g_wph);
    cudaGetSymbolAddress((void**)&wpl, g_wpl);
    cudaGetSymbolAddress((void**)&qh,  g_qh);
    cudaGetSymbolAddress((void**)&ql,  g_ql);
    cudaGetSymbolAddress((void**)&kh,  g_kh);
    cudaGetSymbolAddress((void**)&kl,  g_kl);
    cudaGetSymbolAddress((void**)&vh,  g_vh);
    cudaGetSymbolAddress((void**)&vl,  g_vl);
    cudaGetSymbolAddress((void**)&zh,  g_zh);
    cudaGetSymbolAddress((void**)&zl,  g_zl);

    cudaFuncSetAttribute(gemm_mma_kernel<0>,
                         cudaFuncAttributeMaxDynamicSharedMemorySize, GT_SMEM);
    cudaFuncSetAttribute(gemm_mma_kernel<1>,
                         cudaFuncAttributeMaxDynamicSharedMemorySize, GT_SMEM);
    cudaFuncSetAttribute(attn_mma_kernel,
                         cudaFuncAttributeMaxDynamicSharedMemorySize, AT_SMEM);

    split_kernel<<<(R_SZ * K_SZ / 4 + 255) / 256, 256>>>(x, xhi, xlo, R_SZ * K_SZ / 4);
    tsplit_kernel<<<dim3(N3_SZ / 32, K_SZ / 32), 256>>>(W_attn, wah, wal, K_SZ, N3_SZ);
    tsplit_kernel<<<dim3(M_SZ / 32, K_SZ / 32), 256>>>(W_proj, wph, wpl, K_SZ, M_SZ);

    gemm_mma_kernel<1><<<dim3(N3_SZ / 128, R_SZ / 128), 128, GT_SMEM>>>(
        xhi, xlo, wah, wal, b_attn, nullptr, N3_SZ, qh, ql, kh, kl, vh, vl);

    attn_mma_kernel<<<dim3(P_SZ / 128, BH_SZ), 128, AT_SMEM>>>(
        qh, ql, kh, kl, vh, vl, zh, zl);

    gemm_mma_kernel<0><<<dim3(M_SZ / 128, R_SZ / 128), 128, GT_SMEM>>>(
        zh, zl, wph, wpl, b_proj, out, M_SZ,
        nullptr, nullptr, nullptr, nullptr, nullptr, nullptr);
}

// round 9
// speedup vs baseline: 1.1617x; 1.1354x over previous
#include <cuda_runtime.h>
#include <cuda_bf16.h>
#include <cstdint>
#include <string.h>
#include <math.h>

#define B_SZ 2
#define P_SZ 2048
#define M_SZ 1024
#define H_SZ 16
#define D_SZ 64
#define N3_SZ 3072
#define R_SZ (B_SZ * P_SZ)      // 4096
#define K_SZ M_SZ               // 1024
#define BH_SZ (B_SZ * H_SZ)     // 32

// ---------------- scratch (__device__ globals) -----------------------------
__device__ __nv_bfloat16 g_xhi[(size_t)R_SZ * K_SZ];
__device__ __nv_bfloat16 g_xlo[(size_t)R_SZ * K_SZ];
__device__ __nv_bfloat16 g_wah[(size_t)N3_SZ * K_SZ];
__device__ __nv_bfloat16 g_wal[(size_t)N3_SZ * K_SZ];
__device__ __nv_bfloat16 g_wph[(size_t)M_SZ * K_SZ];
__device__ __nv_bfloat16 g_wpl[(size_t)M_SZ * K_SZ];
__device__ __nv_bfloat16 g_qh[(size_t)BH_SZ * P_SZ * D_SZ];
__device__ __nv_bfloat16 g_ql[(size_t)BH_SZ * P_SZ * D_SZ];
__device__ __nv_bfloat16 g_kh[(size_t)BH_SZ * P_SZ * D_SZ];
__device__ __nv_bfloat16 g_kl[(size_t)BH_SZ * P_SZ * D_SZ];
__device__ __nv_bfloat16 g_vh[(size_t)BH_SZ * P_SZ * D_SZ];
__device__ __nv_bfloat16 g_vl[(size_t)BH_SZ * P_SZ * D_SZ];
__device__ __nv_bfloat16 g_zh[(size_t)R_SZ * K_SZ];
__device__ __nv_bfloat16 g_zl[(size_t)R_SZ * K_SZ];

// ---------------- PTX helpers (base ISA) -----------------------------------
__device__ __forceinline__ uint32_t smem_u32(const void* p) {
    uint32_t a;
    asm("{ .reg .u64 t; cvta.to.shared.u64 t, %1; cvt.u32.u64 %0, t; }" : "=r"(a) : "l"(p));
    return a;
}
__device__ __forceinline__ void ldsm4(uint32_t* r, uint32_t addr) {
    asm volatile("ldmatrix.sync.aligned.m8n8.x4.shared.b16 {%0,%1,%2,%3}, [%4];"
                 : "=r"(r[0]), "=r"(r[1]), "=r"(r[2]), "=r"(r[3]) : "r"(addr));
}
__device__ __forceinline__ void ldsm4t(uint32_t* r, uint32_t addr) {
    asm volatile("ldmatrix.sync.aligned.m8n8.x4.trans.shared.b16 {%0,%1,%2,%3}, [%4];"
                 : "=r"(r[0]), "=r"(r[1]), "=r"(r[2]), "=r"(r[3]) : "r"(addr));
}
__device__ __forceinline__ void mma16816(float* c, const uint32_t* a, const uint32_t* b) {
    asm volatile(
        "mma.sync.aligned.m16n8k16.row.col.f32.bf16.bf16.f32 "
        "{%0,%1,%2,%3}, {%4,%5,%6,%7}, {%8,%9}, {%0,%1,%2,%3};"
        : "+f"(c[0]), "+f"(c[1]), "+f"(c[2]), "+f"(c[3])
        : "r"(a[0]), "r"(a[1]), "r"(a[2]), "r"(a[3]), "r"(b[0]), "r"(b[1]));
}
__device__ __forceinline__ void cpasync16(uint32_t saddr, const void* gaddr) {
    asm volatile("cp.async.cg.shared.global [%0], [%1], 16;" :: "r"(saddr), "l"(gaddr) : "memory");
}
__device__ __forceinline__ void sts32(uint32_t addr, uint32_t v) {
    asm volatile("st.shared.b32 [%0], %1;" :: "r"(addr), "r"(v) : "memory");
}
__device__ __forceinline__ void sts64(uint32_t addr, float a, float b) {
    asm volatile("st.shared.v2.f32 [%0], {%1,%2};" :: "r"(addr), "f"(a), "f"(b) : "memory");
}
__device__ __forceinline__ uint4 lds128(uint32_t addr) {
    uint4 v;
    asm volatile("ld.shared.v4.b32 {%0,%1,%2,%3}, [%4];"
                 : "=r"(v.x), "=r"(v.y), "=r"(v.z), "=r"(v.w) : "r"(addr));
    return v;
}
__device__ __forceinline__ void split2(float a, float b, uint32_t& hu, uint32_t& lu) {
    __nv_bfloat16 ha = __float2bfloat16(a), hb = __float2bfloat16(b);
    float ra = a - __bfloat162float(ha), rb = b - __bfloat162float(hb);
    __nv_bfloat162 H = __halves2bfloat162(ha, hb);
    __nv_bfloat162 L = __floats2bfloat162_rn(ra, rb);
    memcpy(&hu, &H, 4); memcpy(&lu, &L, 4);
}

// ---------------- fp32 -> bf16 hi/lo split ---------------------------------
struct alignas(8) bf16x4 { __nv_bfloat162 a, b; };

__global__ __launch_bounds__(256) void split_kernel(
    const float* __restrict__ in, __nv_bfloat16* __restrict__ hi,
    __nv_bfloat16* __restrict__ lo, int n4)
{
    int i = blockIdx.x * 256 + threadIdx.x;
    if (i >= n4) return;
    float4 v = ((const float4*)in)[i];
    float h0 = __bfloat162float(__float2bfloat16(v.x));
    float h1 = __bfloat162float(__float2bfloat16(v.y));
    float h2 = __bfloat162float(__float2bfloat16(v.z));
    float h3 = __bfloat162float(__float2bfloat16(v.w));
    bf16x4 H, L;
    H.a = __floats2bfloat162_rn(h0, h1);
    H.b = __floats2bfloat162_rn(h2, h3);
    L.a = __floats2bfloat162_rn(v.x - h0, v.y - h1);
    L.b = __floats2bfloat162_rn(v.z - h2, v.w - h3);
    ((bf16x4*)hi)[i] = H;
    ((bf16x4*)lo)[i] = L;
}

__global__ __launch_bounds__(256) void tsplit_kernel(
    const float* __restrict__ W, __nv_bfloat16* __restrict__ hi,
    __nv_bfloat16* __restrict__ lo, int K, int N)
{
    __shared__ float s[32][33];
    const int n0 = blockIdx.x * 32, k0 = blockIdx.y * 32;
    const int tx = threadIdx.x & 31, ty = threadIdx.x >> 5;
    #pragma unroll
    for (int i = 0; i < 4; i++)
        s[ty + 8 * i][tx] = W[(size_t)(k0 + ty + 8 * i) * N + n0 + tx];
    __syncthreads();
    #pragma unroll
    for (int i = 0; i < 4; i++) {
        int r = ty + 8 * i;
        float v = s[tx][r];
        float h = __bfloat162float(__float2bfloat16(v));
        size_t o = (size_t)(n0 + r) * K + k0 + tx;
        hi[o] = __float2bfloat16(h);
        lo[o] = __float2bfloat16(v - h);
    }
}

// ---------------- split-bf16 mma GEMM: 4 warps, 64x64 warp tile ------------
#define GK_CH   (K_SZ / 32)          // 32 chunks
#define GT_TILE 10240                // 128 rows * 80 B
#define GT_STG  (4 * GT_TILE)
#define GT_SMEM (2 * GT_STG)         // 81920 B

// Q pre-scale: 1/sqrt(64) * log2(e)  (softmax runs base-2)
#define QSCALE (0.125f * 1.44269504088896f)

template<int MODE>
__global__ __launch_bounds__(128) void gemm_mma_kernel(
    const __nv_bfloat16* __restrict__ Ah, const __nv_bfloat16* __restrict__ Al,
    const __nv_bfloat16* __restrict__ Bh, const __nv_bfloat16* __restrict__ Bl,
    const float* __restrict__ bias, float* __restrict__ C, int N,
    __nv_bfloat16* __restrict__ qh, __nv_bfloat16* __restrict__ ql,
    __nv_bfloat16* __restrict__ kh, __nv_bfloat16* __restrict__ kl,
    __nv_bfloat16* __restrict__ vh, __nv_bfloat16* __restrict__ vl)
{
    extern __shared__ char smraw[];
    const uint32_t sbase = smem_u32(smraw);

    const int tid = threadIdx.x;
    const int wid = tid >> 5, lane = tid & 31;
    const int wm = wid & 1, wn = wid >> 1;
    const int g = lane >> 2, t = lane & 3;
    const int row0 = blockIdx.y << 7;
    const int col0 = blockIdx.x << 7;

    const __nv_bfloat16* srcs[4] = {Ah, Al, Bh, Bl};

    // quarter-chunk load: one array's tile (4 cp.async / thread)
    auto load_part = [&](int c, int s, int arr) {
        const int k0 = c << 5;
        const __nv_bfloat16* src = srcs[arr];
        const int rbase = (arr < 2) ? row0 : col0;
        const uint32_t tb = sbase + (uint32_t)s * GT_STG + (uint32_t)arr * GT_TILE;
        #pragma unroll
        for (int it = 0; it < 4; it++) {
            int id = it * 128 + tid, r = id >> 2, q = id & 3;
            cpasync16(tb + (uint32_t)(r * 80 + q * 16),
                      src + (size_t)(rbase + r) * K_SZ + k0 + q * 8);
        }
    };

    float acc[4][8][4] = {};
    const int a_row = lane & 15;
    const int a_cb  = (lane >> 4) << 4;
    const int b2_row = (lane & 7) + ((lane >> 4) << 3);
    const int b2_cb  = ((lane >> 3) & 1) << 4;

    #pragma unroll
    for (int arr = 0; arr < 4; arr++) load_part(0, 0, arr);
    asm volatile("cp.async.commit_group;" ::: "memory");

    for (int c = 0; c < GK_CH; c++) {
        const int s = c & 1, ns = s ^ 1;
        asm volatile("cp.async.wait_group 0;" ::: "memory");
        __syncthreads();

        const uint32_t stg = sbase + (uint32_t)s * GT_STG;
        const uint32_t tAh = stg, tAl = stg + GT_TILE;
        const uint32_t tBh = stg + 2 * GT_TILE, tBl = stg + 3 * GT_TILE;
        const bool more = (c + 1 < GK_CH);

        #pragma unroll
        for (int ks = 0; ks < 2; ks++) {
            const int kb = ks << 5;
            uint32_t ah[4][4], al[4][4], bh[4][4], bl[4][4];
            #pragma unroll
            for (int mt = 0; mt < 4; mt++) {
                const uint32_t ro = (uint32_t)((wm * 64 + mt * 16 + a_row) * 80 + kb + a_cb);
                ldsm4(ah[mt], tAh + ro);
                ldsm4(al[mt], tAl + ro);
            }
            #pragma unroll
            for (int np = 0; np < 4; np++) {
                const uint32_t ro = (uint32_t)((wn * 64 + np * 16 + b2_row) * 80 + kb + b2_cb);
                ldsm4(bh[np], tBh + ro);
                ldsm4(bl[np], tBl + ro);
            }
            // term-major passes with interleaved next-chunk load issues
            #pragma unroll
            for (int np = 0; np < 4; np++)
                #pragma unroll
                for (int mt = 0; mt < 4; mt++) {
                    mma16816(acc[mt][2 * np],     ah[mt], &bh[np][0]);
                    mma16816(acc[mt][2 * np + 1], ah[mt], &bh[np][2]);
                }
            if (more) load_part(c + 1, ns, 2 * ks + 0);
            #pragma unroll
            for (int np = 0; np < 4; np++)
                #pragma unroll
                for (int mt = 0; mt < 4; mt++) {
                    mma16816(acc[mt][2 * np],     ah[mt], &bl[np][0]);
                    mma16816(acc[mt][2 * np + 1], ah[mt], &bl[np][2]);
                }
            if (more) load_part(c + 1, ns, 2 * ks + 1);
            #pragma unroll
            for (int np = 0; np < 4; np++)
                #pragma unroll
                for (int mt = 0; mt < 4; mt++) {
                    mma16816(acc[mt][2 * np],     al[mt], &bh[np][0]);
                    mma16816(acc[mt][2 * np + 1], al[mt], &bh[np][2]);
                }
        }
        asm volatile("cp.async.commit_group;" ::: "memory");
    }
    __syncthreads();   // protect smem reuse by epilogue staging

    if (MODE == 1) {
        const uint32_t hi0 = sbase, lo0 = sbase + 128 * 272;
        #pragma unroll
        for (int mt = 0; mt < 4; mt++) {
            const int rl = wm * 64 + mt * 16 + g;
            #pragma unroll
            for (int nt = 0; nt < 8; nt++) {
                const int cl = wn * 64 + nt * 8 + 2 * t;
                const int col = col0 + cl;
                const float b0 = bias[col], b1 = bias[col + 1];
                float v0 = acc[mt][nt][0] + b0, v1 = acc[mt][nt][1] + b1;
                float v2 = acc[mt][nt][2] + b0, v3 = acc[mt][nt][3] + b1;
                if (col < M_SZ) { v0 *= QSCALE; v1 *= QSCALE; v2 *= QSCALE; v3 *= QSCALE; }
                uint32_t hu, lu;
                split2(v0, v1, hu, lu);
                sts32(hi0 + (uint32_t)(rl * 272 + cl * 2), hu);
                sts32(lo0 + (uint32_t)(rl * 272 + cl * 2), lu);
                split2(v2, v3, hu, lu);
                sts32(hi0 + (uint32_t)((rl + 8) * 272 + cl * 2), hu);
                sts32(lo0 + (uint32_t)((rl + 8) * 272 + cl * 2), lu);
            }
        }
        __syncthreads();
        #pragma unroll
        for (int it = 0; it < 16; it++) {
            const int id = it * 128 + tid, r = id >> 4, s = id & 15;
            const int col = col0 + s * 8;
            const int slice = col >> 10, hh = (col >> 6) & 15, dd = col & 63;
            __nv_bfloat16* oh = (slice == 0) ? qh : (slice == 1) ? kh : vh;
            __nv_bfloat16* ol = (slice == 0) ? ql : (slice == 1) ? kl : vl;
            const int row = row0 + r;
            const int ba = row >> 11, pa = row & 2047;
            const size_t oa = ((size_t)(ba * H_SZ + hh) * P_SZ + pa) * 64 + dd;
            uint4 vh4 = lds128(hi0 + (uint32_t)(r * 272 + s * 16));
            uint4 vl4 = lds128(lo0 + (uint32_t)(r * 272 + s * 16));
            *(uint4*)(oh + oa) = vh4;
            *(uint4*)(ol + oa) = vl4;
        }
    } else {
        #pragma unroll
        for (int mt = 0; mt < 4; mt++) {
            const int rl = wm * 64 + mt * 16 + g;
            #pragma unroll
            for (int nt = 0; nt < 8; nt++) {
                const int cl = wn * 64 + nt * 8 + 2 * t;
                const int col = col0 + cl;
                const float b0 = bias[col], b1 = bias[col + 1];
                sts64(sbase + (uint32_t)(rl * 528 + cl * 4),
                      acc[mt][nt][0] + b0, acc[mt][nt][1] + b1);
                sts64(sbase + (uint32_t)((rl + 8) * 528 + cl * 4),
                      acc[mt][nt][2] + b0, acc[mt][nt][3] + b1);
            }
        }
        __syncthreads();
        #pragma unroll
        for (int it = 0; it < 32; it++) {
            const int id = it * 128 + tid, r = id >> 5, s = id & 31;
            uint4 v = lds128(sbase + (uint32_t)(r * 528 + s * 16));
            *(uint4*)(C + (size_t)(row0 + r) * N + col0 + s * 4) = v;
        }
    }
}

// ---------------- tensor-core flash attention: 4 warps x 32 q-rows ---------
#define AT_ROWB 144
#define AT_QTILE (128 * AT_ROWB)        // 18432
#define AT_KTILE (64 * AT_ROWB)         // 9216
#define AT_KV0   (2 * AT_QTILE)         // 36864
#define AT_STG   (4 * AT_KTILE)         // 36864
#define AT_SMEM  (AT_KV0 + 2 * AT_STG)  // 110592

__global__ __launch_bounds__(128) void attn_mma_kernel(
    const __nv_bfloat16* __restrict__ qh, const __nv_bfloat16* __restrict__ ql,
    const __nv_bfloat16* __restrict__ kh, const __nv_bfloat16* __restrict__ kl,
    const __nv_bfloat16* __restrict__ vh, const __nv_bfloat16* __restrict__ vl,
    __nv_bfloat16* __restrict__ zh, __nv_bfloat16* __restrict__ zl)
{
    extern __shared__ char smraw[];
    const uint32_t sb = smem_u32(smraw);
    const int tid = threadIdx.x, w = tid >> 5, lane = tid & 31;
    const int g = lane >> 2, t = lane & 3;
    const int qt = blockIdx.x, bh = blockIdx.y;
    const int q0 = qt << 7;
    const size_t hb = (size_t)bh * P_SZ * 64;

    {   // Q hi/lo tile
        const __nv_bfloat16* Qh = qh + hb + (size_t)q0 * 64;
        const __nv_bfloat16* Ql = ql + hb + (size_t)q0 * 64;
        #pragma unroll
        for (int it = 0; it < 8; it++) {
            int id = it * 128 + tid, r = id >> 3, c = id & 7;
            cpasync16(sb + (uint32_t)(r * AT_ROWB + c * 16), Qh + r * 64 + c * 8);
            cpasync16(sb + AT_QTILE + (uint32_t)(r * AT_ROWB + c * 16), Ql + r * 64 + c * 8);
        }
    }
    const __nv_bfloat16* kvsrc[4] = {kh + hb, kl + hb, vh + hb, vl + hb};
    // one array's KV tile (4 cp.async / thread)
    auto load_kv_part = [&](int kvt, int s, int a) {
        const uint32_t stg = sb + AT_KV0 + (uint32_t)s * AT_STG;
        const size_t rb = (size_t)(kvt << 6) * 64;
        #pragma unroll
        for (int it = 0; it < 4; it++) {
            int id = it * 128 + tid, r = id >> 3, c = id & 7;
            cpasync16(stg + (uint32_t)(a * AT_KTILE + r * AT_ROWB + c * 16),
                      kvsrc[a] + rb + r * 64 + c * 8);
        }
    };
    const int ntiles = 2 * qt + 2;
    #pragma unroll
    for (int a = 0; a < 4; a++) load_kv_part(0, 0, a);
    asm volatile("cp.async.commit_group;" ::: "memory");

    uint32_t qhf[2][4][4], qlf[2][4][4];
    float oacc[2][8][4] = {};
    float mrow[2][2], lrow[2][2];
    #pragma unroll
    for (int mt = 0; mt < 2; mt++) {
        mrow[mt][0] = -1e30f; mrow[mt][1] = -1e30f;
        lrow[mt][0] = 0.f;    lrow[mt][1] = 0.f;
    }
    const int arow = (lane & 7) + ((lane >> 3) & 1) * 8;
    const int achk = lane >> 4;
    const int wrow_min = q0 + 32 * w;
    const int wrow_max = wrow_min + 31;

    for (int kvt = 0; kvt < ntiles; kvt++) {
        const int s = kvt & 1, ns = s ^ 1;
        asm volatile("cp.async.wait_group 0;" ::: "memory");
        __syncthreads();
        const bool more = (kvt + 1 < ntiles);
        if (kvt == 0) {
            #pragma unroll
            for (int mt = 0; mt < 2; mt++)
                #pragma unroll
                for (int ks = 0; ks < 4; ks++) {
                    uint32_t ad = sb + (uint32_t)((32 * w + 16 * mt + arow) * AT_ROWB +
                                                  (2 * ks + achk) * 16);
                    ldsm4(qhf[mt][ks], ad);
                    ldsm4(qlf[mt][ks], ad + AT_QTILE);
                }
        }
        const int c_base = kvt << 6;
        if (c_base <= wrow_max) {
            const uint32_t kb = sb + AT_KV0 + (uint32_t)s * AT_STG;

            // ---- S = Q K^T: term-major per j ----
            float sacc[2][8][4] = {};
            #pragma unroll
            for (int j = 0; j < 8; j++) {
                uint32_t khf[2][4], klf[2][4];
                #pragma unroll
                for (int cp = 0; cp < 2; cp++) {
                    uint32_t ad = kb + (uint32_t)((8 * j + (lane & 7)) * AT_ROWB +
                                                  (4 * cp + (lane >> 3)) * 16);
                    ldsm4(khf[cp], ad);
                    ldsm4(klf[cp], ad + AT_KTILE);
                }
                #pragma unroll
                for (int cp = 0; cp < 2; cp++)
                    #pragma unroll
                    for (int mt = 0; mt < 2; mt++) {
                        mma16816(sacc[mt][j], qhf[mt][2 * cp],     &khf[cp][0]);
                        mma16816(sacc[mt][j], qhf[mt][2 * cp + 1], &khf[cp][2]);
                    }
                #pragma unroll
                for (int cp = 0; cp < 2; cp++)
                    #pragma unroll
                    for (int mt = 0; mt < 2; mt++) {
                        mma16816(sacc[mt][j], qhf[mt][2 * cp],     &klf[cp][0]);
                        mma16816(sacc[mt][j], qhf[mt][2 * cp + 1], &klf[cp][2]);
                    }
                #pragma unroll
                for (int cp = 0; cp < 2; cp++)
                    #pragma unroll
                    for (int mt = 0; mt < 2; mt++) {
                        mma16816(sacc[mt][j], qlf[mt][2 * cp],     &khf[cp][0]);
                        mma16816(sacc[mt][j], qlf[mt][2 * cp + 1], &khf[cp][2]);
                    }
            }
            if (more) { load_kv_part(kvt + 1, ns, 0); load_kv_part(kvt + 1, ns, 1); }

            if (c_base + 63 > wrow_min) {
                #pragma unroll
                for (int mt = 0; mt < 2; mt++) {
                    const int lr0 = wrow_min + 16 * mt + g;
                    #pragma unroll
                    for (int j = 0; j < 8; j++) {
                        const int c0 = c_base + 8 * j + 2 * t;
                        if (c0     > lr0)     sacc[mt][j][0] = -1e30f;
                        if (c0 + 1 > lr0)     sacc[mt][j][1] = -1e30f;
                        if (c0     > lr0 + 8) sacc[mt][j][2] = -1e30f;
                        if (c0 + 1 > lr0 + 8) sacc[mt][j][3] = -1e30f;
                    }
                }
            }

            #pragma unroll
            for (int mt = 0; mt < 2; mt++) {
                float mx0 = -1e30f, mx1 = -1e30f;
                #pragma unroll
                for (int j = 0; j < 8; j++) {
                    mx0 = fmaxf(mx0, fmaxf(sacc[mt][j][0], sacc[mt][j][1]));
                    mx1 = fmaxf(mx1, fmaxf(sacc[mt][j][2], sacc[mt][j][3]));
                }
                mx0 = fmaxf(mx0, __shfl_xor_sync(0xffffffffu, mx0, 1));
                mx0 = fmaxf(mx0, __shfl_xor_sync(0xffffffffu, mx0, 2));
                mx1 = fmaxf(mx1, __shfl_xor_sync(0xffffffffu, mx1, 1));
                mx1 = fmaxf(mx1, __shfl_xor_sync(0xffffffffu, mx1, 2));
                const float mn0 = fmaxf(mrow[mt][0], mx0), mn1 = fmaxf(mrow[mt][1], mx1);
                const float al0 = exp2f(mrow[mt][0] - mn0), al1 = exp2f(mrow[mt][1] - mn1);
                float sum0 = 0.f, sum1 = 0.f;
                #pragma unroll
                for (int j = 0; j < 8; j++) {
                    sacc[mt][j][0] = exp2f(sacc[mt][j][0] - mn0);
                    sacc[mt][j][1] = exp2f(sacc[mt][j][1] - mn0);
                    sacc[mt][j][2] = exp2f(sacc[mt][j][2] - mn1);
                    sacc[mt][j][3] = exp2f(sacc[mt][j][3] - mn1);
                    sum0 += sacc[mt][j][0] + sacc[mt][j][1];
                    sum1 += sacc[mt][j][2] + sacc[mt][j][3];
                }
                sum0 += __shfl_xor_sync(0xffffffffu, sum0, 1);
                sum0 += __shfl_xor_sync(0xffffffffu, sum0, 2);
                sum1 += __shfl_xor_sync(0xffffffffu, sum1, 1);
                sum1 += __shfl_xor_sync(0xffffffffu, sum1, 2);
                lrow[mt][0] = lrow[mt][0] * al0 + sum0; mrow[mt][0] = mn0;
                lrow[mt][1] = lrow[mt][1] * al1 + sum1; mrow[mt][1] = mn1;
                #pragma unroll
                for (int j = 0; j < 8; j++) {
                    oacc[mt][j][0] *= al0; oacc[mt][j][1] *= al0;
                    oacc[mt][j][2] *= al1; oacc[mt][j][3] *= al1;
                }
            }

            // ---- O += P V: term-major per s2, interleaved loads ----
            #pragma unroll
            for (int s2 = 0; s2 < 4; s2++) {
                uint32_t pah[2][4], pal[2][4];
                #pragma unroll
                for (int mt = 0; mt < 2; mt++) {
                    split2(sacc[mt][2 * s2][0],     sacc[mt][2 * s2][1],     pah[mt][0], pal[mt][0]);
                    split2(sacc[mt][2 * s2][2],     sacc[mt][2 * s2][3],     pah[mt][1], pal[mt][1]);
                    split2(sacc[mt][2 * s2 + 1][0], sacc[mt][2 * s2 + 1][1], pah[mt][2], pal[mt][2]);
                    split2(sacc[mt][2 * s2 + 1][2], sacc[mt][2 * s2 + 1][3], pah[mt][3], pal[mt][3]);
                }
                uint32_t vhf[4][4], vlf[4][4];
                #pragma unroll
                for (int jp = 0; jp < 4; jp++) {
                    uint32_t ad = kb + 2 * AT_KTILE +
                        (uint32_t)((16 * s2 + (lane & 15)) * AT_ROWB + (2 * jp + (lane >> 4)) * 16);
                    ldsm4t(vhf[jp], ad);
                    ldsm4t(vlf[jp], ad + AT_KTILE);
                }
                #pragma unroll
                for (int jp = 0; jp < 4; jp++)
                    #pragma unroll
                    for (int mt = 0; mt < 2; mt++) {
                        mma16816(oacc[mt][2 * jp],     pah[mt], &vhf[jp][0]);
                        mma16816(oacc[mt][2 * jp + 1], pah[mt], &vhf[jp][2]);
                    }
                #pragma unroll
                for (int jp = 0; jp < 4; jp++)
                    #pragma unroll
                    for (int mt = 0; mt < 2; mt++) {
                        mma16816(oacc[mt][2 * jp],     pah[mt], &vlf[jp][0]);
                        mma16816(oacc[mt][2 * jp + 1], pah[mt], &vlf[jp][2]);
                    }
                #pragma unroll
                for (int jp = 0; jp < 4; jp++)
                    #pragma unroll
                    for (int mt = 0; mt < 2; mt++) {
                        mma16816(oacc[mt][2 * jp],     pal[mt], &vhf[jp][0]);
                        mma16816(oacc[mt][2 * jp + 1], pal[mt], &vhf[jp][2]);
                    }
                if (more && s2 == 0) load_kv_part(kvt + 1, ns, 2);
                if (more && s2 == 2) load_kv_part(kvt + 1, ns, 3);
            }
        } else if (more) {
            // causally-skipped warps still issue their share of the loads
            #pragma unroll
            for (int a = 0; a < 4; a++) load_kv_part(kvt + 1, ns, a);
        }
        asm volatile("cp.async.commit_group;" ::: "memory");
    }
    __syncthreads();   // protect KV smem reuse by epilogue staging

    const uint32_t oh0 = sb + AT_KV0, ol0 = oh0 + 128 * AT_ROWB;
    #pragma unroll
    for (int mt = 0; mt < 2; mt++) {
        const float i0 = 1.f / lrow[mt][0], i1 = 1.f / lrow[mt][1];
        const int rl = 32 * w + 16 * mt + g;
        #pragma unroll
        for (int j = 0; j < 8; j++) {
            const int cl = 8 * j + 2 * t;
            uint32_t hu, lu;
            split2(oacc[mt][j][0] * i0, oacc[mt][j][1] * i0, hu, lu);
            sts32(oh0 + (uint32_t)(rl * AT_ROWB + cl * 2), hu);
            sts32(ol0 + (uint32_t)(rl * AT_ROWB + cl * 2), lu);
            split2(oacc[mt][j][2] * i1, oacc[mt][j][3] * i1, hu, lu);
            sts32(oh0 + (uint32_t)((rl + 8) * AT_ROWB + cl * 2), hu);
            sts32(ol0 + (uint32_t)((rl + 8) * AT_ROWB + cl * 2), lu);
        }
    }
    __syncthreads();
    const int b = bh >> 4, h = bh & 15;
    #pragma unroll
    for (int it = 0; it < 8; it++) {
        const int id = it * 128 + tid, r = id >> 3, s = id & 7;
        const size_t dst = ((size_t)b * P_SZ + q0 + r) * K_SZ + h * 64 + s * 8;
        uint4 vh4 = lds128(oh0 + (uint32_t)(r * AT_ROWB + s * 16));
        uint4 vl4 = lds128(ol0 + (uint32_t)(r * AT_ROWB + s * 16));
        *(uint4*)(zh + dst) = vh4;
        *(uint4*)(zl + dst) = vl4;
    }
}

// ---------------------------------------------------------------------------
extern "C" void kernel_launch(void* const* d_in, const int* in_sizes, int n_in,
                              void* d_out, int out_size)
{
    (void)in_sizes; (void)n_in; (void)out_size;
    const float* x      = (const float*)d_in[0];
    const float* W_attn = (const float*)d_in[1];
    const float* b_attn = (const float*)d_in[2];
    const float* W_proj = (const float*)d_in[3];
    const float* b_proj = (const float*)d_in[4];
    float* out = (float*)d_out;

    __nv_bfloat16 *xhi, *xlo, *wah, *wal, *wph, *wpl;
    __nv_bfloat16 *qh, *ql, *kh, *kl, *vh, *vl, *zh, *zl;
    cudaGetSymbolAddress((void**)&xhi, g_xhi);
    cudaGetSymbolAddress((void**)&xlo, g_xlo);
    cudaGetSymbolAddress((void**)&wah, g_wah);
    cudaGetSymbolAddress((void**)&wal, g_wal);
    cudaGetSymbolAddress((void**)&wph, g_wph);
    cudaGetSymbolAddress((void**)&wpl, g_wpl);
    cudaGetSymbolAddress((void**)&qh,  g_qh);
    cudaGetSymbolAddress((void**)&ql,  g_ql);
    cudaGetSymbolAddress((void**)&kh,  g_kh);
    cudaGetSymbolAddress((void**)&kl,  g_kl);
    cudaGetSymbolAddress((void**)&vh,  g_vh);
    cudaGetSymbolAddress((void**)&vl,  g_vl);
    cudaGetSymbolAddress((void**)&zh,  g_zh);
    cudaGetSymbolAddress((void**)&zl,  g_zl);

    cudaFuncSetAttribute(gemm_mma_kernel<0>,
                         cudaFuncAttributeMaxDynamicSharedMemorySize, GT_SMEM);
    cudaFuncSetAttribute(gemm_mma_kernel<1>,
                         cudaFuncAttributeMaxDynamicSharedMemorySize, GT_SMEM);
    cudaFuncSetAttribute(attn_mma_kernel,
                         cudaFuncAttributeMaxDynamicSharedMemorySize, AT_SMEM);

    split_kernel<<<(R_SZ * K_SZ / 4 + 255) / 256, 256>>>(x, xhi, xlo, R_SZ * K_SZ / 4);
    tsplit_kernel<<<dim3(N3_SZ / 32, K_SZ / 32), 256>>>(W_attn, wah, wal, K_SZ, N3_SZ);
    tsplit_kernel<<<dim3(M_SZ / 32, K_SZ / 32), 256>>>(W_proj, wph, wpl, K_SZ, M_SZ);

    gemm_mma_kernel<1><<<dim3(N3_SZ / 128, R_SZ / 128), 128, GT_SMEM>>>(
        xhi, xlo, wah, wal, b_attn, nullptr, N3_SZ, qh, ql, kh, kl, vh, vl);

    attn_mma_kernel<<<dim3(P_SZ / 128, BH_SZ), 128, AT_SMEM>>>(
        qh, ql, kh, kl, vh, vl, zh, zl);

    gemm_mma_kernel<0><<<dim3(M_SZ / 128, R_SZ / 128), 128, GT_SMEM>>>(
        zh, zl, wph, wpl, b_proj, out, M_SZ,
        nullptr, nullptr, nullptr, nullptr, nullptr, nullptr);
}

// round 10
// speedup vs baseline: 1.1620x; 1.0002x over previous
#include <cuda_runtime.h>
#include <cuda_bf16.h>
#include <cstdint>
#include <string.h>
#include <math.h>

#define B_SZ 2
#define P_SZ 2048
#define M_SZ 1024
#define H_SZ 16
#define D_SZ 64
#define N3_SZ 3072
#define R_SZ (B_SZ * P_SZ)      // 4096
#define K_SZ M_SZ               // 1024
#define BH_SZ (B_SZ * H_SZ)     // 32

// ---------------- scratch (__device__ globals) -----------------------------
__device__ __nv_bfloat16 g_xhi[(size_t)R_SZ * K_SZ];
__device__ __nv_bfloat16 g_xlo[(size_t)R_SZ * K_SZ];
__device__ __nv_bfloat16 g_wah[(size_t)N3_SZ * K_SZ];
__device__ __nv_bfloat16 g_wal[(size_t)N3_SZ * K_SZ];
__device__ __nv_bfloat16 g_wph[(size_t)M_SZ * K_SZ];
__device__ __nv_bfloat16 g_wpl[(size_t)M_SZ * K_SZ];
__device__ __nv_bfloat16 g_qh[(size_t)BH_SZ * P_SZ * D_SZ];
__device__ __nv_bfloat16 g_ql[(size_t)BH_SZ * P_SZ * D_SZ];
__device__ __nv_bfloat16 g_kh[(size_t)BH_SZ * P_SZ * D_SZ];
__device__ __nv_bfloat16 g_kl[(size_t)BH_SZ * P_SZ * D_SZ];
__device__ __nv_bfloat16 g_vh[(size_t)BH_SZ * P_SZ * D_SZ];
__device__ __nv_bfloat16 g_vl[(size_t)BH_SZ * P_SZ * D_SZ];
__device__ __nv_bfloat16 g_zh[(size_t)R_SZ * K_SZ];
__device__ __nv_bfloat16 g_zl[(size_t)R_SZ * K_SZ];

// ---------------- PTX helpers (base ISA) -----------------------------------
__device__ __forceinline__ uint32_t smem_u32(const void* p) {
    uint32_t a;
    asm("{ .reg .u64 t; cvta.to.shared.u64 t, %1; cvt.u32.u64 %0, t; }" : "=r"(a) : "l"(p));
    return a;
}
__device__ __forceinline__ void ldsm4(uint32_t* r, uint32_t addr) {
    asm volatile("ldmatrix.sync.aligned.m8n8.x4.shared.b16 {%0,%1,%2,%3}, [%4];"
                 : "=r"(r[0]), "=r"(r[1]), "=r"(r[2]), "=r"(r[3]) : "r"(addr));
}
__device__ __forceinline__ void ldsm4t(uint32_t* r, uint32_t addr) {
    asm volatile("ldmatrix.sync.aligned.m8n8.x4.trans.shared.b16 {%0,%1,%2,%3}, [%4];"
                 : "=r"(r[0]), "=r"(r[1]), "=r"(r[2]), "=r"(r[3]) : "r"(addr));
}
__device__ __forceinline__ void mma16816(float* c, const uint32_t* a, const uint32_t* b) {
    asm volatile(
        "mma.sync.aligned.m16n8k16.row.col.f32.bf16.bf16.f32 "
        "{%0,%1,%2,%3}, {%4,%5,%6,%7}, {%8,%9}, {%0,%1,%2,%3};"
        : "+f"(c[0]), "+f"(c[1]), "+f"(c[2]), "+f"(c[3])
        : "r"(a[0]), "r"(a[1]), "r"(a[2]), "r"(a[3]), "r"(b[0]), "r"(b[1]));
}
__device__ __forceinline__ void cpasync16(uint32_t saddr, const void* gaddr) {
    asm volatile("cp.async.cg.shared.global [%0], [%1], 16;" :: "r"(saddr), "l"(gaddr) : "memory");
}
__device__ __forceinline__ void sts32(uint32_t addr, uint32_t v) {
    asm volatile("st.shared.b32 [%0], %1;" :: "r"(addr), "r"(v) : "memory");
}
__device__ __forceinline__ void sts64(uint32_t addr, float a, float b) {
    asm volatile("st.shared.v2.f32 [%0], {%1,%2};" :: "r"(addr), "f"(a), "f"(b) : "memory");
}
__device__ __forceinline__ uint4 lds128(uint32_t addr) {
    uint4 v;
    asm volatile("ld.shared.v4.b32 {%0,%1,%2,%3}, [%4];"
                 : "=r"(v.x), "=r"(v.y), "=r"(v.z), "=r"(v.w) : "r"(addr));
    return v;
}
__device__ __forceinline__ void split2(float a, float b, uint32_t& hu, uint32_t& lu) {
    __nv_bfloat16 ha = __float2bfloat16(a), hb = __float2bfloat16(b);
    float ra = a - __bfloat162float(ha), rb = b - __bfloat162float(hb);
    __nv_bfloat162 H = __halves2bfloat162(ha, hb);
    __nv_bfloat162 L = __floats2bfloat162_rn(ra, rb);
    memcpy(&hu, &H, 4); memcpy(&lu, &L, 4);
}

// ---------------- fp32 -> bf16 hi/lo split ---------------------------------
struct alignas(8) bf16x4 { __nv_bfloat162 a, b; };

__global__ __launch_bounds__(256) void split_kernel(
    const float* __restrict__ in, __nv_bfloat16* __restrict__ hi,
    __nv_bfloat16* __restrict__ lo, int n4)
{
    int i = blockIdx.x * 256 + threadIdx.x;
    if (i >= n4) return;
    float4 v = ((const float4*)in)[i];
    float h0 = __bfloat162float(__float2bfloat16(v.x));
    float h1 = __bfloat162float(__float2bfloat16(v.y));
    float h2 = __bfloat162float(__float2bfloat16(v.z));
    float h3 = __bfloat162float(__float2bfloat16(v.w));
    bf16x4 H, L;
    H.a = __floats2bfloat162_rn(h0, h1);
    H.b = __floats2bfloat162_rn(h2, h3);
    L.a = __floats2bfloat162_rn(v.x - h0, v.y - h1);
    L.b = __floats2bfloat162_rn(v.z - h2, v.w - h3);
    ((bf16x4*)hi)[i] = H;
    ((bf16x4*)lo)[i] = L;
}

__global__ __launch_bounds__(256) void tsplit_kernel(
    const float* __restrict__ W, __nv_bfloat16* __restrict__ hi,
    __nv_bfloat16* __restrict__ lo, int K, int N)
{
    __shared__ float s[32][33];
    const int n0 = blockIdx.x * 32, k0 = blockIdx.y * 32;
    const int tx = threadIdx.x & 31, ty = threadIdx.x >> 5;
    #pragma unroll
    for (int i = 0; i < 4; i++)
        s[ty + 8 * i][tx] = W[(size_t)(k0 + ty + 8 * i) * N + n0 + tx];
    __syncthreads();
    #pragma unroll
    for (int i = 0; i < 4; i++) {
        int r = ty + 8 * i;
        float v = s[tx][r];
        float h = __bfloat162float(__float2bfloat16(v));
        size_t o = (size_t)(n0 + r) * K + k0 + tx;
        hi[o] = __float2bfloat16(h);
        lo[o] = __float2bfloat16(v - h);
    }
}

// ---------------- split-bf16 mma GEMM: 4 warps, 64x64 warp tile ------------
#define GK_CH   (K_SZ / 32)          // 32 chunks
#define GT_TILE 10240                // 128 rows * 80 B
#define GT_STG  (4 * GT_TILE)
#define GT_SMEM (2 * GT_STG)         // 81920 B

// Q pre-scale: 1/sqrt(64) * log2(e)  (softmax runs base-2)
#define QSCALE (0.125f * 1.44269504088896f)

template<int MODE>
__global__ __launch_bounds__(128) void gemm_mma_kernel(
    const __nv_bfloat16* __restrict__ Ah, const __nv_bfloat16* __restrict__ Al,
    const __nv_bfloat16* __restrict__ Bh, const __nv_bfloat16* __restrict__ Bl,
    const float* __restrict__ bias, float* __restrict__ C, int N,
    __nv_bfloat16* __restrict__ qh, __nv_bfloat16* __restrict__ ql,
    __nv_bfloat16* __restrict__ kh, __nv_bfloat16* __restrict__ kl,
    __nv_bfloat16* __restrict__ vh, __nv_bfloat16* __restrict__ vl)
{
    extern __shared__ char smraw[];
    const uint32_t sbase = smem_u32(smraw);

    const int tid = threadIdx.x;
    const int wid = tid >> 5, lane = tid & 31;
    const int wm = wid & 1, wn = wid >> 1;
    const int g = lane >> 2, t = lane & 3;
    const int row0 = blockIdx.y << 7;
    const int col0 = blockIdx.x << 7;

    const __nv_bfloat16* srcs[4] = {Ah, Al, Bh, Bl};

    auto load_part = [&](int c, int s, int arr) {
        const int k0 = c << 5;
        const __nv_bfloat16* src = srcs[arr];
        const int rbase = (arr < 2) ? row0 : col0;
        const uint32_t tb = sbase + (uint32_t)s * GT_STG + (uint32_t)arr * GT_TILE;
        #pragma unroll
        for (int it = 0; it < 4; it++) {
            int id = it * 128 + tid, r = id >> 2, q = id & 3;
            cpasync16(tb + (uint32_t)(r * 80 + q * 16),
                      src + (size_t)(rbase + r) * K_SZ + k0 + q * 8);
        }
    };

    float acc[4][8][4] = {};
    const int a_row = lane & 15;
    const int a_cb  = (lane >> 4) << 4;
    const int b2_row = (lane & 7) + ((lane >> 4) << 3);
    const int b2_cb  = ((lane >> 3) & 1) << 4;

    #pragma unroll
    for (int arr = 0; arr < 4; arr++) load_part(0, 0, arr);
    asm volatile("cp.async.commit_group;" ::: "memory");

    for (int c = 0; c < GK_CH; c++) {
        const int s = c & 1, ns = s ^ 1;
        asm volatile("cp.async.wait_group 0;" ::: "memory");
        __syncthreads();

        const uint32_t stg = sbase + (uint32_t)s * GT_STG;
        const uint32_t tAh = stg, tAl = stg + GT_TILE;
        const uint32_t tBh = stg + 2 * GT_TILE, tBl = stg + 3 * GT_TILE;
        const bool more = (c + 1 < GK_CH);

        #pragma unroll
        for (int ks = 0; ks < 2; ks++) {
            const int kb = ks << 5;
            uint32_t ah[4][4], al[4][4], bh[4][4], bl[4][4];
            // minimal preload: only pass-1 operands (ah, bh)
            #pragma unroll
            for (int mt = 0; mt < 4; mt++)
                ldsm4(ah[mt], tAh + (uint32_t)((wm * 64 + mt * 16 + a_row) * 80 + kb + a_cb));
            #pragma unroll
            for (int np = 0; np < 4; np++)
                ldsm4(bh[np], tBh + (uint32_t)((wn * 64 + np * 16 + b2_row) * 80 + kb + b2_cb));
            // pass 1 (ah*bh) with al/bl loads interleaved (used >=1 pass later)
            #pragma unroll
            for (int np = 0; np < 4; np++) {
                ldsm4(al[np], tAl + (uint32_t)((wm * 64 + np * 16 + a_row) * 80 + kb + a_cb));
                ldsm4(bl[np], tBl + (uint32_t)((wn * 64 + np * 16 + b2_row) * 80 + kb + b2_cb));
                #pragma unroll
                for (int mt = 0; mt < 4; mt++) {
                    mma16816(acc[mt][2 * np],     ah[mt], &bh[np][0]);
                    mma16816(acc[mt][2 * np + 1], ah[mt], &bh[np][2]);
                }
            }
            if (more) load_part(c + 1, ns, 2 * ks + 0);
            // pass 2 (ah*bl)
            #pragma unroll
            for (int np = 0; np < 4; np++)
                #pragma unroll
                for (int mt = 0; mt < 4; mt++) {
                    mma16816(acc[mt][2 * np],     ah[mt], &bl[np][0]);
                    mma16816(acc[mt][2 * np + 1], ah[mt], &bl[np][2]);
                }
            if (more) load_part(c + 1, ns, 2 * ks + 1);
            // pass 3 (al*bh)
            #pragma unroll
            for (int np = 0; np < 4; np++)
                #pragma unroll
                for (int mt = 0; mt < 4; mt++) {
                    mma16816(acc[mt][2 * np],     al[mt], &bh[np][0]);
                    mma16816(acc[mt][2 * np + 1], al[mt], &bh[np][2]);
                }
        }
        asm volatile("cp.async.commit_group;" ::: "memory");
    }
    __syncthreads();

    if (MODE == 1) {
        const uint32_t hi0 = sbase, lo0 = sbase + 128 * 272;
        #pragma unroll
        for (int mt = 0; mt < 4; mt++) {
            const int rl = wm * 64 + mt * 16 + g;
            #pragma unroll
            for (int nt = 0; nt < 8; nt++) {
                const int cl = wn * 64 + nt * 8 + 2 * t;
                const int col = col0 + cl;
                const float b0 = bias[col], b1 = bias[col + 1];
                float v0 = acc[mt][nt][0] + b0, v1 = acc[mt][nt][1] + b1;
                float v2 = acc[mt][nt][2] + b0, v3 = acc[mt][nt][3] + b1;
                if (col < M_SZ) { v0 *= QSCALE; v1 *= QSCALE; v2 *= QSCALE; v3 *= QSCALE; }
                uint32_t hu, lu;
                split2(v0, v1, hu, lu);
                sts32(hi0 + (uint32_t)(rl * 272 + cl * 2), hu);
                sts32(lo0 + (uint32_t)(rl * 272 + cl * 2), lu);
                split2(v2, v3, hu, lu);
                sts32(hi0 + (uint32_t)((rl + 8) * 272 + cl * 2), hu);
                sts32(lo0 + (uint32_t)((rl + 8) * 272 + cl * 2), lu);
            }
        }
        __syncthreads();
        #pragma unroll
        for (int it = 0; it < 16; it++) {
            const int id = it * 128 + tid, r = id >> 4, s = id & 15;
            const int col = col0 + s * 8;
            const int slice = col >> 10, hh = (col >> 6) & 15, dd = col & 63;
            __nv_bfloat16* oh = (slice == 0) ? qh : (slice == 1) ? kh : vh;
            __nv_bfloat16* ol = (slice == 0) ? ql : (slice == 1) ? kl : vl;
            const int row = row0 + r;
            const int ba = row >> 11, pa = row & 2047;
            const size_t oa = ((size_t)(ba * H_SZ + hh) * P_SZ + pa) * 64 + dd;
            uint4 vh4 = lds128(hi0 + (uint32_t)(r * 272 + s * 16));
            uint4 vl4 = lds128(lo0 + (uint32_t)(r * 272 + s * 16));
            *(uint4*)(oh + oa) = vh4;
            *(uint4*)(ol + oa) = vl4;
        }
    } else {
        #pragma unroll
        for (int mt = 0; mt < 4; mt++) {
            const int rl = wm * 64 + mt * 16 + g;
            #pragma unroll
            for (int nt = 0; nt < 8; nt++) {
                const int cl = wn * 64 + nt * 8 + 2 * t;
                const int col = col0 + cl;
                const float b0 = bias[col], b1 = bias[col + 1];
                sts64(sbase + (uint32_t)(rl * 528 + cl * 4),
                      acc[mt][nt][0] + b0, acc[mt][nt][1] + b1);
                sts64(sbase + (uint32_t)((rl + 8) * 528 + cl * 4),
                      acc[mt][nt][2] + b0, acc[mt][nt][3] + b1);
            }
        }
        __syncthreads();
        #pragma unroll
        for (int it = 0; it < 32; it++) {
            const int id = it * 128 + tid, r = id >> 5, s = id & 31;
            uint4 v = lds128(sbase + (uint32_t)(r * 528 + s * 16));
            *(uint4*)(C + (size_t)(row0 + r) * N + col0 + s * 4) = v;
        }
    }
}

// ---------------- tensor-core flash attention: 4 warps x 32 q-rows ---------
#define AT_ROWB 144
#define AT_QTILE (128 * AT_ROWB)        // 18432
#define AT_KTILE (64 * AT_ROWB)         // 9216
#define AT_KV0   (2 * AT_QTILE)         // 36864
#define AT_STG   (4 * AT_KTILE)         // 36864
#define AT_SMEM  (AT_KV0 + 2 * AT_STG)  // 110592

__global__ __launch_bounds__(128) void attn_mma_kernel(
    const __nv_bfloat16* __restrict__ qh, const __nv_bfloat16* __restrict__ ql,
    const __nv_bfloat16* __restrict__ kh, const __nv_bfloat16* __restrict__ kl,
    const __nv_bfloat16* __restrict__ vh, const __nv_bfloat16* __restrict__ vl,
    __nv_bfloat16* __restrict__ zh, __nv_bfloat16* __restrict__ zl)
{
    extern __shared__ char smraw[];
    const uint32_t sb = smem_u32(smraw);
    const int tid = threadIdx.x, w = tid >> 5, lane = tid & 31;
    const int g = lane >> 2, t = lane & 3;
    const int qt = blockIdx.x, bh = blockIdx.y;
    const int q0 = qt << 7;
    const size_t hb = (size_t)bh * P_SZ * 64;

    {   // Q hi/lo tile
        const __nv_bfloat16* Qh = qh + hb + (size_t)q0 * 64;
        const __nv_bfloat16* Ql = ql + hb + (size_t)q0 * 64;
        #pragma unroll
        for (int it = 0; it < 8; it++) {
            int id = it * 128 + tid, r = id >> 3, c = id & 7;
            cpasync16(sb + (uint32_t)(r * AT_ROWB + c * 16), Qh + r * 64 + c * 8);
            cpasync16(sb + AT_QTILE + (uint32_t)(r * AT_ROWB + c * 16), Ql + r * 64 + c * 8);
        }
    }
    const __nv_bfloat16* kvsrc[4] = {kh + hb, kl + hb, vh + hb, vl + hb};
    auto load_kv_part = [&](int kvt, int s, int a) {
        const uint32_t stg = sb + AT_KV0 + (uint32_t)s * AT_STG;
        const size_t rb = (size_t)(kvt << 6) * 64;
        #pragma unroll
        for (int it = 0; it < 4; it++) {
            int id = it * 128 + tid, r = id >> 3, c = id & 7;
            cpasync16(stg + (uint32_t)(a * AT_KTILE + r * AT_ROWB + c * 16),
                      kvsrc[a] + rb + r * 64 + c * 8);
        }
    };
    const int ntiles = 2 * qt + 2;
    #pragma unroll
    for (int a = 0; a < 4; a++) load_kv_part(0, 0, a);
    asm volatile("cp.async.commit_group;" ::: "memory");

    uint32_t qhf[2][4][4], qlf[2][4][4];
    float oacc[2][8][4] = {};
    float mrow[2][2], lrow[2][2];
    #pragma unroll
    for (int mt = 0; mt < 2; mt++) {
        mrow[mt][0] = -1e30f; mrow[mt][1] = -1e30f;
        lrow[mt][0] = 0.f;    lrow[mt][1] = 0.f;
    }
    const int arow = (lane & 7) + ((lane >> 3) & 1) * 8;
    const int achk = lane >> 4;
    const int wrow_min = q0 + 32 * w;
    const int wrow_max = wrow_min + 31;

    for (int kvt = 0; kvt < ntiles; kvt++) {
        const int s = kvt & 1, ns = s ^ 1;
        asm volatile("cp.async.wait_group 0;" ::: "memory");
        __syncthreads();
        const bool more = (kvt + 1 < ntiles);
        if (kvt == 0) {
            #pragma unroll
            for (int mt = 0; mt < 2; mt++)
                #pragma unroll
                for (int ks = 0; ks < 4; ks++) {
                    uint32_t ad = sb + (uint32_t)((32 * w + 16 * mt + arow) * AT_ROWB +
                                                  (2 * ks + achk) * 16);
                    ldsm4(qhf[mt][ks], ad);
                    ldsm4(qlf[mt][ks], ad + AT_QTILE);
                }
        }
        const int c_base = kvt << 6;
        if (c_base <= wrow_max) {
            const uint32_t kb = sb + AT_KV0 + (uint32_t)s * AT_STG;

            // ---- S = Q K^T: K-fragments double-buffered across j ----
            float sacc[2][8][4] = {};
            uint32_t khf[2][2][4], klf[2][2][4];   // [buf][cp][4]
            #pragma unroll
            for (int cp = 0; cp < 2; cp++) {
                uint32_t ad = kb + (uint32_t)((lane & 7) * AT_ROWB + (4 * cp + (lane >> 3)) * 16);
                ldsm4(khf[0][cp], ad);
                ldsm4(klf[0][cp], ad + AT_KTILE);
            }
            #pragma unroll
            for (int j = 0; j < 8; j++) {
                const int cur = j & 1, nxt = cur ^ 1;
                if (j < 7) {
                    #pragma unroll
                    for (int cp = 0; cp < 2; cp++) {
                        uint32_t ad = kb + (uint32_t)((8 * (j + 1) + (lane & 7)) * AT_ROWB +
                                                      (4 * cp + (lane >> 3)) * 16);
                        ldsm4(khf[nxt][cp], ad);
                        ldsm4(klf[nxt][cp], ad + AT_KTILE);
                    }
                }
                #pragma unroll
                for (int cp = 0; cp < 2; cp++)
                    #pragma unroll
                    for (int mt = 0; mt < 2; mt++) {
                        mma16816(sacc[mt][j], qhf[mt][2 * cp],     &khf[cur][cp][0]);
                        mma16816(sacc[mt][j], qhf[mt][2 * cp + 1], &khf[cur][cp][2]);
                    }
                #pragma unroll
                for (int cp = 0; cp < 2; cp++)
                    #pragma unroll
                    for (int mt = 0; mt < 2; mt++) {
                        mma16816(sacc[mt][j], qhf[mt][2 * cp],     &klf[cur][cp][0]);
                        mma16816(sacc[mt][j], qhf[mt][2 * cp + 1], &klf[cur][cp][2]);
                    }
                #pragma unroll
                for (int cp = 0; cp < 2; cp++)
                    #pragma unroll
                    for (int mt = 0; mt < 2; mt++) {
                        mma16816(sacc[mt][j], qlf[mt][2 * cp],     &khf[cur][cp][0]);
                        mma16816(sacc[mt][j], qlf[mt][2 * cp + 1], &khf[cur][cp][2]);
                    }
            }
            if (more) { load_kv_part(kvt + 1, ns, 0); load_kv_part(kvt + 1, ns, 1); }

            if (c_base + 63 > wrow_min) {
                #pragma unroll
                for (int mt = 0; mt < 2; mt++) {
                    const int lr0 = wrow_min + 16 * mt + g;
                    #pragma unroll
                    for (int j = 0; j < 8; j++) {
                        const int c0 = c_base + 8 * j + 2 * t;
                        if (c0     > lr0)     sacc[mt][j][0] = -1e30f;
                        if (c0 + 1 > lr0)     sacc[mt][j][1] = -1e30f;
                        if (c0     > lr0 + 8) sacc[mt][j][2] = -1e30f;
                        if (c0 + 1 > lr0 + 8) sacc[mt][j][3] = -1e30f;
                    }
                }
            }

            #pragma unroll
            for (int mt = 0; mt < 2; mt++) {
                float mx0 = -1e30f, mx1 = -1e30f;
                #pragma unroll
                for (int j = 0; j < 8; j++) {
                    mx0 = fmaxf(mx0, fmaxf(sacc[mt][j][0], sacc[mt][j][1]));
                    mx1 = fmaxf(mx1, fmaxf(sacc[mt][j][2], sacc[mt][j][3]));
                }
                mx0 = fmaxf(mx0, __shfl_xor_sync(0xffffffffu, mx0, 1));
                mx0 = fmaxf(mx0, __shfl_xor_sync(0xffffffffu, mx0, 2));
                mx1 = fmaxf(mx1, __shfl_xor_sync(0xffffffffu, mx1, 1));
                mx1 = fmaxf(mx1, __shfl_xor_sync(0xffffffffu, mx1, 2));
                const float mn0 = fmaxf(mrow[mt][0], mx0), mn1 = fmaxf(mrow[mt][1], mx1);
                const float al0 = exp2f(mrow[mt][0] - mn0), al1 = exp2f(mrow[mt][1] - mn1);
                float sum0 = 0.f, sum1 = 0.f;
                #pragma unroll
                for (int j = 0; j < 8; j++) {
                    sacc[mt][j][0] = exp2f(sacc[mt][j][0] - mn0);
                    sacc[mt][j][1] = exp2f(sacc[mt][j][1] - mn0);
                    sacc[mt][j][2] = exp2f(sacc[mt][j][2] - mn1);
                    sacc[mt][j][3] = exp2f(sacc[mt][j][3] - mn1);
                    sum0 += sacc[mt][j][0] + sacc[mt][j][1];
                    sum1 += sacc[mt][j][2] + sacc[mt][j][3];
                }
                sum0 += __shfl_xor_sync(0xffffffffu, sum0, 1);
                sum0 += __shfl_xor_sync(0xffffffffu, sum0, 2);
                sum1 += __shfl_xor_sync(0xffffffffu, sum1, 1);
                sum1 += __shfl_xor_sync(0xffffffffu, sum1, 2);
                lrow[mt][0] = lrow[mt][0] * al0 + sum0; mrow[mt][0] = mn0;
                lrow[mt][1] = lrow[mt][1] * al1 + sum1; mrow[mt][1] = mn1;
                #pragma unroll
                for (int j = 0; j < 8; j++) {
                    oacc[mt][j][0] *= al0; oacc[mt][j][1] *= al0;
                    oacc[mt][j][2] *= al1; oacc[mt][j][3] *= al1;
                }
            }

            // ---- O += P V: vhf preloaded, vlf interleaved into pass 1 ----
            #pragma unroll
            for (int s2 = 0; s2 < 4; s2++) {
                uint32_t pah[2][4], pal[2][4];
                #pragma unroll
                for (int mt = 0; mt < 2; mt++) {
                    split2(sacc[mt][2 * s2][0],     sacc[mt][2 * s2][1],     pah[mt][0], pal[mt][0]);
                    split2(sacc[mt][2 * s2][2],     sacc[mt][2 * s2][3],     pah[mt][1], pal[mt][1]);
                    split2(sacc[mt][2 * s2 + 1][0], sacc[mt][2 * s2 + 1][1], pah[mt][2], pal[mt][2]);
                    split2(sacc[mt][2 * s2 + 1][2], sacc[mt][2 * s2 + 1][3], pah[mt][3], pal[mt][3]);
                }
                uint32_t vhf[4][4], vlf[4][4];
                #pragma unroll
                for (int jp = 0; jp < 4; jp++) {
                    uint32_t ad = kb + 2 * AT_KTILE +
                        (uint32_t)((16 * s2 + (lane & 15)) * AT_ROWB + (2 * jp + (lane >> 4)) * 16);
                    ldsm4t(vhf[jp], ad);
                }
                #pragma unroll
                for (int jp = 0; jp < 4; jp++) {
                    uint32_t ad = kb + 2 * AT_KTILE +
                        (uint32_t)((16 * s2 + (lane & 15)) * AT_ROWB + (2 * jp + (lane >> 4)) * 16);
                    ldsm4t(vlf[jp], ad + AT_KTILE);
                    #pragma unroll
                    for (int mt = 0; mt < 2; mt++) {
                        mma16816(oacc[mt][2 * jp],     pah[mt], &vhf[jp][0]);
                        mma16816(oacc[mt][2 * jp + 1], pah[mt], &vhf[jp][2]);
                    }
                }
                #pragma unroll
                for (int jp = 0; jp < 4; jp++)
                    #pragma unroll
                    for (int mt = 0; mt < 2; mt++) {
                        mma16816(oacc[mt][2 * jp],     pah[mt], &vlf[jp][0]);
                        mma16816(oacc[mt][2 * jp + 1], pah[mt], &vlf[jp][2]);
                    }
                #pragma unroll
                for (int jp = 0; jp < 4; jp++)
                    #pragma unroll
                    for (int mt = 0; mt < 2; mt++) {
                        mma16816(oacc[mt][2 * jp],     pal[mt], &vhf[jp][0]);
                        mma16816(oacc[mt][2 * jp + 1], pal[mt], &vhf[jp][2]);
                    }
                if (more && s2 == 0) load_kv_part(kvt + 1, ns, 2);
                if (more && s2 == 2) load_kv_part(kvt + 1, ns, 3);
            }
        } else if (more) {
            #pragma unroll
            for (int a = 0; a < 4; a++) load_kv_part(kvt + 1, ns, a);
        }
        asm volatile("cp.async.commit_group;" ::: "memory");
    }
    __syncthreads();

    const uint32_t oh0 = sb + AT_KV0, ol0 = oh0 + 128 * AT_ROWB;
    #pragma unroll
    for (int mt = 0; mt < 2; mt++) {
        const float i0 = 1.f / lrow[mt][0], i1 = 1.f / lrow[mt][1];
        const int rl = 32 * w + 16 * mt + g;
        #pragma unroll
        for (int j = 0; j < 8; j++) {
            const int cl = 8 * j + 2 * t;
            uint32_t hu, lu;
            split2(oacc[mt][j][0] * i0, oacc[mt][j][1] * i0, hu, lu);
            sts32(oh0 + (uint32_t)(rl * AT_ROWB + cl * 2), hu);
            sts32(ol0 + (uint32_t)(rl * AT_ROWB + cl * 2), lu);
            split2(oacc[mt][j][2] * i1, oacc[mt][j][3] * i1, hu, lu);
            sts32(oh0 + (uint32_t)((rl + 8) * AT_ROWB + cl * 2), hu);
            sts32(ol0 + (uint32_t)((rl + 8) * AT_ROWB + cl * 2), lu);
        }
    }
    __syncthreads();
    const int b = bh >> 4, h = bh & 15;
    #pragma unroll
    for (int it = 0; it < 8; it++) {
        const int id = it * 128 + tid, r = id >> 3, s = id & 7;
        const size_t dst = ((size_t)b * P_SZ + q0 + r) * K_SZ + h * 64 + s * 8;
        uint4 vh4 = lds128(oh0 + (uint32_t)(r * AT_ROWB + s * 16));
        uint4 vl4 = lds128(ol0 + (uint32_t)(r * AT_ROWB + s * 16));
        *(uint4*)(zh + dst) = vh4;
        *(uint4*)(zl + dst) = vl4;
    }
}

// ---------------------------------------------------------------------------
extern "C" void kernel_launch(void* const* d_in, const int* in_sizes, int n_in,
                              void* d_out, int out_size)
{
    (void)in_sizes; (void)n_in; (void)out_size;
    const float* x      = (const float*)d_in[0];
    const float* W_attn = (const float*)d_in[1];
    const float* b_attn = (const float*)d_in[2];
    const float* W_proj = (const float*)d_in[3];
    const float* b_proj = (const float*)d_in[4];
    float* out = (float*)d_out;

    __nv_bfloat16 *xhi, *xlo, *wah, *wal, *wph, *wpl;
    __nv_bfloat16 *qh, *ql, *kh, *kl, *vh, *vl, *zh, *zl;
    cudaGetSymbolAddress((void**)&xhi, g_xhi);
    cudaGetSymbolAddress((void**)&xlo, g_xlo);
    cudaGetSymbolAddress((void**)&wah, g_wah);
    cudaGetSymbolAddress((void**)&wal, g_wal);
    cudaGetSymbolAddress((void**)&wph, g_wph);
    cudaGetSymbolAddress((void**)&wpl, g_wpl);
    cudaGetSymbolAddress((void**)&qh,  g_qh);
    cudaGetSymbolAddress((void**)&ql,  g_ql);
    cudaGetSymbolAddress((void**)&kh,  g_kh);
    cudaGetSymbolAddress((void**)&kl,  g_kl);
    cudaGetSymbolAddress((void**)&vh,  g_vh);
    cudaGetSymbolAddress((void**)&vl,  g_vl);
    cudaGetSymbolAddress((void**)&zh,  g_zh);
    cudaGetSymbolAddress((void**)&zl,  g_zl);

    cudaFuncSetAttribute(gemm_mma_kernel<0>,
                         cudaFuncAttributeMaxDynamicSharedMemorySize, GT_SMEM);
    cudaFuncSetAttribute(gemm_mma_kernel<1>,
                         cudaFuncAttributeMaxDynamicSharedMemorySize, GT_SMEM);
    cudaFuncSetAttribute(attn_mma_kernel,
                         cudaFuncAttributeMaxDynamicSharedMemorySize, AT_SMEM);

    split_kernel<<<(R_SZ * K_SZ / 4 + 255) / 256, 256>>>(x, xhi, xlo, R_SZ * K_SZ / 4);
    tsplit_kernel<<<dim3(N3_SZ / 32, K_SZ / 32), 256>>>(W_attn, wah, wal, K_SZ, N3_SZ);
    tsplit_kernel<<<dim3(M_SZ / 32, K_SZ / 32), 256>>>(W_proj, wph, wpl, K_SZ, M_SZ);

    gemm_mma_kernel<1><<<dim3(N3_SZ / 128, R_SZ / 128), 128, GT_SMEM>>>(
        xhi, xlo, wah, wal, b_attn, nullptr, N3_SZ, qh, ql, kh, kl, vh, vl);

    attn_mma_kernel<<<dim3(P_SZ / 128, BH_SZ), 128, AT_SMEM>>>(
        qh, ql, kh, kl, vh, vl, zh, zl);

    gemm_mma_kernel<0><<<dim3(M_SZ / 128, R_SZ / 128), 128, GT_SMEM>>>(
        zh, zl, wph, wpl, b_proj, out, M_SZ,
        nullptr, nullptr, nullptr, nullptr, nullptr, nullptr);
}

// round 11
// speedup vs baseline: 1.1732x; 1.0096x over previous
#include <cuda_runtime.h>
#include <cuda_bf16.h>
#include <cstdint>
#include <string.h>
#include <math.h>

#define B_SZ 2
#define P_SZ 2048
#define M_SZ 1024
#define H_SZ 16
#define D_SZ 64
#define N3_SZ 3072
#define R_SZ (B_SZ * P_SZ)      // 4096
#define K_SZ M_SZ               // 1024
#define BH_SZ (B_SZ * H_SZ)     // 32

// ---------------- scratch (__device__ globals) -----------------------------
__device__ __nv_bfloat16 g_xhi[(size_t)R_SZ * K_SZ];
__device__ __nv_bfloat16 g_xlo[(size_t)R_SZ * K_SZ];
__device__ __nv_bfloat16 g_wah[(size_t)N3_SZ * K_SZ];
__device__ __nv_bfloat16 g_wal[(size_t)N3_SZ * K_SZ];
__device__ __nv_bfloat16 g_wph[(size_t)M_SZ * K_SZ];
__device__ __nv_bfloat16 g_wpl[(size_t)M_SZ * K_SZ];
__device__ __nv_bfloat16 g_qh[(size_t)BH_SZ * P_SZ * D_SZ];
__device__ __nv_bfloat16 g_ql[(size_t)BH_SZ * P_SZ * D_SZ];
__device__ __nv_bfloat16 g_kh[(size_t)BH_SZ * P_SZ * D_SZ];
__device__ __nv_bfloat16 g_kl[(size_t)BH_SZ * P_SZ * D_SZ];
__device__ __nv_bfloat16 g_vh[(size_t)BH_SZ * P_SZ * D_SZ];
__device__ __nv_bfloat16 g_vl[(size_t)BH_SZ * P_SZ * D_SZ];
__device__ __nv_bfloat16 g_zh[(size_t)R_SZ * K_SZ];
__device__ __nv_bfloat16 g_zl[(size_t)R_SZ * K_SZ];

// ---------------- PTX helpers (base ISA) -----------------------------------
__device__ __forceinline__ uint32_t smem_u32(const void* p) {
    uint32_t a;
    asm("{ .reg .u64 t; cvta.to.shared.u64 t, %1; cvt.u32.u64 %0, t; }" : "=r"(a) : "l"(p));
    return a;
}
__device__ __forceinline__ void ldsm4(uint32_t* r, uint32_t addr) {
    asm volatile("ldmatrix.sync.aligned.m8n8.x4.shared.b16 {%0,%1,%2,%3}, [%4];"
                 : "=r"(r[0]), "=r"(r[1]), "=r"(r[2]), "=r"(r[3]) : "r"(addr));
}
__device__ __forceinline__ void ldsm4t(uint32_t* r, uint32_t addr) {
    asm volatile("ldmatrix.sync.aligned.m8n8.x4.trans.shared.b16 {%0,%1,%2,%3}, [%4];"
                 : "=r"(r[0]), "=r"(r[1]), "=r"(r[2]), "=r"(r[3]) : "r"(addr));
}
__device__ __forceinline__ void mma16816(float* c, const uint32_t* a, const uint32_t* b) {
    asm volatile(
        "mma.sync.aligned.m16n8k16.row.col.f32.bf16.bf16.f32 "
        "{%0,%1,%2,%3}, {%4,%5,%6,%7}, {%8,%9}, {%0,%1,%2,%3};"
        : "+f"(c[0]), "+f"(c[1]), "+f"(c[2]), "+f"(c[3])
        : "r"(a[0]), "r"(a[1]), "r"(a[2]), "r"(a[3]), "r"(b[0]), "r"(b[1]));
}
__device__ __forceinline__ void cpasync16(uint32_t saddr, const void* gaddr) {
    asm volatile("cp.async.cg.shared.global [%0], [%1], 16;" :: "r"(saddr), "l"(gaddr) : "memory");
}
__device__ __forceinline__ void sts32(uint32_t addr, uint32_t v) {
    asm volatile("st.shared.b32 [%0], %1;" :: "r"(addr), "r"(v) : "memory");
}
__device__ __forceinline__ void sts64(uint32_t addr, float a, float b) {
    asm volatile("st.shared.v2.f32 [%0], {%1,%2};" :: "r"(addr), "f"(a), "f"(b) : "memory");
}
__device__ __forceinline__ uint4 lds128(uint32_t addr) {
    uint4 v;
    asm volatile("ld.shared.v4.b32 {%0,%1,%2,%3}, [%4];"
                 : "=r"(v.x), "=r"(v.y), "=r"(v.z), "=r"(v.w) : "r"(addr));
    return v;
}
__device__ __forceinline__ void split2(float a, float b, uint32_t& hu, uint32_t& lu) {
    __nv_bfloat16 ha = __float2bfloat16(a), hb = __float2bfloat16(b);
    float ra = a - __bfloat162float(ha), rb = b - __bfloat162float(hb);
    __nv_bfloat162 H = __halves2bfloat162(ha, hb);
    __nv_bfloat162 L = __floats2bfloat162_rn(ra, rb);
    memcpy(&hu, &H, 4); memcpy(&lu, &L, 4);
}

// ---------------- fp32 -> bf16 hi/lo split ---------------------------------
struct alignas(8) bf16x4 { __nv_bfloat162 a, b; };

__global__ __launch_bounds__(256) void split_kernel(
    const float* __restrict__ in, __nv_bfloat16* __restrict__ hi,
    __nv_bfloat16* __restrict__ lo, int n4)
{
    int i = blockIdx.x * 256 + threadIdx.x;
    if (i >= n4) return;
    float4 v = ((const float4*)in)[i];
    float h0 = __bfloat162float(__float2bfloat16(v.x));
    float h1 = __bfloat162float(__float2bfloat16(v.y));
    float h2 = __bfloat162float(__float2bfloat16(v.z));
    float h3 = __bfloat162float(__float2bfloat16(v.w));
    bf16x4 H, L;
    H.a = __floats2bfloat162_rn(h0, h1);
    H.b = __floats2bfloat162_rn(h2, h3);
    L.a = __floats2bfloat162_rn(v.x - h0, v.y - h1);
    L.b = __floats2bfloat162_rn(v.z - h2, v.w - h3);
    ((bf16x4*)hi)[i] = H;
    ((bf16x4*)lo)[i] = L;
}

__global__ __launch_bounds__(256) void tsplit_kernel(
    const float* __restrict__ W, __nv_bfloat16* __restrict__ hi,
    __nv_bfloat16* __restrict__ lo, int K, int N)
{
    __shared__ float s[32][33];
    const int n0 = blockIdx.x * 32, k0 = blockIdx.y * 32;
    const int tx = threadIdx.x & 31, ty = threadIdx.x >> 5;
    #pragma unroll
    for (int i = 0; i < 4; i++)
        s[ty + 8 * i][tx] = W[(size_t)(k0 + ty + 8 * i) * N + n0 + tx];
    __syncthreads();
    #pragma unroll
    for (int i = 0; i < 4; i++) {
        int r = ty + 8 * i;
        float v = s[tx][r];
        float h = __bfloat162float(__float2bfloat16(v));
        size_t o = (size_t)(n0 + r) * K + k0 + tx;
        hi[o] = __float2bfloat16(h);
        lo[o] = __float2bfloat16(v - h);
    }
}

// ---------------- split-bf16 mma GEMM: 4 warps, 64x64 warp tile ------------
#define GK_CH   (K_SZ / 32)          // 32 chunks
#define GT_TILE 10240                // 128 rows * 80 B
#define GT_STG  (4 * GT_TILE)
#define GT_SMEM (2 * GT_STG)         // 81920 B

// Q pre-scale: 1/sqrt(64) * log2(e)  (softmax runs base-2)
#define QSCALE (0.125f * 1.44269504088896f)

template<int MODE>
__global__ __launch_bounds__(128) void gemm_mma_kernel(
    const __nv_bfloat16* __restrict__ Ah, const __nv_bfloat16* __restrict__ Al,
    const __nv_bfloat16* __restrict__ Bh, const __nv_bfloat16* __restrict__ Bl,
    const float* __restrict__ bias, float* __restrict__ C, int N,
    __nv_bfloat16* __restrict__ qh, __nv_bfloat16* __restrict__ ql,
    __nv_bfloat16* __restrict__ kh, __nv_bfloat16* __restrict__ kl,
    __nv_bfloat16* __restrict__ vh, __nv_bfloat16* __restrict__ vl)
{
    extern __shared__ char smraw[];
    const uint32_t sbase = smem_u32(smraw);

    const int tid = threadIdx.x;
    const int wid = tid >> 5, lane = tid & 31;
    const int wm = wid & 1, wn = wid >> 1;
    const int g = lane >> 2, t = lane & 3;
    const int row0 = blockIdx.y << 7;
    const int col0 = blockIdx.x << 7;

    const __nv_bfloat16* srcs[4] = {Ah, Al, Bh, Bl};

    auto load_part = [&](int c, int s, int arr) {
        const int k0 = c << 5;
        const __nv_bfloat16* src = srcs[arr];
        const int rbase = (arr < 2) ? row0 : col0;
        const uint32_t tb = sbase + (uint32_t)s * GT_STG + (uint32_t)arr * GT_TILE;
        #pragma unroll
        for (int it = 0; it < 4; it++) {
            int id = it * 128 + tid, r = id >> 2, q = id & 3;
            cpasync16(tb + (uint32_t)(r * 80 + q * 16),
                      src + (size_t)(rbase + r) * K_SZ + k0 + q * 8);
        }
    };

    float acc[4][8][4] = {};
    const int a_row = lane & 15;
    const int a_cb  = (lane >> 4) << 4;
    const int b2_row = (lane & 7) + ((lane >> 4) << 3);
    const int b2_cb  = ((lane >> 3) & 1) << 4;

    #pragma unroll
    for (int arr = 0; arr < 4; arr++) load_part(0, 0, arr);
    asm volatile("cp.async.commit_group;" ::: "memory");

    for (int c = 0; c < GK_CH; c++) {
        const int s = c & 1, ns = s ^ 1;
        asm volatile("cp.async.wait_group 0;" ::: "memory");
        __syncthreads();

        const uint32_t stg = sbase + (uint32_t)s * GT_STG;
        const uint32_t tAh = stg, tAl = stg + GT_TILE;
        const uint32_t tBh = stg + 2 * GT_TILE, tBl = stg + 3 * GT_TILE;
        const bool more = (c + 1 < GK_CH);

        #pragma unroll
        for (int ks = 0; ks < 2; ks++) {
            const int kb = ks << 5;
            uint32_t ah[4][4], al[4][4], bh[4][4], bl[4][4];
            #pragma unroll
            for (int mt = 0; mt < 4; mt++)
                ldsm4(ah[mt], tAh + (uint32_t)((wm * 64 + mt * 16 + a_row) * 80 + kb + a_cb));
            #pragma unroll
            for (int np = 0; np < 4; np++)
                ldsm4(bh[np], tBh + (uint32_t)((wn * 64 + np * 16 + b2_row) * 80 + kb + b2_cb));
            #pragma unroll
            for (int np = 0; np < 4; np++) {
                ldsm4(al[np], tAl + (uint32_t)((wm * 64 + np * 16 + a_row) * 80 + kb + a_cb));
                ldsm4(bl[np], tBl + (uint32_t)((wn * 64 + np * 16 + b2_row) * 80 + kb + b2_cb));
                #pragma unroll
                for (int mt = 0; mt < 4; mt++) {
                    mma16816(acc[mt][2 * np],     ah[mt], &bh[np][0]);
                    mma16816(acc[mt][2 * np + 1], ah[mt], &bh[np][2]);
                }
            }
            if (more) load_part(c + 1, ns, 2 * ks + 0);
            #pragma unroll
            for (int np = 0; np < 4; np++)
                #pragma unroll
                for (int mt = 0; mt < 4; mt++) {
                    mma16816(acc[mt][2 * np],     ah[mt], &bl[np][0]);
                    mma16816(acc[mt][2 * np + 1], ah[mt], &bl[np][2]);
                }
            if (more) load_part(c + 1, ns, 2 * ks + 1);
            #pragma unroll
            for (int np = 0; np < 4; np++)
                #pragma unroll
                for (int mt = 0; mt < 4; mt++) {
                    mma16816(acc[mt][2 * np],     al[mt], &bh[np][0]);
                    mma16816(acc[mt][2 * np + 1], al[mt], &bh[np][2]);
                }
        }
        asm volatile("cp.async.commit_group;" ::: "memory");
    }
    __syncthreads();

    if (MODE == 1) {
        const uint32_t hi0 = sbase, lo0 = sbase + 128 * 272;
        #pragma unroll
        for (int mt = 0; mt < 4; mt++) {
            const int rl = wm * 64 + mt * 16 + g;
            #pragma unroll
            for (int nt = 0; nt < 8; nt++) {
                const int cl = wn * 64 + nt * 8 + 2 * t;
                const int col = col0 + cl;
                const float b0 = bias[col], b1 = bias[col + 1];
                float v0 = acc[mt][nt][0] + b0, v1 = acc[mt][nt][1] + b1;
                float v2 = acc[mt][nt][2] + b0, v3 = acc[mt][nt][3] + b1;
                if (col < M_SZ) { v0 *= QSCALE; v1 *= QSCALE; v2 *= QSCALE; v3 *= QSCALE; }
                uint32_t hu, lu;
                split2(v0, v1, hu, lu);
                sts32(hi0 + (uint32_t)(rl * 272 + cl * 2), hu);
                sts32(lo0 + (uint32_t)(rl * 272 + cl * 2), lu);
                split2(v2, v3, hu, lu);
                sts32(hi0 + (uint32_t)((rl + 8) * 272 + cl * 2), hu);
                sts32(lo0 + (uint32_t)((rl + 8) * 272 + cl * 2), lu);
            }
        }
        __syncthreads();
        #pragma unroll
        for (int it = 0; it < 16; it++) {
            const int id = it * 128 + tid, r = id >> 4, s = id & 15;
            const int col = col0 + s * 8;
            const int slice = col >> 10, hh = (col >> 6) & 15, dd = col & 63;
            __nv_bfloat16* oh = (slice == 0) ? qh : (slice == 1) ? kh : vh;
            __nv_bfloat16* ol = (slice == 0) ? ql : (slice == 1) ? kl : vl;
            const int row = row0 + r;
            const int ba = row >> 11, pa = row & 2047;
            const size_t oa = ((size_t)(ba * H_SZ + hh) * P_SZ + pa) * 64 + dd;
            uint4 vh4 = lds128(hi0 + (uint32_t)(r * 272 + s * 16));
            uint4 vl4 = lds128(lo0 + (uint32_t)(r * 272 + s * 16));
            *(uint4*)(oh + oa) = vh4;
            *(uint4*)(ol + oa) = vl4;
        }
    } else {
        #pragma unroll
        for (int mt = 0; mt < 4; mt++) {
            const int rl = wm * 64 + mt * 16 + g;
            #pragma unroll
            for (int nt = 0; nt < 8; nt++) {
                const int cl = wn * 64 + nt * 8 + 2 * t;
                const int col = col0 + cl;
                const float b0 = bias[col], b1 = bias[col + 1];
                sts64(sbase + (uint32_t)(rl * 528 + cl * 4),
                      acc[mt][nt][0] + b0, acc[mt][nt][1] + b1);
                sts64(sbase + (uint32_t)((rl + 8) * 528 + cl * 4),
                      acc[mt][nt][2] + b0, acc[mt][nt][3] + b1);
            }
        }
        __syncthreads();
        #pragma unroll
        for (int it = 0; it < 32; it++) {
            const int id = it * 128 + tid, r = id >> 5, s = id & 31;
            uint4 v = lds128(sbase + (uint32_t)(r * 528 + s * 16));
            *(uint4*)(C + (size_t)(row0 + r) * N + col0 + s * 4) = v;
        }
    }
}

// ---------------- tensor-core flash attention: 4 warps x 32 q-rows ---------
// smem layout (73.7 KB -> 2 CTAs/SM):
//   [0, AT_STG)        : Q hi/lo during prologue; KV stage 1 afterwards;
//                        O hi/lo staging in the epilogue
//   [AT_STG, 2*AT_STG) : KV stage 0
#define AT_ROWB 144
#define AT_QTILE (128 * AT_ROWB)        // 18432
#define AT_KTILE (64 * AT_ROWB)         // 9216
#define AT_STG   (4 * AT_KTILE)         // 36864
#define AT_SMEM  (2 * AT_STG)           // 73728

__global__ __launch_bounds__(128) void attn_mma_kernel(
    const __nv_bfloat16* __restrict__ qh, const __nv_bfloat16* __restrict__ ql,
    const __nv_bfloat16* __restrict__ kh, const __nv_bfloat16* __restrict__ kl,
    const __nv_bfloat16* __restrict__ vh, const __nv_bfloat16* __restrict__ vl,
    __nv_bfloat16* __restrict__ zh, __nv_bfloat16* __restrict__ zl)
{
    extern __shared__ char smraw[];
    const uint32_t sb = smem_u32(smraw);
    const int tid = threadIdx.x, w = tid >> 5, lane = tid & 31;
    const int g = lane >> 2, t = lane & 3;
    const int qt = blockIdx.x, bh = blockIdx.y;
    const int q0 = qt << 7;
    const size_t hb = (size_t)bh * P_SZ * 64;

    const __nv_bfloat16* kvsrc[4] = {kh + hb, kl + hb, vh + hb, vl + hb};
    auto stage_base = [&](int s) -> uint32_t { return (s == 0) ? sb + AT_STG : sb; };
    auto load_kv_part = [&](int kvt, int s, int a) {
        const uint32_t stg = stage_base(s);
        const size_t rb = (size_t)(kvt << 6) * 64;
        #pragma unroll
        for (int it = 0; it < 4; it++) {
            int id = it * 128 + tid, r = id >> 3, c = id & 7;
            cpasync16(stg + (uint32_t)(a * AT_KTILE + r * AT_ROWB + c * 16),
                      kvsrc[a] + rb + r * 64 + c * 8);
        }
    };

    {   // Q hi/lo into region 0 (will become KV stage 1)
        const __nv_bfloat16* Qh = qh + hb + (size_t)q0 * 64;
        const __nv_bfloat16* Ql = ql + hb + (size_t)q0 * 64;
        #pragma unroll
        for (int it = 0; it < 8; it++) {
            int id = it * 128 + tid, r = id >> 3, c = id & 7;
            cpasync16(sb + (uint32_t)(r * AT_ROWB + c * 16), Qh + r * 64 + c * 8);
            cpasync16(sb + AT_QTILE + (uint32_t)(r * AT_ROWB + c * 16), Ql + r * 64 + c * 8);
        }
    }
    #pragma unroll
    for (int a = 0; a < 4; a++) load_kv_part(0, 0, a);
    asm volatile("cp.async.commit_group;" ::: "memory");
    asm volatile("cp.async.wait_group 0;" ::: "memory");
    __syncthreads();

    // extract Q fragments (Q region is dead afterwards)
    uint32_t qhf[2][4][4], qlf[2][4][4];
    const int arow = (lane & 7) + ((lane >> 3) & 1) * 8;
    const int achk = lane >> 4;
    #pragma unroll
    for (int mt = 0; mt < 2; mt++)
        #pragma unroll
        for (int ks = 0; ks < 4; ks++) {
            uint32_t ad = sb + (uint32_t)((32 * w + 16 * mt + arow) * AT_ROWB +
                                          (2 * ks + achk) * 16);
            ldsm4(qhf[mt][ks], ad);
            ldsm4(qlf[mt][ks], ad + AT_QTILE);
        }
    __syncthreads();   // Q reads done before anyone writes stage 1

    float oacc[2][8][4] = {};
    float mrow[2][2], lrow[2][2];
    #pragma unroll
    for (int mt = 0; mt < 2; mt++) {
        mrow[mt][0] = -1e30f; mrow[mt][1] = -1e30f;
        lrow[mt][0] = 0.f;    lrow[mt][1] = 0.f;
    }
    const int wrow_min = q0 + 32 * w;
    const int wrow_max = wrow_min + 31;
    const int ntiles = 2 * qt + 2;

    for (int kvt = 0; kvt < ntiles; kvt++) {
        const int s = kvt & 1, ns = s ^ 1;
        if (kvt > 0) {
            asm volatile("cp.async.wait_group 0;" ::: "memory");
            __syncthreads();
        }
        const bool more = (kvt + 1 < ntiles);
        const int c_base = kvt << 6;
        if (c_base <= wrow_max) {
            const uint32_t kb = stage_base(s);

            // ---- S = Q K^T: K-fragments double-buffered across j ----
            float sacc[2][8][4] = {};
            uint32_t khf[2][2][4], klf[2][2][4];
            #pragma unroll
            for (int cp = 0; cp < 2; cp++) {
                uint32_t ad = kb + (uint32_t)((lane & 7) * AT_ROWB + (4 * cp + (lane >> 3)) * 16);
                ldsm4(khf[0][cp], ad);
                ldsm4(klf[0][cp], ad + AT_KTILE);
            }
            #pragma unroll
            for (int j = 0; j < 8; j++) {
                const int cur = j & 1, nxt = cur ^ 1;
                if (j < 7) {
                    #pragma unroll
                    for (int cp = 0; cp < 2; cp++) {
                        uint32_t ad = kb + (uint32_t)((8 * (j + 1) + (lane & 7)) * AT_ROWB +
                                                      (4 * cp + (lane >> 3)) * 16);
                        ldsm4(khf[nxt][cp], ad);
                        ldsm4(klf[nxt][cp], ad + AT_KTILE);
                    }
                }
                #pragma unroll
                for (int cp = 0; cp < 2; cp++)
                    #pragma unroll
                    for (int mt = 0; mt < 2; mt++) {
                        mma16816(sacc[mt][j], qhf[mt][2 * cp],     &khf[cur][cp][0]);
                        mma16816(sacc[mt][j], qhf[mt][2 * cp + 1], &khf[cur][cp][2]);
                    }
                #pragma unroll
                for (int cp = 0; cp < 2; cp++)
                    #pragma unroll
                    for (int mt = 0; mt < 2; mt++) {
                        mma16816(sacc[mt][j], qhf[mt][2 * cp],     &klf[cur][cp][0]);
                        mma16816(sacc[mt][j], qhf[mt][2 * cp + 1], &klf[cur][cp][2]);
                    }
                #pragma unroll
                for (int cp = 0; cp < 2; cp++)
                    #pragma unroll
                    for (int mt = 0; mt < 2; mt++) {
                        mma16816(sacc[mt][j], qlf[mt][2 * cp],     &khf[cur][cp][0]);
                        mma16816(sacc[mt][j], qlf[mt][2 * cp + 1], &khf[cur][cp][2]);
                    }
            }
            if (more) { load_kv_part(kvt + 1, ns, 0); load_kv_part(kvt + 1, ns, 1); }

            if (c_base + 63 > wrow_min) {
                #pragma unroll
                for (int mt = 0; mt < 2; mt++) {
                    const int lr0 = wrow_min + 16 * mt + g;
                    #pragma unroll
                    for (int j = 0; j < 8; j++) {
                        const int c0 = c_base + 8 * j + 2 * t;
                        if (c0     > lr0)     sacc[mt][j][0] = -1e30f;
                        if (c0 + 1 > lr0)     sacc[mt][j][1] = -1e30f;
                        if (c0     > lr0 + 8) sacc[mt][j][2] = -1e30f;
                        if (c0 + 1 > lr0 + 8) sacc[mt][j][3] = -1e30f;
                    }
                }
            }

            #pragma unroll
            for (int mt = 0; mt < 2; mt++) {
                float mx0 = -1e30f, mx1 = -1e30f;
                #pragma unroll
                for (int j = 0; j < 8; j++) {
                    mx0 = fmaxf(mx0, fmaxf(sacc[mt][j][0], sacc[mt][j][1]));
                    mx1 = fmaxf(mx1, fmaxf(sacc[mt][j][2], sacc[mt][j][3]));
                }
                mx0 = fmaxf(mx0, __shfl_xor_sync(0xffffffffu, mx0, 1));
                mx0 = fmaxf(mx0, __shfl_xor_sync(0xffffffffu, mx0, 2));
                mx1 = fmaxf(mx1, __shfl_xor_sync(0xffffffffu, mx1, 1));
                mx1 = fmaxf(mx1, __shfl_xor_sync(0xffffffffu, mx1, 2));
                const float mn0 = fmaxf(mrow[mt][0], mx0), mn1 = fmaxf(mrow[mt][1], mx1);
                const float al0 = exp2f(mrow[mt][0] - mn0), al1 = exp2f(mrow[mt][1] - mn1);
                float sum0 = 0.f, sum1 = 0.f;
                #pragma unroll
                for (int j = 0; j < 8; j++) {
                    sacc[mt][j][0] = exp2f(sacc[mt][j][0] - mn0);
                    sacc[mt][j][1] = exp2f(sacc[mt][j][1] - mn0);
                    sacc[mt][j][2] = exp2f(sacc[mt][j][2] - mn1);
                    sacc[mt][j][3] = exp2f(sacc[mt][j][3] - mn1);
                    sum0 += sacc[mt][j][0] + sacc[mt][j][1];
                    sum1 += sacc[mt][j][2] + sacc[mt][j][3];
                }
                sum0 += __shfl_xor_sync(0xffffffffu, sum0, 1);
                sum0 += __shfl_xor_sync(0xffffffffu, sum0, 2);
                sum1 += __shfl_xor_sync(0xffffffffu, sum1, 1);
                sum1 += __shfl_xor_sync(0xffffffffu, sum1, 2);
                lrow[mt][0] = lrow[mt][0] * al0 + sum0; mrow[mt][0] = mn0;
                lrow[mt][1] = lrow[mt][1] * al1 + sum1; mrow[mt][1] = mn1;
                #pragma unroll
                for (int j = 0; j < 8; j++) {
                    oacc[mt][j][0] *= al0; oacc[mt][j][1] *= al0;
                    oacc[mt][j][2] *= al1; oacc[mt][j][3] *= al1;
                }
            }

            // ---- O += P V ----
            #pragma unroll
            for (int s2 = 0; s2 < 4; s2++) {
                uint32_t pah[2][4], pal[2][4];
                #pragma unroll
                for (int mt = 0; mt < 2; mt++) {
                    split2(sacc[mt][2 * s2][0],     sacc[mt][2 * s2][1],     pah[mt][0], pal[mt][0]);
                    split2(sacc[mt][2 * s2][2],     sacc[mt][2 * s2][3],     pah[mt][1], pal[mt][1]);
                    split2(sacc[mt][2 * s2 + 1][0], sacc[mt][2 * s2 + 1][1], pah[mt][2], pal[mt][2]);
                    split2(sacc[mt][2 * s2 + 1][2], sacc[mt][2 * s2 + 1][3], pah[mt][3], pal[mt][3]);
                }
                uint32_t vhf[4][4], vlf[4][4];
                #pragma unroll
                for (int jp = 0; jp < 4; jp++) {
                    uint32_t ad = kb + 2 * AT_KTILE +
                        (uint32_t)((16 * s2 + (lane & 15)) * AT_ROWB + (2 * jp + (lane >> 4)) * 16);
                    ldsm4t(vhf[jp], ad);
                }
                #pragma unroll
                for (int jp = 0; jp < 4; jp++) {
                    uint32_t ad = kb + 2 * AT_KTILE +
                        (uint32_t)((16 * s2 + (lane & 15)) * AT_ROWB + (2 * jp + (lane >> 4)) * 16);
                    ldsm4t(vlf[jp], ad + AT_KTILE);
                    #pragma unroll
                    for (int mt = 0; mt < 2; mt++) {
                        mma16816(oacc[mt][2 * jp],     pah[mt], &vhf[jp][0]);
                        mma16816(oacc[mt][2 * jp + 1], pah[mt], &vhf[jp][2]);
                    }
                }
                #pragma unroll
                for (int jp = 0; jp < 4; jp++)
                    #pragma unroll
                    for (int mt = 0; mt < 2; mt++) {
                        mma16816(oacc[mt][2 * jp],     pah[mt], &vlf[jp][0]);
                        mma16816(oacc[mt][2 * jp + 1], pah[mt], &vlf[jp][2]);
                    }
                #pragma unroll
                for (int jp = 0; jp < 4; jp++)
                    #pragma unroll
                    for (int mt = 0; mt < 2; mt++) {
                        mma16816(oacc[mt][2 * jp],     pal[mt], &vhf[jp][0]);
                        mma16816(oacc[mt][2 * jp + 1], pal[mt], &vhf[jp][2]);
                    }
                if (more && s2 == 0) load_kv_part(kvt + 1, ns, 2);
                if (more && s2 == 2) load_kv_part(kvt + 1, ns, 3);
            }
        } else if (more) {
            #pragma unroll
            for (int a = 0; a < 4; a++) load_kv_part(kvt + 1, ns, a);
        }
        asm volatile("cp.async.commit_group;" ::: "memory");
    }
    __syncthreads();

    // epilogue staging in region 0
    const uint32_t oh0 = sb, ol0 = sb + AT_QTILE;
    #pragma unroll
    for (int mt = 0; mt < 2; mt++) {
        const float i0 = 1.f / lrow[mt][0], i1 = 1.f / lrow[mt][1];
        const int rl = 32 * w + 16 * mt + g;
        #pragma unroll
        for (int j = 0; j < 8; j++) {
            const int cl = 8 * j + 2 * t;
            uint32_t hu, lu;
            split2(oacc[mt][j][0] * i0, oacc[mt][j][1] * i0, hu, lu);
            sts32(oh0 + (uint32_t)(rl * AT_ROWB + cl * 2), hu);
            sts32(ol0 + (uint32_t)(rl * AT_ROWB + cl * 2), lu);
            split2(oacc[mt][j][2] * i1, oacc[mt][j][3] * i1, hu, lu);
            sts32(oh0 + (uint32_t)((rl + 8) * AT_ROWB + cl * 2), hu);
            sts32(ol0 + (uint32_t)((rl + 8) * AT_ROWB + cl * 2), lu);
        }
    }
    __syncthreads();
    const int b = bh >> 4, h = bh & 15;
    #pragma unroll
    for (int it = 0; it < 8; it++) {
        const int id = it * 128 + tid, r = id >> 3, s = id & 7;
        const size_t dst = ((size_t)b * P_SZ + q0 + r) * K_SZ + h * 64 + s * 8;
        uint4 vh4 = lds128(oh0 + (uint32_t)(r * AT_ROWB + s * 16));
        uint4 vl4 = lds128(ol0 + (uint32_t)(r * AT_ROWB + s * 16));
        *(uint4*)(zh + dst) = vh4;
        *(uint4*)(zl + dst) = vl4;
    }
}

// ---------------------------------------------------------------------------
extern "C" void kernel_launch(void* const* d_in, const int* in_sizes, int n_in,
                              void* d_out, int out_size)
{
    (void)in_sizes; (void)n_in; (void)out_size;
    const float* x      = (const float*)d_in[0];
    const float* W_attn = (const float*)d_in[1];
    const float* b_attn = (const float*)d_in[2];
    const float* W_proj = (const float*)d_in[3];
    const float* b_proj = (const float*)d_in[4];
    float* out = (float*)d_out;

    __nv_bfloat16 *xhi, *xlo, *wah, *wal, *wph, *wpl;
    __nv_bfloat16 *qh, *ql, *kh, *kl, *vh, *vl, *zh, *zl;
    cudaGetSymbolAddress((void**)&xhi, g_xhi);
    cudaGetSymbolAddress((void**)&xlo, g_xlo);
    cudaGetSymbolAddress((void**)&wah, g_wah);
    cudaGetSymbolAddress((void**)&wal, g_wal);
    cudaGetSymbolAddress((void**)&wph, g_wph);
    cudaGetSymbolAddress((void**)&wpl, g_wpl);
    cudaGetSymbolAddress((void**)&qh,  g_qh);
    cudaGetSymbolAddress((void**)&ql,  g_ql);
    cudaGetSymbolAddress((void**)&kh,  g_kh);
    cudaGetSymbolAddress((void**)&kl,  g_kl);
    cudaGetSymbolAddress((void**)&vh,  g_vh);
    cudaGetSymbolAddress((void**)&vl,  g_vl);
    cudaGetSymbolAddress((void**)&zh,  g_zh);
    cudaGetSymbolAddress((void**)&zl,  g_zl);

    cudaFuncSetAttribute(gemm_mma_kernel<0>,
                         cudaFuncAttributeMaxDynamicSharedMemorySize, GT_SMEM);
    cudaFuncSetAttribute(gemm_mma_kernel<1>,
                         cudaFuncAttributeMaxDynamicSharedMemorySize, GT_SMEM);
    cudaFuncSetAttribute(attn_mma_kernel,
                         cudaFuncAttributeMaxDynamicSharedMemorySize, AT_SMEM);

    split_kernel<<<(R_SZ * K_SZ / 4 + 255) / 256, 256>>>(x, xhi, xlo, R_SZ * K_SZ / 4);
    tsplit_kernel<<<dim3(N3_SZ / 32, K_SZ / 32), 256>>>(W_attn, wah, wal, K_SZ, N3_SZ);
    tsplit_kernel<<<dim3(M_SZ / 32, K_SZ / 32), 256>>>(W_proj, wph, wpl, K_SZ, M_SZ);

    gemm_mma_kernel<1><<<dim3(N3_SZ / 128, R_SZ / 128), 128, GT_SMEM>>>(
        xhi, xlo, wah, wal, b_attn, nullptr, N3_SZ, qh, ql, kh, kl, vh, vl);

    attn_mma_kernel<<<dim3(P_SZ / 128, BH_SZ), 128, AT_SMEM>>>(
        qh, ql, kh, kl, vh, vl, zh, zl);

    gemm_mma_kernel<0><<<dim3(M_SZ / 128, R_SZ / 128), 128, GT_SMEM>>>(
        zh, zl, wph, wpl, b_proj, out, M_SZ,
        nullptr, nullptr, nullptr, nullptr, nullptr, nullptr);
}

// round 12
// speedup vs baseline: 1.4701x; 1.2531x over previous
#include <cuda_runtime.h>
#include <cuda_fp16.h>
#include <cstdint>
#include <string.h>
#include <math.h>

#define B_SZ 2
#define P_SZ 2048
#define M_SZ 1024
#define H_SZ 16
#define D_SZ 64
#define N3_SZ 3072
#define R_SZ (B_SZ * P_SZ)      // 4096
#define K_SZ M_SZ               // 1024
#define BH_SZ (B_SZ * H_SZ)     // 32

// ---------------- scratch (__device__ globals) -----------------------------
__device__ __half g_xhi[(size_t)R_SZ * K_SZ];
__device__ __half g_xlo[(size_t)R_SZ * K_SZ];
__device__ __half g_wa [(size_t)N3_SZ * K_SZ];   // W_attn^T single fp16
__device__ __half g_wp [(size_t)M_SZ * K_SZ];    // W_proj^T single fp16
__device__ __half g_qh[(size_t)BH_SZ * P_SZ * D_SZ];
__device__ __half g_ql[(size_t)BH_SZ * P_SZ * D_SZ];
__device__ __half g_kh[(size_t)BH_SZ * P_SZ * D_SZ];
__device__ __half g_kl[(size_t)BH_SZ * P_SZ * D_SZ];
__device__ __half g_vh[(size_t)BH_SZ * P_SZ * D_SZ];
__device__ __half g_vl[(size_t)BH_SZ * P_SZ * D_SZ];
__device__ __half g_zh[(size_t)R_SZ * K_SZ];
__device__ __half g_zl[(size_t)R_SZ * K_SZ];

// ---------------- PTX helpers (base ISA) -----------------------------------
__device__ __forceinline__ uint32_t smem_u32(const void* p) {
    uint32_t a;
    asm("{ .reg .u64 t; cvta.to.shared.u64 t, %1; cvt.u32.u64 %0, t; }" : "=r"(a) : "l"(p));
    return a;
}
__device__ __forceinline__ void ldsm4(uint32_t* r, uint32_t addr) {
    asm volatile("ldmatrix.sync.aligned.m8n8.x4.shared.b16 {%0,%1,%2,%3}, [%4];"
                 : "=r"(r[0]), "=r"(r[1]), "=r"(r[2]), "=r"(r[3]) : "r"(addr));
}
__device__ __forceinline__ void ldsm4t(uint32_t* r, uint32_t addr) {
    asm volatile("ldmatrix.sync.aligned.m8n8.x4.trans.shared.b16 {%0,%1,%2,%3}, [%4];"
                 : "=r"(r[0]), "=r"(r[1]), "=r"(r[2]), "=r"(r[3]) : "r"(addr));
}
__device__ __forceinline__ void mma16816(float* c, const uint32_t* a, const uint32_t* b) {
    asm volatile(
        "mma.sync.aligned.m16n8k16.row.col.f32.f16.f16.f32 "
        "{%0,%1,%2,%3}, {%4,%5,%6,%7}, {%8,%9}, {%0,%1,%2,%3};"
        : "+f"(c[0]), "+f"(c[1]), "+f"(c[2]), "+f"(c[3])
        : "r"(a[0]), "r"(a[1]), "r"(a[2]), "r"(a[3]), "r"(b[0]), "r"(b[1]));
}
__device__ __forceinline__ void cpasync16(uint32_t saddr, const void* gaddr) {
    asm volatile("cp.async.cg.shared.global [%0], [%1], 16;" :: "r"(saddr), "l"(gaddr) : "memory");
}
__device__ __forceinline__ void sts32(uint32_t addr, uint32_t v) {
    asm volatile("st.shared.b32 [%0], %1;" :: "r"(addr), "r"(v) : "memory");
}
__device__ __forceinline__ void sts64(uint32_t addr, float a, float b) {
    asm volatile("st.shared.v2.f32 [%0], {%1,%2};" :: "r"(addr), "f"(a), "f"(b) : "memory");
}
__device__ __forceinline__ uint4 lds128(uint32_t addr) {
    uint4 v;
    asm volatile("ld.shared.v4.b32 {%0,%1,%2,%3}, [%4];"
                 : "=r"(v.x), "=r"(v.y), "=r"(v.z), "=r"(v.w) : "r"(addr));
    return v;
}
// fp32 pair -> fp16 hi pair + fp16 residual pair
__device__ __forceinline__ void split2h(float a, float b, uint32_t& hu, uint32_t& lu) {
    __half ha = __float2half_rn(a), hb = __float2half_rn(b);
    float ra = a - __half2float(ha), rb = b - __half2float(hb);
    __half2 H = __halves2half2(ha, hb);
    __half2 L = __floats2half2_rn(ra, rb);
    memcpy(&hu, &H, 4); memcpy(&lu, &L, 4);
}
__device__ __forceinline__ uint32_t pack2h(float a, float b) {
    __half2 H = __floats2half2_rn(a, b);
    uint32_t u; memcpy(&u, &H, 4); return u;
}

// ---------------- fp32 -> fp16 hi/lo split ---------------------------------
struct alignas(8) h16x4 { __half2 a, b; };

__global__ __launch_bounds__(256) void split_kernel(
    const float* __restrict__ in, __half* __restrict__ hi,
    __half* __restrict__ lo, int n4)
{
    int i = blockIdx.x * 256 + threadIdx.x;
    if (i >= n4) return;
    float4 v = ((const float4*)in)[i];
    __half h0 = __float2half_rn(v.x), h1 = __float2half_rn(v.y);
    __half h2 = __float2half_rn(v.z), h3 = __float2half_rn(v.w);
    h16x4 H, L;
    H.a = __halves2half2(h0, h1);
    H.b = __halves2half2(h2, h3);
    L.a = __floats2half2_rn(v.x - __half2float(h0), v.y - __half2float(h1));
    L.b = __floats2half2_rn(v.z - __half2float(h2), v.w - __half2float(h3));
    ((h16x4*)hi)[i] = H;
    ((h16x4*)lo)[i] = L;
}

// W [K,N] fp32 -> Wt [N,K] fp16 single (transpose + round)
__global__ __launch_bounds__(256) void tsingle_kernel(
    const float* __restrict__ W, __half* __restrict__ out, int K, int N)
{
    __shared__ float s[32][33];
    const int n0 = blockIdx.x * 32, k0 = blockIdx.y * 32;
    const int tx = threadIdx.x & 31, ty = threadIdx.x >> 5;
    #pragma unroll
    for (int i = 0; i < 4; i++)
        s[ty + 8 * i][tx] = W[(size_t)(k0 + ty + 8 * i) * N + n0 + tx];
    __syncthreads();
    #pragma unroll
    for (int i = 0; i < 4; i++) {
        int r = ty + 8 * i;
        out[(size_t)(n0 + r) * K + k0 + tx] = __float2half_rn(s[tx][r]);
    }
}

// ---------------- fp16 2-term mma GEMM: C = (Ah+Al)@B^T --------------------
#define GK_CH   (K_SZ / 32)          // 32 chunks
#define GT_TILE 10240                // 128 rows * 80 B
#define GT_STG  (3 * GT_TILE)        // Ah, Al, B
#define GT_SMEM 69632                // max(2*GT_STG=61440, epilogue 69632)

// Q pre-scale: 1/sqrt(64) * log2(e)
#define QSCALE (0.125f * 1.44269504088896f)

template<int MODE>
__global__ __launch_bounds__(128) void gemm_mma_kernel(
    const __half* __restrict__ Ah, const __half* __restrict__ Al,
    const __half* __restrict__ B,
    const float* __restrict__ bias, float* __restrict__ C, int N,
    __half* __restrict__ qh, __half* __restrict__ ql,
    __half* __restrict__ kh, __half* __restrict__ kl,
    __half* __restrict__ vh, __half* __restrict__ vl)
{
    extern __shared__ char smraw[];
    const uint32_t sbase = smem_u32(smraw);

    const int tid = threadIdx.x;
    const int wid = tid >> 5, lane = tid & 31;
    const int wm = wid & 1, wn = wid >> 1;
    const int g = lane >> 2, t = lane & 3;
    const int row0 = blockIdx.y << 7;
    const int col0 = blockIdx.x << 7;

    const __half* srcs[3] = {Ah, Al, B};

    auto load_part = [&](int c, int s, int arr) {
        const int k0 = c << 5;
        const __half* src = srcs[arr];
        const int rbase = (arr < 2) ? row0 : col0;
        const uint32_t tb = sbase + (uint32_t)s * GT_STG + (uint32_t)arr * GT_TILE;
        #pragma unroll
        for (int it = 0; it < 4; it++) {
            int id = it * 128 + tid, r = id >> 2, q = id & 3;
            cpasync16(tb + (uint32_t)(r * 80 + q * 16),
                      src + (size_t)(rbase + r) * K_SZ + k0 + q * 8);
        }
    };

    float acc[4][8][4] = {};
    const int a_row = lane & 15;
    const int a_cb  = (lane >> 4) << 4;
    const int b2_row = (lane & 7) + ((lane >> 4) << 3);
    const int b2_cb  = ((lane >> 3) & 1) << 4;

    #pragma unroll
    for (int arr = 0; arr < 3; arr++) load_part(0, 0, arr);
    asm volatile("cp.async.commit_group;" ::: "memory");

    for (int c = 0; c < GK_CH; c++) {
        const int s = c & 1, ns = s ^ 1;
        asm volatile("cp.async.wait_group 0;" ::: "memory");
        __syncthreads();

        const uint32_t stg = sbase + (uint32_t)s * GT_STG;
        const uint32_t tAh = stg, tAl = stg + GT_TILE, tB = stg + 2 * GT_TILE;
        const bool more = (c + 1 < GK_CH);

        #pragma unroll
        for (int ks = 0; ks < 2; ks++) {
            const int kb = ks << 5;
            uint32_t ah[4][4], al[4][4], bf[4][4];
            #pragma unroll
            for (int mt = 0; mt < 4; mt++)
                ldsm4(ah[mt], tAh + (uint32_t)((wm * 64 + mt * 16 + a_row) * 80 + kb + a_cb));
            #pragma unroll
            for (int np = 0; np < 4; np++)
                ldsm4(bf[np], tB + (uint32_t)((wn * 64 + np * 16 + b2_row) * 80 + kb + b2_cb));
            // pass 1 (ah*b) with al loads interleaved
            #pragma unroll
            for (int np = 0; np < 4; np++) {
                ldsm4(al[np], tAl + (uint32_t)((wm * 64 + np * 16 + a_row) * 80 + kb + a_cb));
                #pragma unroll
                for (int mt = 0; mt < 4; mt++) {
                    mma16816(acc[mt][2 * np],     ah[mt], &bf[np][0]);
                    mma16816(acc[mt][2 * np + 1], ah[mt], &bf[np][2]);
                }
            }
            if (more && ks == 0) load_part(c + 1, ns, 0);
            if (more && ks == 1) load_part(c + 1, ns, 2);
            // pass 2 (al*b)
            #pragma unroll
            for (int np = 0; np < 4; np++)
                #pragma unroll
                for (int mt = 0; mt < 4; mt++) {
                    mma16816(acc[mt][2 * np],     al[mt], &bf[np][0]);
                    mma16816(acc[mt][2 * np + 1], al[mt], &bf[np][2]);
                }
            if (more && ks == 0) load_part(c + 1, ns, 1);
        }
        asm volatile("cp.async.commit_group;" ::: "memory");
    }
    __syncthreads();

    if (MODE == 1) {
        const uint32_t hi0 = sbase, lo0 = sbase + 128 * 272;
        #pragma unroll
        for (int mt = 0; mt < 4; mt++) {
            const int rl = wm * 64 + mt * 16 + g;
            #pragma unroll
            for (int nt = 0; nt < 8; nt++) {
                const int cl = wn * 64 + nt * 8 + 2 * t;
                const int col = col0 + cl;
                const float b0 = bias[col], b1 = bias[col + 1];
                float v0 = acc[mt][nt][0] + b0, v1 = acc[mt][nt][1] + b1;
                float v2 = acc[mt][nt][2] + b0, v3 = acc[mt][nt][3] + b1;
                if (col < M_SZ) { v0 *= QSCALE; v1 *= QSCALE; v2 *= QSCALE; v3 *= QSCALE; }
                uint32_t hu, lu;
                split2h(v0, v1, hu, lu);
                sts32(hi0 + (uint32_t)(rl * 272 + cl * 2), hu);
                sts32(lo0 + (uint32_t)(rl * 272 + cl * 2), lu);
                split2h(v2, v3, hu, lu);
                sts32(hi0 + (uint32_t)((rl + 8) * 272 + cl * 2), hu);
                sts32(lo0 + (uint32_t)((rl + 8) * 272 + cl * 2), lu);
            }
        }
        __syncthreads();
        #pragma unroll
        for (int it = 0; it < 16; it++) {
            const int id = it * 128 + tid, r = id >> 4, s = id & 15;
            const int col = col0 + s * 8;
            const int slice = col >> 10, hh = (col >> 6) & 15, dd = col & 63;
            __half* oh = (slice == 0) ? qh : (slice == 1) ? kh : vh;
            __half* ol = (slice == 0) ? ql : (slice == 1) ? kl : vl;
            const int row = row0 + r;
            const int ba = row >> 11, pa = row & 2047;
            const size_t oa = ((size_t)(ba * H_SZ + hh) * P_SZ + pa) * 64 + dd;
            uint4 vh4 = lds128(hi0 + (uint32_t)(r * 272 + s * 16));
            uint4 vl4 = lds128(lo0 + (uint32_t)(r * 272 + s * 16));
            *(uint4*)(oh + oa) = vh4;
            *(uint4*)(ol + oa) = vl4;
        }
    } else {
        #pragma unroll
        for (int mt = 0; mt < 4; mt++) {
            const int rl = wm * 64 + mt * 16 + g;
            #pragma unroll
            for (int nt = 0; nt < 8; nt++) {
                const int cl = wn * 64 + nt * 8 + 2 * t;
                const int col = col0 + cl;
                const float b0 = bias[col], b1 = bias[col + 1];
                sts64(sbase + (uint32_t)(rl * 528 + cl * 4),
                      acc[mt][nt][0] + b0, acc[mt][nt][1] + b1);
                sts64(sbase + (uint32_t)((rl + 8) * 528 + cl * 4),
                      acc[mt][nt][2] + b0, acc[mt][nt][3] + b1);
            }
        }
        __syncthreads();
        #pragma unroll
        for (int it = 0; it < 32; it++) {
            const int id = it * 128 + tid, r = id >> 5, s = id & 31;
            uint4 v = lds128(sbase + (uint32_t)(r * 528 + s * 16));
            *(uint4*)(C + (size_t)(row0 + r) * N + col0 + s * 4) = v;
        }
    }
}

// ---------------- fp16 flash attention: S 3-term, PV 2-term ----------------
#define AT_ROWB 144
#define AT_QTILE (128 * AT_ROWB)        // 18432
#define AT_KTILE (64 * AT_ROWB)         // 9216
#define AT_STG   (4 * AT_KTILE)         // 36864 (Kh,Kl,Vh,Vl)
#define AT_SMEM  (2 * AT_STG)           // 73728

__global__ __launch_bounds__(128) void attn_mma_kernel(
    const __half* __restrict__ qh, const __half* __restrict__ ql,
    const __half* __restrict__ kh, const __half* __restrict__ kl,
    const __half* __restrict__ vh, const __half* __restrict__ vl,
    __half* __restrict__ zh, __half* __restrict__ zl)
{
    extern __shared__ char smraw[];
    const uint32_t sb = smem_u32(smraw);
    const int tid = threadIdx.x, w = tid >> 5, lane = tid & 31;
    const int g = lane >> 2, t = lane & 3;
    const int qt = blockIdx.x, bh = blockIdx.y;
    const int q0 = qt << 7;
    const size_t hb = (size_t)bh * P_SZ * 64;

    const __half* kvsrc[4] = {kh + hb, kl + hb, vh + hb, vl + hb};
    auto stage_base = [&](int s) -> uint32_t { return (s == 0) ? sb + AT_STG : sb; };
    auto load_kv_part = [&](int kvt, int s, int a) {
        const uint32_t stg = stage_base(s);
        const size_t rb = (size_t)(kvt << 6) * 64;
        #pragma unroll
        for (int it = 0; it < 4; it++) {
            int id = it * 128 + tid, r = id >> 3, c = id & 7;
            cpasync16(stg + (uint32_t)(a * AT_KTILE + r * AT_ROWB + c * 16),
                      kvsrc[a] + rb + r * 64 + c * 8);
        }
    };

    {   // Q hi/lo into region 0 (becomes KV stage 1 afterwards)
        const __half* Qh = qh + hb + (size_t)q0 * 64;
        const __half* Ql = ql + hb + (size_t)q0 * 64;
        #pragma unroll
        for (int it = 0; it < 8; it++) {
            int id = it * 128 + tid, r = id >> 3, c = id & 7;
            cpasync16(sb + (uint32_t)(r * AT_ROWB + c * 16), Qh + r * 64 + c * 8);
            cpasync16(sb + AT_QTILE + (uint32_t)(r * AT_ROWB + c * 16), Ql + r * 64 + c * 8);
        }
    }
    #pragma unroll
    for (int a = 0; a < 4; a++) load_kv_part(0, 0, a);
    asm volatile("cp.async.commit_group;" ::: "memory");
    asm volatile("cp.async.wait_group 0;" ::: "memory");
    __syncthreads();

    uint32_t qhf[2][4][4], qlf[2][4][4];
    const int arow = (lane & 7) + ((lane >> 3) & 1) * 8;
    const int achk = lane >> 4;
    #pragma unroll
    for (int mt = 0; mt < 2; mt++)
        #pragma unroll
        for (int ks = 0; ks < 4; ks++) {
            uint32_t ad = sb + (uint32_t)((32 * w + 16 * mt + arow) * AT_ROWB +
                                          (2 * ks + achk) * 16);
            ldsm4(qhf[mt][ks], ad);
            ldsm4(qlf[mt][ks], ad + AT_QTILE);
        }
    __syncthreads();   // Q reads done before stage-1 writes

    float oacc[2][8][4] = {};
    float mrow[2][2], lrow[2][2];
    #pragma unroll
    for (int mt = 0; mt < 2; mt++) {
        mrow[mt][0] = -1e30f; mrow[mt][1] = -1e30f;
        lrow[mt][0] = 0.f;    lrow[mt][1] = 0.f;
    }
    const int wrow_min = q0 + 32 * w;
    const int wrow_max = wrow_min + 31;
    const int ntiles = 2 * qt + 2;

    for (int kvt = 0; kvt < ntiles; kvt++) {
        const int s = kvt & 1, ns = s ^ 1;
        if (kvt > 0) {
            asm volatile("cp.async.wait_group 0;" ::: "memory");
            __syncthreads();
        }
        const bool more = (kvt + 1 < ntiles);
        const int c_base = kvt << 6;
        if (c_base <= wrow_max) {
            const uint32_t kb = stage_base(s);

            // ---- S = Q K^T (fp16 3-term), K double-buffered across j ----
            float sacc[2][8][4] = {};
            uint32_t khf[2][2][4], klf[2][2][4];
            #pragma unroll
            for (int cp = 0; cp < 2; cp++) {
                uint32_t ad = kb + (uint32_t)((lane & 7) * AT_ROWB + (4 * cp + (lane >> 3)) * 16);
                ldsm4(khf[0][cp], ad);
                ldsm4(klf[0][cp], ad + AT_KTILE);
            }
            #pragma unroll
            for (int j = 0; j < 8; j++) {
                const int cur = j & 1, nxt = cur ^ 1;
                if (j < 7) {
                    #pragma unroll
                    for (int cp = 0; cp < 2; cp++) {
                        uint32_t ad = kb + (uint32_t)((8 * (j + 1) + (lane & 7)) * AT_ROWB +
                                                      (4 * cp + (lane >> 3)) * 16);
                        ldsm4(khf[nxt][cp], ad);
                        ldsm4(klf[nxt][cp], ad + AT_KTILE);
                    }
                }
                #pragma unroll
                for (int cp = 0; cp < 2; cp++)
                    #pragma unroll
                    for (int mt = 0; mt < 2; mt++) {
                        mma16816(sacc[mt][j], qhf[mt][2 * cp],     &khf[cur][cp][0]);
                        mma16816(sacc[mt][j], qhf[mt][2 * cp + 1], &khf[cur][cp][2]);
                    }
                #pragma unroll
                for (int cp = 0; cp < 2; cp++)
                    #pragma unroll
                    for (int mt = 0; mt < 2; mt++) {
                        mma16816(sacc[mt][j], qhf[mt][2 * cp],     &klf[cur][cp][0]);
                        mma16816(sacc[mt][j], qhf[mt][2 * cp + 1], &klf[cur][cp][2]);
                    }
                #pragma unroll
                for (int cp = 0; cp < 2; cp++)
                    #pragma unroll
                    for (int mt = 0; mt < 2; mt++) {
                        mma16816(sacc[mt][j], qlf[mt][2 * cp],     &khf[cur][cp][0]);
                        mma16816(sacc[mt][j], qlf[mt][2 * cp + 1], &khf[cur][cp][2]);
                    }
            }
            if (more) { load_kv_part(kvt + 1, ns, 0); load_kv_part(kvt + 1, ns, 1); }

            if (c_base + 63 > wrow_min) {
                #pragma unroll
                for (int mt = 0; mt < 2; mt++) {
                    const int lr0 = wrow_min + 16 * mt + g;
                    #pragma unroll
                    for (int j = 0; j < 8; j++) {
                        const int c0 = c_base + 8 * j + 2 * t;
                        if (c0     > lr0)     sacc[mt][j][0] = -1e30f;
                        if (c0 + 1 > lr0)     sacc[mt][j][1] = -1e30f;
                        if (c0     > lr0 + 8) sacc[mt][j][2] = -1e30f;
                        if (c0 + 1 > lr0 + 8) sacc[mt][j][3] = -1e30f;
                    }
                }
            }

            #pragma unroll
            for (int mt = 0; mt < 2; mt++) {
                float mx0 = -1e30f, mx1 = -1e30f;
                #pragma unroll
                for (int j = 0; j < 8; j++) {
                    mx0 = fmaxf(mx0, fmaxf(sacc[mt][j][0], sacc[mt][j][1]));
                    mx1 = fmaxf(mx1, fmaxf(sacc[mt][j][2], sacc[mt][j][3]));
                }
                mx0 = fmaxf(mx0, __shfl_xor_sync(0xffffffffu, mx0, 1));
                mx0 = fmaxf(mx0, __shfl_xor_sync(0xffffffffu, mx0, 2));
                mx1 = fmaxf(mx1, __shfl_xor_sync(0xffffffffu, mx1, 1));
                mx1 = fmaxf(mx1, __shfl_xor_sync(0xffffffffu, mx1, 2));
                const float mn0 = fmaxf(mrow[mt][0], mx0), mn1 = fmaxf(mrow[mt][1], mx1);
                const float al0 = exp2f(mrow[mt][0] - mn0), al1 = exp2f(mrow[mt][1] - mn1);
                float sum0 = 0.f, sum1 = 0.f;
                #pragma unroll
                for (int j = 0; j < 8; j++) {
                    sacc[mt][j][0] = exp2f(sacc[mt][j][0] - mn0);
                    sacc[mt][j][1] = exp2f(sacc[mt][j][1] - mn0);
                    sacc[mt][j][2] = exp2f(sacc[mt][j][2] - mn1);
                    sacc[mt][j][3] = exp2f(sacc[mt][j][3] - mn1);
                    sum0 += sacc[mt][j][0] + sacc[mt][j][1];
                    sum1 += sacc[mt][j][2] + sacc[mt][j][3];
                }
                sum0 += __shfl_xor_sync(0xffffffffu, sum0, 1);
                sum0 += __shfl_xor_sync(0xffffffffu, sum0, 2);
                sum1 += __shfl_xor_sync(0xffffffffu, sum1, 1);
                sum1 += __shfl_xor_sync(0xffffffffu, sum1, 2);
                lrow[mt][0] = lrow[mt][0] * al0 + sum0; mrow[mt][0] = mn0;
                lrow[mt][1] = lrow[mt][1] * al1 + sum1; mrow[mt][1] = mn1;
                #pragma unroll
                for (int j = 0; j < 8; j++) {
                    oacc[mt][j][0] *= al0; oacc[mt][j][1] *= al0;
                    oacc[mt][j][2] *= al1; oacc[mt][j][3] *= al1;
                }
            }

            // ---- O += P V (fp16 2-term: P single, V hi/lo) ----
            #pragma unroll
            for (int s2 = 0; s2 < 4; s2++) {
                uint32_t pf[2][4];
                #pragma unroll
                for (int mt = 0; mt < 2; mt++) {
                    pf[mt][0] = pack2h(sacc[mt][2 * s2][0],     sacc[mt][2 * s2][1]);
                    pf[mt][1] = pack2h(sacc[mt][2 * s2][2],     sacc[mt][2 * s2][3]);
                    pf[mt][2] = pack2h(sacc[mt][2 * s2 + 1][0], sacc[mt][2 * s2 + 1][1]);
                    pf[mt][3] = pack2h(sacc[mt][2 * s2 + 1][2], sacc[mt][2 * s2 + 1][3]);
                }
                uint32_t vhf[4][4], vlf[4][4];
                #pragma unroll
                for (int jp = 0; jp < 4; jp++) {
                    uint32_t ad = kb + 2 * AT_KTILE +
                        (uint32_t)((16 * s2 + (lane & 15)) * AT_ROWB + (2 * jp + (lane >> 4)) * 16);
                    ldsm4t(vhf[jp], ad);
                }
                // pass 1 (p*vh) with vl loads interleaved
                #pragma unroll
                for (int jp = 0; jp < 4; jp++) {
                    uint32_t ad = kb + 2 * AT_KTILE +
                        (uint32_t)((16 * s2 + (lane & 15)) * AT_ROWB + (2 * jp + (lane >> 4)) * 16);
                    ldsm4t(vlf[jp], ad + AT_KTILE);
                    #pragma unroll
                    for (int mt = 0; mt < 2; mt++) {
                        mma16816(oacc[mt][2 * jp],     pf[mt], &vhf[jp][0]);
                        mma16816(oacc[mt][2 * jp + 1], pf[mt], &vhf[jp][2]);
                    }
                }
                // pass 2 (p*vl)
                #pragma unroll
                for (int jp = 0; jp < 4; jp++)
                    #pragma unroll
                    for (int mt = 0; mt < 2; mt++) {
                        mma16816(oacc[mt][2 * jp],     pf[mt], &vlf[jp][0]);
                        mma16816(oacc[mt][2 * jp + 1], pf[mt], &vlf[jp][2]);
                    }
                if (more && s2 == 0) load_kv_part(kvt + 1, ns, 2);
                if (more && s2 == 2) load_kv_part(kvt + 1, ns, 3);
            }
        } else if (more) {
            #pragma unroll
            for (int a = 0; a < 4; a++) load_kv_part(kvt + 1, ns, a);
        }
        asm volatile("cp.async.commit_group;" ::: "memory");
    }
    __syncthreads();

    // epilogue: stage z hi/lo in region 0, coalesced 16B stores
    const uint32_t oh0 = sb, ol0 = sb + AT_QTILE;
    #pragma unroll
    for (int mt = 0; mt < 2; mt++) {
        const float i0 = 1.f / lrow[mt][0], i1 = 1.f / lrow[mt][1];
        const int rl = 32 * w + 16 * mt + g;
        #pragma unroll
        for (int j = 0; j < 8; j++) {
            const int cl = 8 * j + 2 * t;
            uint32_t hu, lu;
            split2h(oacc[mt][j][0] * i0, oacc[mt][j][1] * i0, hu, lu);
            sts32(oh0 + (uint32_t)(rl * AT_ROWB + cl * 2), hu);
            sts32(ol0 + (uint32_t)(rl * AT_ROWB + cl * 2), lu);
            split2h(oacc[mt][j][2] * i1, oacc[mt][j][3] * i1, hu, lu);
            sts32(oh0 + (uint32_t)((rl + 8) * AT_ROWB + cl * 2), hu);
            sts32(ol0 + (uint32_t)((rl + 8) * AT_ROWB + cl * 2), lu);
        }
    }
    __syncthreads();
    const int b = bh >> 4, h = bh & 15;
    #pragma unroll
    for (int it = 0; it < 8; it++) {
        const int id = it * 128 + tid, r = id >> 3, s = id & 7;
        const size_t dst = ((size_t)b * P_SZ + q0 + r) * K_SZ + h * 64 + s * 8;
        uint4 vh4 = lds128(oh0 + (uint32_t)(r * AT_ROWB + s * 16));
        uint4 vl4 = lds128(ol0 + (uint32_t)(r * AT_ROWB + s * 16));
        *(uint4*)(zh + dst) = vh4;
        *(uint4*)(zl + dst) = vl4;
    }
}

// ---------------------------------------------------------------------------
extern "C" void kernel_launch(void* const* d_in, const int* in_sizes, int n_in,
                              void* d_out, int out_size)
{
    (void)in_sizes; (void)n_in; (void)out_size;
    const float* x      = (const float*)d_in[0];
    const float* W_attn = (const float*)d_in[1];
    const float* b_attn = (const float*)d_in[2];
    const float* W_proj = (const float*)d_in[3];
    const float* b_proj = (const float*)d_in[4];
    float* out = (float*)d_out;

    __half *xhi, *xlo, *wa, *wp;
    __half *qh, *ql, *kh, *kl, *vh, *vl, *zh, *zl;
    cudaGetSymbolAddress((void**)&xhi, g_xhi);
    cudaGetSymbolAddress((void**)&xlo, g_xlo);
    cudaGetSymbolAddress((void**)&wa,  g_wa);
    cudaGetSymbolAddress((void**)&wp,  g_wp);
    cudaGetSymbolAddress((void**)&qh,  g_qh);
    cudaGetSymbolAddress((void**)&ql,  g_ql);
    cudaGetSymbolAddress((void**)&kh,  g_kh);
    cudaGetSymbolAddress((void**)&kl,  g_kl);
    cudaGetSymbolAddress((void**)&vh,  g_vh);
    cudaGetSymbolAddress((void**)&vl,  g_vl);
    cudaGetSymbolAddress((void**)&zh,  g_zh);
    cudaGetSymbolAddress((void**)&zl,  g_zl);

    cudaFuncSetAttribute(gemm_mma_kernel<0>,
                         cudaFuncAttributeMaxDynamicSharedMemorySize, GT_SMEM);
    cudaFuncSetAttribute(gemm_mma_kernel<1>,
                         cudaFuncAttributeMaxDynamicSharedMemorySize, GT_SMEM);
    cudaFuncSetAttribute(attn_mma_kernel,
                         cudaFuncAttributeMaxDynamicSharedMemorySize, AT_SMEM);

    split_kernel<<<(R_SZ * K_SZ / 4 + 255) / 256, 256>>>(x, xhi, xlo, R_SZ * K_SZ / 4);
    tsingle_kernel<<<dim3(N3_SZ / 32, K_SZ / 32), 256>>>(W_attn, wa, K_SZ, N3_SZ);
    tsingle_kernel<<<dim3(M_SZ / 32, K_SZ / 32), 256>>>(W_proj, wp, K_SZ, M_SZ);

    gemm_mma_kernel<1><<<dim3(N3_SZ / 128, R_SZ / 128), 128, GT_SMEM>>>(
        xhi, xlo, wa, b_attn, nullptr, N3_SZ, qh, ql, kh, kl, vh, vl);

    attn_mma_kernel<<<dim3(P_SZ / 128, BH_SZ), 128, AT_SMEM>>>(
        qh, ql, kh, kl, vh, vl, zh, zl);

    gemm_mma_kernel<0><<<dim3(M_SZ / 128, R_SZ / 128), 128, GT_SMEM>>>(
        zh, zl, wp, b_proj, out, M_SZ,
        nullptr, nullptr, nullptr, nullptr, nullptr, nullptr);
}

// round 13
// speedup vs baseline: 1.7359x; 1.1808x over previous
#include <cuda_runtime.h>
#include <cuda_fp16.h>
#include <cstdint>
#include <string.h>
#include <math.h>

#define B_SZ 2
#define P_SZ 2048
#define M_SZ 1024
#define H_SZ 16
#define D_SZ 64
#define N3_SZ 3072
#define R_SZ (B_SZ * P_SZ)      // 4096
#define K_SZ M_SZ               // 1024
#define BH_SZ (B_SZ * H_SZ)     // 32

// ---------------- scratch (__device__ globals) -----------------------------
__device__ __half g_xhi[(size_t)R_SZ * K_SZ];
__device__ __half g_xlo[(size_t)R_SZ * K_SZ];
__device__ __half g_wa [(size_t)N3_SZ * K_SZ];   // W_attn^T fp16
__device__ __half g_wp [(size_t)M_SZ * K_SZ];    // W_proj^T fp16
__device__ __half g_qh[(size_t)BH_SZ * P_SZ * D_SZ];
__device__ __half g_ql[(size_t)BH_SZ * P_SZ * D_SZ];
__device__ __half g_k [(size_t)BH_SZ * P_SZ * D_SZ];   // K single fp16
__device__ __half g_v [(size_t)BH_SZ * P_SZ * D_SZ];   // V single fp16
__device__ __half g_zh[(size_t)R_SZ * K_SZ];
__device__ __half g_zl[(size_t)R_SZ * K_SZ];

// ---------------- PTX helpers (base ISA) -----------------------------------
__device__ __forceinline__ uint32_t smem_u32(const void* p) {
    uint32_t a;
    asm("{ .reg .u64 t; cvta.to.shared.u64 t, %1; cvt.u32.u64 %0, t; }" : "=r"(a) : "l"(p));
    return a;
}
__device__ __forceinline__ void ldsm4(uint32_t* r, uint32_t addr) {
    asm volatile("ldmatrix.sync.aligned.m8n8.x4.shared.b16 {%0,%1,%2,%3}, [%4];"
                 : "=r"(r[0]), "=r"(r[1]), "=r"(r[2]), "=r"(r[3]) : "r"(addr));
}
__device__ __forceinline__ void ldsm4t(uint32_t* r, uint32_t addr) {
    asm volatile("ldmatrix.sync.aligned.m8n8.x4.trans.shared.b16 {%0,%1,%2,%3}, [%4];"
                 : "=r"(r[0]), "=r"(r[1]), "=r"(r[2]), "=r"(r[3]) : "r"(addr));
}
__device__ __forceinline__ void mma16816(float* c, const uint32_t* a, const uint32_t* b) {
    asm volatile(
        "mma.sync.aligned.m16n8k16.row.col.f32.f16.f16.f32 "
        "{%0,%1,%2,%3}, {%4,%5,%6,%7}, {%8,%9}, {%0,%1,%2,%3};"
        : "+f"(c[0]), "+f"(c[1]), "+f"(c[2]), "+f"(c[3])
        : "r"(a[0]), "r"(a[1]), "r"(a[2]), "r"(a[3]), "r"(b[0]), "r"(b[1]));
}
__device__ __forceinline__ void cpasync16(uint32_t saddr, const void* gaddr) {
    asm volatile("cp.async.cg.shared.global [%0], [%1], 16;" :: "r"(saddr), "l"(gaddr) : "memory");
}
__device__ __forceinline__ void sts32(uint32_t addr, uint32_t v) {
    asm volatile("st.shared.b32 [%0], %1;" :: "r"(addr), "r"(v) : "memory");
}
__device__ __forceinline__ void sts64(uint32_t addr, float a, float b) {
    asm volatile("st.shared.v2.f32 [%0], {%1,%2};" :: "r"(addr), "f"(a), "f"(b) : "memory");
}
__device__ __forceinline__ uint4 lds128(uint32_t addr) {
    uint4 v;
    asm volatile("ld.shared.v4.b32 {%0,%1,%2,%3}, [%4];"
                 : "=r"(v.x), "=r"(v.y), "=r"(v.z), "=r"(v.w) : "r"(addr));
    return v;
}
__device__ __forceinline__ void split2h(float a, float b, uint32_t& hu, uint32_t& lu) {
    __half ha = __float2half_rn(a), hb = __float2half_rn(b);
    float ra = a - __half2float(ha), rb = b - __half2float(hb);
    __half2 H = __halves2half2(ha, hb);
    __half2 L = __floats2half2_rn(ra, rb);
    memcpy(&hu, &H, 4); memcpy(&lu, &L, 4);
}
__device__ __forceinline__ uint32_t pack2h(float a, float b) {
    __half2 H = __floats2half2_rn(a, b);
    uint32_t u; memcpy(&u, &H, 4); return u;
}

// ---------------- fp32 -> fp16 hi/lo split ---------------------------------
struct alignas(8) h16x4 { __half2 a, b; };

__global__ __launch_bounds__(256) void split_kernel(
    const float* __restrict__ in, __half* __restrict__ hi,
    __half* __restrict__ lo, int n4)
{
    int i = blockIdx.x * 256 + threadIdx.x;
    if (i >= n4) return;
    float4 v = ((const float4*)in)[i];
    __half h0 = __float2half_rn(v.x), h1 = __float2half_rn(v.y);
    __half h2 = __float2half_rn(v.z), h3 = __float2half_rn(v.w);
    h16x4 H, L;
    H.a = __halves2half2(h0, h1);
    H.b = __halves2half2(h2, h3);
    L.a = __floats2half2_rn(v.x - __half2float(h0), v.y - __half2float(h1));
    L.b = __floats2half2_rn(v.z - __half2float(h2), v.w - __half2float(h3));
    ((h16x4*)hi)[i] = H;
    ((h16x4*)lo)[i] = L;
}

__global__ __launch_bounds__(256) void tsingle_kernel(
    const float* __restrict__ W, __half* __restrict__ out, int K, int N)
{
    __shared__ float s[32][33];
    const int n0 = blockIdx.x * 32, k0 = blockIdx.y * 32;
    const int tx = threadIdx.x & 31, ty = threadIdx.x >> 5;
    #pragma unroll
    for (int i = 0; i < 4; i++)
        s[ty + 8 * i][tx] = W[(size_t)(k0 + ty + 8 * i) * N + n0 + tx];
    __syncthreads();
    #pragma unroll
    for (int i = 0; i < 4; i++) {
        int r = ty + 8 * i;
        out[(size_t)(n0 + r) * K + k0 + tx] = __float2half_rn(s[tx][r]);
    }
}

// ---------------- fp16 2-term mma GEMM: C = (Ah+Al)@B^T --------------------
#define GK_CH   (K_SZ / 32)
#define GT_TILE 10240
#define GT_STG  (3 * GT_TILE)
#define GT_SMEM 69632

// Q pre-scale: 1/sqrt(64) * log2(e)
#define QSCALE (0.125f * 1.44269504088896f)

template<int MODE>
__global__ __launch_bounds__(128) void gemm_mma_kernel(
    const __half* __restrict__ Ah, const __half* __restrict__ Al,
    const __half* __restrict__ B,
    const float* __restrict__ bias, float* __restrict__ C, int N,
    __half* __restrict__ qh, __half* __restrict__ ql,
    __half* __restrict__ kk, __half* __restrict__ vv)
{
    extern __shared__ char smraw[];
    const uint32_t sbase = smem_u32(smraw);

    const int tid = threadIdx.x;
    const int wid = tid >> 5, lane = tid & 31;
    const int wm = wid & 1, wn = wid >> 1;
    const int g = lane >> 2, t = lane & 3;
    const int row0 = blockIdx.y << 7;
    const int col0 = blockIdx.x << 7;

    const __half* srcs[3] = {Ah, Al, B};

    auto load_part = [&](int c, int s, int arr) {
        const int k0 = c << 5;
        const __half* src = srcs[arr];
        const int rbase = (arr < 2) ? row0 : col0;
        const uint32_t tb = sbase + (uint32_t)s * GT_STG + (uint32_t)arr * GT_TILE;
        #pragma unroll
        for (int it = 0; it < 4; it++) {
            int id = it * 128 + tid, r = id >> 2, q = id & 3;
            cpasync16(tb + (uint32_t)(r * 80 + q * 16),
                      src + (size_t)(rbase + r) * K_SZ + k0 + q * 8);
        }
    };

    float acc[4][8][4] = {};
    const int a_row = lane & 15;
    const int a_cb  = (lane >> 4) << 4;
    const int b2_row = (lane & 7) + ((lane >> 4) << 3);
    const int b2_cb  = ((lane >> 3) & 1) << 4;

    #pragma unroll
    for (int arr = 0; arr < 3; arr++) load_part(0, 0, arr);
    asm volatile("cp.async.commit_group;" ::: "memory");

    for (int c = 0; c < GK_CH; c++) {
        const int s = c & 1, ns = s ^ 1;
        asm volatile("cp.async.wait_group 0;" ::: "memory");
        __syncthreads();

        const uint32_t stg = sbase + (uint32_t)s * GT_STG;
        const uint32_t tAh = stg, tAl = stg + GT_TILE, tB = stg + 2 * GT_TILE;
        const bool more = (c + 1 < GK_CH);

        #pragma unroll
        for (int ks = 0; ks < 2; ks++) {
            const int kb = ks << 5;
            uint32_t ah[4][4], al[4][4], bf[4][4];
            #pragma unroll
            for (int mt = 0; mt < 4; mt++)
                ldsm4(ah[mt], tAh + (uint32_t)((wm * 64 + mt * 16 + a_row) * 80 + kb + a_cb));
            #pragma unroll
            for (int np = 0; np < 4; np++)
                ldsm4(bf[np], tB + (uint32_t)((wn * 64 + np * 16 + b2_row) * 80 + kb + b2_cb));
            #pragma unroll
            for (int np = 0; np < 4; np++) {
                ldsm4(al[np], tAl + (uint32_t)((wm * 64 + np * 16 + a_row) * 80 + kb + a_cb));
                #pragma unroll
                for (int mt = 0; mt < 4; mt++) {
                    mma16816(acc[mt][2 * np],     ah[mt], &bf[np][0]);
                    mma16816(acc[mt][2 * np + 1], ah[mt], &bf[np][2]);
                }
            }
            if (more && ks == 0) load_part(c + 1, ns, 0);
            if (more && ks == 1) load_part(c + 1, ns, 2);
            #pragma unroll
            for (int np = 0; np < 4; np++)
                #pragma unroll
                for (int mt = 0; mt < 4; mt++) {
                    mma16816(acc[mt][2 * np],     al[mt], &bf[np][0]);
                    mma16816(acc[mt][2 * np + 1], al[mt], &bf[np][2]);
                }
            if (more && ks == 0) load_part(c + 1, ns, 1);
        }
        asm volatile("cp.async.commit_group;" ::: "memory");
    }
    __syncthreads();

    if (MODE == 1) {
        const uint32_t hi0 = sbase, lo0 = sbase + 128 * 272;
        #pragma unroll
        for (int mt = 0; mt < 4; mt++) {
            const int rl = wm * 64 + mt * 16 + g;
            #pragma unroll
            for (int nt = 0; nt < 8; nt++) {
                const int cl = wn * 64 + nt * 8 + 2 * t;
                const int col = col0 + cl;
                const float b0 = bias[col], b1 = bias[col + 1];
                float v0 = acc[mt][nt][0] + b0, v1 = acc[mt][nt][1] + b1;
                float v2 = acc[mt][nt][2] + b0, v3 = acc[mt][nt][3] + b1;
                if (col < M_SZ) { v0 *= QSCALE; v1 *= QSCALE; v2 *= QSCALE; v3 *= QSCALE; }
                uint32_t hu, lu;
                split2h(v0, v1, hu, lu);
                sts32(hi0 + (uint32_t)(rl * 272 + cl * 2), hu);
                sts32(lo0 + (uint32_t)(rl * 272 + cl * 2), lu);
                split2h(v2, v3, hu, lu);
                sts32(hi0 + (uint32_t)((rl + 8) * 272 + cl * 2), hu);
                sts32(lo0 + (uint32_t)((rl + 8) * 272 + cl * 2), lu);
            }
        }
        __syncthreads();
        #pragma unroll
        for (int it = 0; it < 16; it++) {
            const int id = it * 128 + tid, r = id >> 4, s = id & 15;
            const int col = col0 + s * 8;
            const int slice = col >> 10, hh = (col >> 6) & 15, dd = col & 63;
            __half* oh = (slice == 0) ? qh : (slice == 1) ? kk : vv;
            const int row = row0 + r;
            const int ba = row >> 11, pa = row & 2047;
            const size_t oa = ((size_t)(ba * H_SZ + hh) * P_SZ + pa) * 64 + dd;
            uint4 vh4 = lds128(hi0 + (uint32_t)(r * 272 + s * 16));
            *(uint4*)(oh + oa) = vh4;
            if (slice == 0) {   // only Q keeps the residual
                uint4 vl4 = lds128(lo0 + (uint32_t)(r * 272 + s * 16));
                *(uint4*)(ql + oa) = vl4;
            }
        }
    } else {
        #pragma unroll
        for (int mt = 0; mt < 4; mt++) {
            const int rl = wm * 64 + mt * 16 + g;
            #pragma unroll
            for (int nt = 0; nt < 8; nt++) {
                const int cl = wn * 64 + nt * 8 + 2 * t;
                const int col = col0 + cl;
                const float b0 = bias[col], b1 = bias[col + 1];
                sts64(sbase + (uint32_t)(rl * 528 + cl * 4),
                      acc[mt][nt][0] + b0, acc[mt][nt][1] + b1);
                sts64(sbase + (uint32_t)((rl + 8) * 528 + cl * 4),
                      acc[mt][nt][2] + b0, acc[mt][nt][3] + b1);
            }
        }
        __syncthreads();
        #pragma unroll
        for (int it = 0; it < 32; it++) {
            const int id = it * 128 + tid, r = id >> 5, s = id & 31;
            uint4 v = lds128(sbase + (uint32_t)(r * 528 + s * 16));
            *(uint4*)(C + (size_t)(row0 + r) * N + col0 + s * 4) = v;
        }
    }
}

// ---------------- fp16 flash attention: S 2-term, PV 1-term ----------------
// smem: region0 [0, 36864) = Q hi/lo, then KV stage 1 (first 18432) + epilogue
//       region1 [36864, 55296) = KV stage 0   (K tile + V tile, single fp16)
#define AT_ROWB 144
#define AT_QTILE (128 * AT_ROWB)        // 18432
#define AT_KTILE (64 * AT_ROWB)         // 9216
#define AT_STG   (2 * AT_KTILE)         // 18432 (K, V)
#define AT_SMEM  (2 * AT_QTILE + AT_STG) // 55296... region0 36864 + region1 18432

__global__ __launch_bounds__(128) void attn_mma_kernel(
    const __half* __restrict__ qh, const __half* __restrict__ ql,
    const __half* __restrict__ kk, const __half* __restrict__ vv,
    __half* __restrict__ zh, __half* __restrict__ zl)
{
    extern __shared__ char smraw[];
    const uint32_t sb = smem_u32(smraw);
    const int tid = threadIdx.x, w = tid >> 5, lane = tid & 31;
    const int g = lane >> 2, t = lane & 3;
    const int qt = blockIdx.x, bh = blockIdx.y;
    const int q0 = qt << 7;
    const size_t hb = (size_t)bh * P_SZ * 64;

    const __half* kvsrc[2] = {kk + hb, vv + hb};
    // stage 0 -> region1 (sb + 2*AT_QTILE); stage 1 -> region0 (sb)
    auto stage_base = [&](int s) -> uint32_t {
        return (s == 0) ? sb + 2 * AT_QTILE : sb;
    };
    auto load_kv_part = [&](int kvt, int s, int a) {
        const uint32_t stg = stage_base(s);
        const size_t rb = (size_t)(kvt << 6) * 64;
        #pragma unroll
        for (int it = 0; it < 4; it++) {
            int id = it * 128 + tid, r = id >> 3, c = id & 7;
            cpasync16(stg + (uint32_t)(a * AT_KTILE + r * AT_ROWB + c * 16),
                      kvsrc[a] + rb + r * 64 + c * 8);
        }
    };

    {   // Q hi/lo into region 0
        const __half* Qh = qh + hb + (size_t)q0 * 64;
        const __half* Ql = ql + hb + (size_t)q0 * 64;
        #pragma unroll
        for (int it = 0; it < 8; it++) {
            int id = it * 128 + tid, r = id >> 3, c = id & 7;
            cpasync16(sb + (uint32_t)(r * AT_ROWB + c * 16), Qh + r * 64 + c * 8);
            cpasync16(sb + AT_QTILE + (uint32_t)(r * AT_ROWB + c * 16), Ql + r * 64 + c * 8);
        }
    }
    load_kv_part(0, 0, 0);
    load_kv_part(0, 0, 1);
    asm volatile("cp.async.commit_group;" ::: "memory");
    asm volatile("cp.async.wait_group 0;" ::: "memory");
    __syncthreads();

    uint32_t qhf[2][4][4], qlf[2][4][4];
    const int arow = (lane & 7) + ((lane >> 3) & 1) * 8;
    const int achk = lane >> 4;
    #pragma unroll
    for (int mt = 0; mt < 2; mt++)
        #pragma unroll
        for (int ks = 0; ks < 4; ks++) {
            uint32_t ad = sb + (uint32_t)((32 * w + 16 * mt + arow) * AT_ROWB +
                                          (2 * ks + achk) * 16);
            ldsm4(qhf[mt][ks], ad);
            ldsm4(qlf[mt][ks], ad + AT_QTILE);
        }
    __syncthreads();   // Q reads done before stage-1 writes to region 0

    float oacc[2][8][4] = {};
    float mrow[2][2], lrow[2][2];
    #pragma unroll
    for (int mt = 0; mt < 2; mt++) {
        mrow[mt][0] = -1e30f; mrow[mt][1] = -1e30f;
        lrow[mt][0] = 0.f;    lrow[mt][1] = 0.f;
    }
    const int wrow_min = q0 + 32 * w;
    const int wrow_max = wrow_min + 31;
    const int ntiles = 2 * qt + 2;

    for (int kvt = 0; kvt < ntiles; kvt++) {
        const int s = kvt & 1, ns = s ^ 1;
        if (kvt > 0) {
            asm volatile("cp.async.wait_group 0;" ::: "memory");
            __syncthreads();
        }
        const bool more = (kvt + 1 < ntiles);
        const int c_base = kvt << 6;
        if (c_base <= wrow_max) {
            const uint32_t kb = stage_base(s);

            // ---- S = Q K^T (2 passes: qh*k, ql*k), K double-buffered ----
            float sacc[2][8][4] = {};
            uint32_t kf[2][2][4];
            #pragma unroll
            for (int cp = 0; cp < 2; cp++) {
                uint32_t ad = kb + (uint32_t)((lane & 7) * AT_ROWB + (4 * cp + (lane >> 3)) * 16);
                ldsm4(kf[0][cp], ad);
            }
            #pragma unroll
            for (int j = 0; j < 8; j++) {
                const int cur = j & 1, nxt = cur ^ 1;
                if (j < 7) {
                    #pragma unroll
                    for (int cp = 0; cp < 2; cp++) {
                        uint32_t ad = kb + (uint32_t)((8 * (j + 1) + (lane & 7)) * AT_ROWB +
                                                      (4 * cp + (lane >> 3)) * 16);
                        ldsm4(kf[nxt][cp], ad);
                    }
                }
                #pragma unroll
                for (int cp = 0; cp < 2; cp++)
                    #pragma unroll
                    for (int mt = 0; mt < 2; mt++) {
                        mma16816(sacc[mt][j], qhf[mt][2 * cp],     &kf[cur][cp][0]);
                        mma16816(sacc[mt][j], qhf[mt][2 * cp + 1], &kf[cur][cp][2]);
                    }
                #pragma unroll
                for (int cp = 0; cp < 2; cp++)
                    #pragma unroll
                    for (int mt = 0; mt < 2; mt++) {
                        mma16816(sacc[mt][j], qlf[mt][2 * cp],     &kf[cur][cp][0]);
                        mma16816(sacc[mt][j], qlf[mt][2 * cp + 1], &kf[cur][cp][2]);
                    }
            }
            if (more) load_kv_part(kvt + 1, ns, 0);

            if (c_base + 63 > wrow_min) {
                #pragma unroll
                for (int mt = 0; mt < 2; mt++) {
                    const int lr0 = wrow_min + 16 * mt + g;
                    #pragma unroll
                    for (int j = 0; j < 8; j++) {
                        const int c0 = c_base + 8 * j + 2 * t;
                        if (c0     > lr0)     sacc[mt][j][0] = -1e30f;
                        if (c0 + 1 > lr0)     sacc[mt][j][1] = -1e30f;
                        if (c0     > lr0 + 8) sacc[mt][j][2] = -1e30f;
                        if (c0 + 1 > lr0 + 8) sacc[mt][j][3] = -1e30f;
                    }
                }
            }

            #pragma unroll
            for (int mt = 0; mt < 2; mt++) {
                float mx0 = -1e30f, mx1 = -1e30f;
                #pragma unroll
                for (int j = 0; j < 8; j++) {
                    mx0 = fmaxf(mx0, fmaxf(sacc[mt][j][0], sacc[mt][j][1]));
                    mx1 = fmaxf(mx1, fmaxf(sacc[mt][j][2], sacc[mt][j][3]));
                }
                mx0 = fmaxf(mx0, __shfl_xor_sync(0xffffffffu, mx0, 1));
                mx0 = fmaxf(mx0, __shfl_xor_sync(0xffffffffu, mx0, 2));
                mx1 = fmaxf(mx1, __shfl_xor_sync(0xffffffffu, mx1, 1));
                mx1 = fmaxf(mx1, __shfl_xor_sync(0xffffffffu, mx1, 2));
                const float mn0 = fmaxf(mrow[mt][0], mx0), mn1 = fmaxf(mrow[mt][1], mx1);
                const float al0 = exp2f(mrow[mt][0] - mn0), al1 = exp2f(mrow[mt][1] - mn1);
                float sum0 = 0.f, sum1 = 0.f;
                #pragma unroll
                for (int j = 0; j < 8; j++) {
                    sacc[mt][j][0] = exp2f(sacc[mt][j][0] - mn0);
                    sacc[mt][j][1] = exp2f(sacc[mt][j][1] - mn0);
                    sacc[mt][j][2] = exp2f(sacc[mt][j][2] - mn1);
                    sacc[mt][j][3] = exp2f(sacc[mt][j][3] - mn1);
                    sum0 += sacc[mt][j][0] + sacc[mt][j][1];
                    sum1 += sacc[mt][j][2] + sacc[mt][j][3];
                }
                sum0 += __shfl_xor_sync(0xffffffffu, sum0, 1);
                sum0 += __shfl_xor_sync(0xffffffffu, sum0, 2);
                sum1 += __shfl_xor_sync(0xffffffffu, sum1, 1);
                sum1 += __shfl_xor_sync(0xffffffffu, sum1, 2);
                lrow[mt][0] = lrow[mt][0] * al0 + sum0; mrow[mt][0] = mn0;
                lrow[mt][1] = lrow[mt][1] * al1 + sum1; mrow[mt][1] = mn1;
                #pragma unroll
                for (int j = 0; j < 8; j++) {
                    oacc[mt][j][0] *= al0; oacc[mt][j][1] *= al0;
                    oacc[mt][j][2] *= al1; oacc[mt][j][3] *= al1;
                }
            }

            // ---- O += P V (1 pass: p single, v single) ----
            #pragma unroll
            for (int s2 = 0; s2 < 4; s2++) {
                uint32_t pf[2][4];
                #pragma unroll
                for (int mt = 0; mt < 2; mt++) {
                    pf[mt][0] = pack2h(sacc[mt][2 * s2][0],     sacc[mt][2 * s2][1]);
                    pf[mt][1] = pack2h(sacc[mt][2 * s2][2],     sacc[mt][2 * s2][3]);
                    pf[mt][2] = pack2h(sacc[mt][2 * s2 + 1][0], sacc[mt][2 * s2 + 1][1]);
                    pf[mt][3] = pack2h(sacc[mt][2 * s2 + 1][2], sacc[mt][2 * s2 + 1][3]);
                }
                uint32_t vf[4][4];
                #pragma unroll
                for (int jp = 0; jp < 4; jp++) {
                    uint32_t ad = kb + AT_KTILE +
                        (uint32_t)((16 * s2 + (lane & 15)) * AT_ROWB + (2 * jp + (lane >> 4)) * 16);
                    ldsm4t(vf[jp], ad);
                }
                #pragma unroll
                for (int jp = 0; jp < 4; jp++)
                    #pragma unroll
                    for (int mt = 0; mt < 2; mt++) {
                        mma16816(oacc[mt][2 * jp],     pf[mt], &vf[jp][0]);
                        mma16816(oacc[mt][2 * jp + 1], pf[mt], &vf[jp][2]);
                    }
                if (more && s2 == 1) load_kv_part(kvt + 1, ns, 1);
            }
        } else if (more) {
            load_kv_part(kvt + 1, ns, 0);
            load_kv_part(kvt + 1, ns, 1);
        }
        asm volatile("cp.async.commit_group;" ::: "memory");
    }
    __syncthreads();

    // epilogue: stage z hi/lo in region 0, coalesced 16B stores
    const uint32_t oh0 = sb, ol0 = sb + AT_QTILE;
    #pragma unroll
    for (int mt = 0; mt < 2; mt++) {
        const float i0 = 1.f / lrow[mt][0], i1 = 1.f / lrow[mt][1];
        const int rl = 32 * w + 16 * mt + g;
        #pragma unroll
        for (int j = 0; j < 8; j++) {
            const int cl = 8 * j + 2 * t;
            uint32_t hu, lu;
            split2h(oacc[mt][j][0] * i0, oacc[mt][j][1] * i0, hu, lu);
            sts32(oh0 + (uint32_t)(rl * AT_ROWB + cl * 2), hu);
            sts32(ol0 + (uint32_t)(rl * AT_ROWB + cl * 2), lu);
            split2h(oacc[mt][j][2] * i1, oacc[mt][j][3] * i1, hu, lu);
            sts32(oh0 + (uint32_t)((rl + 8) * AT_ROWB + cl * 2), hu);
            sts32(ol0 + (uint32_t)((rl + 8) * AT_ROWB + cl * 2), lu);
        }
    }
    __syncthreads();
    const int b = bh >> 4, h = bh & 15;
    #pragma unroll
    for (int it = 0; it < 8; it++) {
        const int id = it * 128 + tid, r = id >> 3, s = id & 7;
        const size_t dst = ((size_t)b * P_SZ + q0 + r) * K_SZ + h * 64 + s * 8;
        uint4 vh4 = lds128(oh0 + (uint32_t)(r * AT_ROWB + s * 16));
        uint4 vl4 = lds128(ol0 + (uint32_t)(r * AT_ROWB + s * 16));
        *(uint4*)(zh + dst) = vh4;
        *(uint4*)(zl + dst) = vl4;
    }
}

// ---------------------------------------------------------------------------
extern "C" void kernel_launch(void* const* d_in, const int* in_sizes, int n_in,
                              void* d_out, int out_size)
{
    (void)in_sizes; (void)n_in; (void)out_size;
    const float* x      = (const float*)d_in[0];
    const float* W_attn = (const float*)d_in[1];
    const float* b_attn = (const float*)d_in[2];
    const float* W_proj = (const float*)d_in[3];
    const float* b_proj = (const float*)d_in[4];
    float* out = (float*)d_out;

    __half *xhi, *xlo, *wa, *wp;
    __half *qh, *ql, *kk, *vv, *zh, *zl;
    cudaGetSymbolAddress((void**)&xhi, g_xhi);
    cudaGetSymbolAddress((void**)&xlo, g_xlo);
    cudaGetSymbolAddress((void**)&wa,  g_wa);
    cudaGetSymbolAddress((void**)&wp,  g_wp);
    cudaGetSymbolAddress((void**)&qh,  g_qh);
    cudaGetSymbolAddress((void**)&ql,  g_ql);
    cudaGetSymbolAddress((void**)&kk,  g_k);
    cudaGetSymbolAddress((void**)&vv,  g_v);
    cudaGetSymbolAddress((void**)&zh,  g_zh);
    cudaGetSymbolAddress((void**)&zl,  g_zl);

    cudaFuncSetAttribute(gemm_mma_kernel<0>,
                         cudaFuncAttributeMaxDynamicSharedMemorySize, GT_SMEM);
    cudaFuncSetAttribute(gemm_mma_kernel<1>,
                         cudaFuncAttributeMaxDynamicSharedMemorySize, GT_SMEM);
    cudaFuncSetAttribute(attn_mma_kernel,
                         cudaFuncAttributeMaxDynamicSharedMemorySize, AT_SMEM);

    split_kernel<<<(R_SZ * K_SZ / 4 + 255) / 256, 256>>>(x, xhi, xlo, R_SZ * K_SZ / 4);
    tsingle_kernel<<<dim3(N3_SZ / 32, K_SZ / 32), 256>>>(W_attn, wa, K_SZ, N3_SZ);
    tsingle_kernel<<<dim3(M_SZ / 32, K_SZ / 32), 256>>>(W_proj, wp, K_SZ, M_SZ);

    gemm_mma_kernel<1><<<dim3(N3_SZ / 128, R_SZ / 128), 128, GT_SMEM>>>(
        xhi, xlo, wa, b_attn, nullptr, N3_SZ, qh, ql, kk, vv);

    attn_mma_kernel<<<dim3(P_SZ / 128, BH_SZ), 128, AT_SMEM>>>(
        qh, ql, kk, vv, zh, zl);

    gemm_mma_kernel<0><<<dim3(M_SZ / 128, R_SZ / 128), 128, GT_SMEM>>>(
        zh, zl, wp, b_proj, out, M_SZ,
        nullptr, nullptr, nullptr, nullptr);
}

// round 14
// speedup vs baseline: 2.1898x; 1.2615x over previous
#include <cuda_runtime.h>
#include <cuda_fp16.h>
#include <cstdint>
#include <string.h>
#include <math.h>

#define B_SZ 2
#define P_SZ 2048
#define M_SZ 1024
#define H_SZ 16
#define D_SZ 64
#define N3_SZ 3072
#define R_SZ (B_SZ * P_SZ)      // 4096
#define K_SZ M_SZ               // 1024
#define BH_SZ (B_SZ * H_SZ)     // 32

// ---------------- scratch (__device__ globals) -----------------------------
__device__ __half g_xh [(size_t)R_SZ * K_SZ];          // x single fp16
__device__ __half g_wa [(size_t)N3_SZ * K_SZ];         // W_attn^T fp16
__device__ __half g_wp [(size_t)M_SZ * K_SZ];          // W_proj^T fp16
__device__ __half g_qh[(size_t)BH_SZ * P_SZ * D_SZ];
__device__ __half g_ql[(size_t)BH_SZ * P_SZ * D_SZ];
__device__ __half g_k [(size_t)BH_SZ * P_SZ * D_SZ];
__device__ __half g_v [(size_t)BH_SZ * P_SZ * D_SZ];
__device__ __half g_z [(size_t)R_SZ * K_SZ];           // z single fp16

// ---------------- PTX helpers (base ISA) -----------------------------------
__device__ __forceinline__ uint32_t smem_u32(const void* p) {
    uint32_t a;
    asm("{ .reg .u64 t; cvta.to.shared.u64 t, %1; cvt.u32.u64 %0, t; }" : "=r"(a) : "l"(p));
    return a;
}
__device__ __forceinline__ void ldsm4(uint32_t* r, uint32_t addr) {
    asm volatile("ldmatrix.sync.aligned.m8n8.x4.shared.b16 {%0,%1,%2,%3}, [%4];"
                 : "=r"(r[0]), "=r"(r[1]), "=r"(r[2]), "=r"(r[3]) : "r"(addr));
}
__device__ __forceinline__ void ldsm4t(uint32_t* r, uint32_t addr) {
    asm volatile("ldmatrix.sync.aligned.m8n8.x4.trans.shared.b16 {%0,%1,%2,%3}, [%4];"
                 : "=r"(r[0]), "=r"(r[1]), "=r"(r[2]), "=r"(r[3]) : "r"(addr));
}
__device__ __forceinline__ void mma16816(float* c, const uint32_t* a, const uint32_t* b) {
    asm volatile(
        "mma.sync.aligned.m16n8k16.row.col.f32.f16.f16.f32 "
        "{%0,%1,%2,%3}, {%4,%5,%6,%7}, {%8,%9}, {%0,%1,%2,%3};"
        : "+f"(c[0]), "+f"(c[1]), "+f"(c[2]), "+f"(c[3])
        : "r"(a[0]), "r"(a[1]), "r"(a[2]), "r"(a[3]), "r"(b[0]), "r"(b[1]));
}
__device__ __forceinline__ void cpasync16(uint32_t saddr, const void* gaddr) {
    asm volatile("cp.async.cg.shared.global [%0], [%1], 16;" :: "r"(saddr), "l"(gaddr) : "memory");
}
__device__ __forceinline__ void sts32(uint32_t addr, uint32_t v) {
    asm volatile("st.shared.b32 [%0], %1;" :: "r"(addr), "r"(v) : "memory");
}
__device__ __forceinline__ void sts64(uint32_t addr, float a, float b) {
    asm volatile("st.shared.v2.f32 [%0], {%1,%2};" :: "r"(addr), "f"(a), "f"(b) : "memory");
}
__device__ __forceinline__ uint4 lds128(uint32_t addr) {
    uint4 v;
    asm volatile("ld.shared.v4.b32 {%0,%1,%2,%3}, [%4];"
                 : "=r"(v.x), "=r"(v.y), "=r"(v.z), "=r"(v.w) : "r"(addr));
    return v;
}
__device__ __forceinline__ void split2h(float a, float b, uint32_t& hu, uint32_t& lu) {
    __half ha = __float2half_rn(a), hb = __float2half_rn(b);
    float ra = a - __half2float(ha), rb = b - __half2float(hb);
    __half2 H = __halves2half2(ha, hb);
    __half2 L = __floats2half2_rn(ra, rb);
    memcpy(&hu, &H, 4); memcpy(&lu, &L, 4);
}
__device__ __forceinline__ uint32_t pack2h(float a, float b) {
    __half2 H = __floats2half2_rn(a, b);
    uint32_t u; memcpy(&u, &H, 4); return u;
}

// ---------------- fp32 -> fp16 single convert ------------------------------
struct alignas(8) h16x4 { __half2 a, b; };

__global__ __launch_bounds__(256) void convert_kernel(
    const float* __restrict__ in, __half* __restrict__ out, int n4)
{
    int i = blockIdx.x * 256 + threadIdx.x;
    if (i >= n4) return;
    float4 v = ((const float4*)in)[i];
    h16x4 H;
    H.a = __floats2half2_rn(v.x, v.y);
    H.b = __floats2half2_rn(v.z, v.w);
    ((h16x4*)out)[i] = H;
}

// W [K,N] fp32 -> Wt [N,K] fp16 (transpose + round)
__global__ __launch_bounds__(256) void tsingle_kernel(
    const float* __restrict__ W, __half* __restrict__ out, int K, int N)
{
    __shared__ float s[32][33];
    const int n0 = blockIdx.x * 32, k0 = blockIdx.y * 32;
    const int tx = threadIdx.x & 31, ty = threadIdx.x >> 5;
    #pragma unroll
    for (int i = 0; i < 4; i++)
        s[ty + 8 * i][tx] = W[(size_t)(k0 + ty + 8 * i) * N + n0 + tx];
    __syncthreads();
    #pragma unroll
    for (int i = 0; i < 4; i++) {
        int r = ty + 8 * i;
        out[(size_t)(n0 + r) * K + k0 + tx] = __float2half_rn(s[tx][r]);
    }
}

// ---------------- fp16 1-term mma GEMM: C = A@B^T --------------------------
#define GK_CH   (K_SZ / 32)
#define GT_TILE 10240                  // 128 rows * 80 B
#define GT_STG  (2 * GT_TILE)          // A, B
#define GT_SMEM 69632                  // epilogue staging dominates

// Q pre-scale: 1/sqrt(64) * log2(e)
#define QSCALE (0.125f * 1.44269504088896f)

template<int MODE>
__global__ __launch_bounds__(128) void gemm_mma_kernel(
    const __half* __restrict__ A, const __half* __restrict__ B,
    const float* __restrict__ bias, float* __restrict__ C, int N,
    __half* __restrict__ qh, __half* __restrict__ ql,
    __half* __restrict__ kk, __half* __restrict__ vv)
{
    extern __shared__ char smraw[];
    const uint32_t sbase = smem_u32(smraw);

    const int tid = threadIdx.x;
    const int wid = tid >> 5, lane = tid & 31;
    const int wm = wid & 1, wn = wid >> 1;
    const int g = lane >> 2, t = lane & 3;
    const int row0 = blockIdx.y << 7;
    const int col0 = blockIdx.x << 7;

    const __half* srcs[2] = {A, B};

    auto load_part = [&](int c, int s, int arr) {
        const int k0 = c << 5;
        const __half* src = srcs[arr];
        const int rbase = (arr == 0) ? row0 : col0;
        const uint32_t tb = sbase + (uint32_t)s * GT_STG + (uint32_t)arr * GT_TILE;
        #pragma unroll
        for (int it = 0; it < 4; it++) {
            int id = it * 128 + tid, r = id >> 2, q = id & 3;
            cpasync16(tb + (uint32_t)(r * 80 + q * 16),
                      src + (size_t)(rbase + r) * K_SZ + k0 + q * 8);
        }
    };

    float acc[4][8][4] = {};
    const int a_row = lane & 15;
    const int a_cb  = (lane >> 4) << 4;
    const int b2_row = (lane & 7) + ((lane >> 4) << 3);
    const int b2_cb  = ((lane >> 3) & 1) << 4;

    load_part(0, 0, 0);
    load_part(0, 0, 1);
    asm volatile("cp.async.commit_group;" ::: "memory");

    for (int c = 0; c < GK_CH; c++) {
        const int s = c & 1, ns = s ^ 1;
        asm volatile("cp.async.wait_group 0;" ::: "memory");
        __syncthreads();

        const uint32_t stg = sbase + (uint32_t)s * GT_STG;
        const uint32_t tA = stg, tB = stg + GT_TILE;
        const bool more = (c + 1 < GK_CH);

        #pragma unroll
        for (int ks = 0; ks < 2; ks++) {
            const int kb = ks << 5;
            uint32_t af[4][4], bf[4][4];
            #pragma unroll
            for (int mt = 0; mt < 4; mt++)
                ldsm4(af[mt], tA + (uint32_t)((wm * 64 + mt * 16 + a_row) * 80 + kb + a_cb));
            #pragma unroll
            for (int np = 0; np < 4; np++)
                ldsm4(bf[np], tB + (uint32_t)((wn * 64 + np * 16 + b2_row) * 80 + kb + b2_cb));
            if (more) load_part(c + 1, ns, ks);   // overlap load issue with MMAs
            #pragma unroll
            for (int np = 0; np < 4; np++)
                #pragma unroll
                for (int mt = 0; mt < 4; mt++) {
                    mma16816(acc[mt][2 * np],     af[mt], &bf[np][0]);
                    mma16816(acc[mt][2 * np + 1], af[mt], &bf[np][2]);
                }
        }
        asm volatile("cp.async.commit_group;" ::: "memory");
    }
    __syncthreads();

    if (MODE == 1) {
        // tile lies fully in one qkv slice (1024 % 128 == 0)
        const int slice = col0 >> 10;
        const uint32_t hi0 = sbase, lo0 = sbase + 128 * 272;
        #pragma unroll
        for (int mt = 0; mt < 4; mt++) {
            const int rl = wm * 64 + mt * 16 + g;
            #pragma unroll
            for (int nt = 0; nt < 8; nt++) {
                const int cl = wn * 64 + nt * 8 + 2 * t;
                const int col = col0 + cl;
                const float b0 = bias[col], b1 = bias[col + 1];
                float v0 = acc[mt][nt][0] + b0, v1 = acc[mt][nt][1] + b1;
                float v2 = acc[mt][nt][2] + b0, v3 = acc[mt][nt][3] + b1;
                if (slice == 0) {
                    v0 *= QSCALE; v1 *= QSCALE; v2 *= QSCALE; v3 *= QSCALE;
                    uint32_t hu, lu;
                    split2h(v0, v1, hu, lu);
                    sts32(hi0 + (uint32_t)(rl * 272 + cl * 2), hu);
                    sts32(lo0 + (uint32_t)(rl * 272 + cl * 2), lu);
                    split2h(v2, v3, hu, lu);
                    sts32(hi0 + (uint32_t)((rl + 8) * 272 + cl * 2), hu);
                    sts32(lo0 + (uint32_t)((rl + 8) * 272 + cl * 2), lu);
                } else {
                    sts32(hi0 + (uint32_t)(rl * 272 + cl * 2), pack2h(v0, v1));
                    sts32(hi0 + (uint32_t)((rl + 8) * 272 + cl * 2), pack2h(v2, v3));
                }
            }
        }
        __syncthreads();
        #pragma unroll
        for (int it = 0; it < 16; it++) {
            const int id = it * 128 + tid, r = id >> 4, s = id & 15;
            const int col = col0 + s * 8;
            const int hh = (col >> 6) & 15, dd = col & 63;
            __half* oh = (slice == 0) ? qh : (slice == 1) ? kk : vv;
            const int row = row0 + r;
            const int ba = row >> 11, pa = row & 2047;
            const size_t oa = ((size_t)(ba * H_SZ + hh) * P_SZ + pa) * 64 + dd;
            uint4 vh4 = lds128(hi0 + (uint32_t)(r * 272 + s * 16));
            *(uint4*)(oh + oa) = vh4;
            if (slice == 0) {
                uint4 vl4 = lds128(lo0 + (uint32_t)(r * 272 + s * 16));
                *(uint4*)(ql + oa) = vl4;
            }
        }
    } else {
        #pragma unroll
        for (int mt = 0; mt < 4; mt++) {
            const int rl = wm * 64 + mt * 16 + g;
            #pragma unroll
            for (int nt = 0; nt < 8; nt++) {
                const int cl = wn * 64 + nt * 8 + 2 * t;
                const int col = col0 + cl;
                const float b0 = bias[col], b1 = bias[col + 1];
                sts64(sbase + (uint32_t)(rl * 528 + cl * 4),
                      acc[mt][nt][0] + b0, acc[mt][nt][1] + b1);
                sts64(sbase + (uint32_t)((rl + 8) * 528 + cl * 4),
                      acc[mt][nt][2] + b0, acc[mt][nt][3] + b1);
            }
        }
        __syncthreads();
        #pragma unroll
        for (int it = 0; it < 32; it++) {
            const int id = it * 128 + tid, r = id >> 5, s = id & 31;
            uint4 v = lds128(sbase + (uint32_t)(r * 528 + s * 16));
            *(uint4*)(C + (size_t)(row0 + r) * N + col0 + s * 4) = v;
        }
    }
}

// ---------------- fp16 flash attention: S 2-term, PV 1-term ----------------
#define AT_ROWB 144
#define AT_QTILE (128 * AT_ROWB)         // 18432
#define AT_KTILE (64 * AT_ROWB)          // 9216
#define AT_STG   (2 * AT_KTILE)          // 18432 (K, V)
#define AT_SMEM  (2 * AT_QTILE + AT_STG) // 55296

__global__ __launch_bounds__(128) void attn_mma_kernel(
    const __half* __restrict__ qh, const __half* __restrict__ ql,
    const __half* __restrict__ kk, const __half* __restrict__ vv,
    __half* __restrict__ z)
{
    extern __shared__ char smraw[];
    const uint32_t sb = smem_u32(smraw);
    const int tid = threadIdx.x, w = tid >> 5, lane = tid & 31;
    const int g = lane >> 2, t = lane & 3;
    const int qt = blockIdx.x, bh = blockIdx.y;
    const int q0 = qt << 7;
    const size_t hb = (size_t)bh * P_SZ * 64;

    const __half* kvsrc[2] = {kk + hb, vv + hb};
    auto stage_base = [&](int s) -> uint32_t {
        return (s == 0) ? sb + 2 * AT_QTILE : sb;
    };
    auto load_kv_part = [&](int kvt, int s, int a) {
        const uint32_t stg = stage_base(s);
        const size_t rb = (size_t)(kvt << 6) * 64;
        #pragma unroll
        for (int it = 0; it < 4; it++) {
            int id = it * 128 + tid, r = id >> 3, c = id & 7;
            cpasync16(stg + (uint32_t)(a * AT_KTILE + r * AT_ROWB + c * 16),
                      kvsrc[a] + rb + r * 64 + c * 8);
        }
    };

    {   // Q hi/lo into region 0
        const __half* Qh = qh + hb + (size_t)q0 * 64;
        const __half* Ql = ql + hb + (size_t)q0 * 64;
        #pragma unroll
        for (int it = 0; it < 8; it++) {
            int id = it * 128 + tid, r = id >> 3, c = id & 7;
            cpasync16(sb + (uint32_t)(r * AT_ROWB + c * 16), Qh + r * 64 + c * 8);
            cpasync16(sb + AT_QTILE + (uint32_t)(r * AT_ROWB + c * 16), Ql + r * 64 + c * 8);
        }
    }
    load_kv_part(0, 0, 0);
    load_kv_part(0, 0, 1);
    asm volatile("cp.async.commit_group;" ::: "memory");
    asm volatile("cp.async.wait_group 0;" ::: "memory");
    __syncthreads();

    uint32_t qhf[2][4][4], qlf[2][4][4];
    const int arow = (lane & 7) + ((lane >> 3) & 1) * 8;
    const int achk = lane >> 4;
    #pragma unroll
    for (int mt = 0; mt < 2; mt++)
        #pragma unroll
        for (int ks = 0; ks < 4; ks++) {
            uint32_t ad = sb + (uint32_t)((32 * w + 16 * mt + arow) * AT_ROWB +
                                          (2 * ks + achk) * 16);
            ldsm4(qhf[mt][ks], ad);
            ldsm4(qlf[mt][ks], ad + AT_QTILE);
        }
    __syncthreads();

    float oacc[2][8][4] = {};
    float mrow[2][2], lrow[2][2];
    #pragma unroll
    for (int mt = 0; mt < 2; mt++) {
        mrow[mt][0] = -1e30f; mrow[mt][1] = -1e30f;
        lrow[mt][0] = 0.f;    lrow[mt][1] = 0.f;
    }
    const int wrow_min = q0 + 32 * w;
    const int wrow_max = wrow_min + 31;
    const int ntiles = 2 * qt + 2;

    for (int kvt = 0; kvt < ntiles; kvt++) {
        const int s = kvt & 1, ns = s ^ 1;
        if (kvt > 0) {
            asm volatile("cp.async.wait_group 0;" ::: "memory");
            __syncthreads();
        }
        const bool more = (kvt + 1 < ntiles);
        const int c_base = kvt << 6;
        if (c_base <= wrow_max) {
            const uint32_t kb = stage_base(s);

            float sacc[2][8][4] = {};
            uint32_t kf[2][2][4];
            #pragma unroll
            for (int cp = 0; cp < 2; cp++) {
                uint32_t ad = kb + (uint32_t)((lane & 7) * AT_ROWB + (4 * cp + (lane >> 3)) * 16);
                ldsm4(kf[0][cp], ad);
            }
            #pragma unroll
            for (int j = 0; j < 8; j++) {
                const int cur = j & 1, nxt = cur ^ 1;
                if (j < 7) {
                    #pragma unroll
                    for (int cp = 0; cp < 2; cp++) {
                        uint32_t ad = kb + (uint32_t)((8 * (j + 1) + (lane & 7)) * AT_ROWB +
                                                      (4 * cp + (lane >> 3)) * 16);
                        ldsm4(kf[nxt][cp], ad);
                    }
                }
                #pragma unroll
                for (int cp = 0; cp < 2; cp++)
                    #pragma unroll
                    for (int mt = 0; mt < 2; mt++) {
                        mma16816(sacc[mt][j], qhf[mt][2 * cp],     &kf[cur][cp][0]);
                        mma16816(sacc[mt][j], qhf[mt][2 * cp + 1], &kf[cur][cp][2]);
                    }
                #pragma unroll
                for (int cp = 0; cp < 2; cp++)
                    #pragma unroll
                    for (int mt = 0; mt < 2; mt++) {
                        mma16816(sacc[mt][j], qlf[mt][2 * cp],     &kf[cur][cp][0]);
                        mma16816(sacc[mt][j], qlf[mt][2 * cp + 1], &kf[cur][cp][2]);
                    }
            }
            if (more) load_kv_part(kvt + 1, ns, 0);

            if (c_base + 63 > wrow_min) {
                #pragma unroll
                for (int mt = 0; mt < 2; mt++) {
                    const int lr0 = wrow_min + 16 * mt + g;
                    #pragma unroll
                    for (int j = 0; j < 8; j++) {
                        const int c0 = c_base + 8 * j + 2 * t;
                        if (c0     > lr0)     sacc[mt][j][0] = -1e30f;
                        if (c0 + 1 > lr0)     sacc[mt][j][1] = -1e30f;
                        if (c0     > lr0 + 8) sacc[mt][j][2] = -1e30f;
                        if (c0 + 1 > lr0 + 8) sacc[mt][j][3] = -1e30f;
                    }
                }
            }

            #pragma unroll
            for (int mt = 0; mt < 2; mt++) {
                float mx0 = -1e30f, mx1 = -1e30f;
                #pragma unroll
                for (int j = 0; j < 8; j++) {
                    mx0 = fmaxf(mx0, fmaxf(sacc[mt][j][0], sacc[mt][j][1]));
                    mx1 = fmaxf(mx1, fmaxf(sacc[mt][j][2], sacc[mt][j][3]));
                }
                mx0 = fmaxf(mx0, __shfl_xor_sync(0xffffffffu, mx0, 1));
                mx0 = fmaxf(mx0, __shfl_xor_sync(0xffffffffu, mx0, 2));
                mx1 = fmaxf(mx1, __shfl_xor_sync(0xffffffffu, mx1, 1));
                mx1 = fmaxf(mx1, __shfl_xor_sync(0xffffffffu, mx1, 2));
                const float mn0 = fmaxf(mrow[mt][0], mx0), mn1 = fmaxf(mrow[mt][1], mx1);
                const float al0 = exp2f(mrow[mt][0] - mn0), al1 = exp2f(mrow[mt][1] - mn1);
                float sum0 = 0.f, sum1 = 0.f;
                #pragma unroll
                for (int j = 0; j < 8; j++) {
                    sacc[mt][j][0] = exp2f(sacc[mt][j][0] - mn0);
                    sacc[mt][j][1] = exp2f(sacc[mt][j][1] - mn0);
                    sacc[mt][j][2] = exp2f(sacc[mt][j][2] - mn1);
                    sacc[mt][j][3] = exp2f(sacc[mt][j][3] - mn1);
                    sum0 += sacc[mt][j][0] + sacc[mt][j][1];
                    sum1 += sacc[mt][j][2] + sacc[mt][j][3];
                }
                sum0 += __shfl_xor_sync(0xffffffffu, sum0, 1);
                sum0 += __shfl_xor_sync(0xffffffffu, sum0, 2);
                sum1 += __shfl_xor_sync(0xffffffffu, sum1, 1);
                sum1 += __shfl_xor_sync(0xffffffffu, sum1, 2);
                lrow[mt][0] = lrow[mt][0] * al0 + sum0; mrow[mt][0] = mn0;
                lrow[mt][1] = lrow[mt][1] * al1 + sum1; mrow[mt][1] = mn1;
                #pragma unroll
                for (int j = 0; j < 8; j++) {
                    oacc[mt][j][0] *= al0; oacc[mt][j][1] *= al0;
                    oacc[mt][j][2] *= al1; oacc[mt][j][3] *= al1;
                }
            }

            #pragma unroll
            for (int s2 = 0; s2 < 4; s2++) {
                uint32_t pf[2][4];
                #pragma unroll
                for (int mt = 0; mt < 2; mt++) {
                    pf[mt][0] = pack2h(sacc[mt][2 * s2][0],     sacc[mt][2 * s2][1]);
                    pf[mt][1] = pack2h(sacc[mt][2 * s2][2],     sacc[mt][2 * s2][3]);
                    pf[mt][2] = pack2h(sacc[mt][2 * s2 + 1][0], sacc[mt][2 * s2 + 1][1]);
                    pf[mt][3] = pack2h(sacc[mt][2 * s2 + 1][2], sacc[mt][2 * s2 + 1][3]);
                }
                uint32_t vf[4][4];
                #pragma unroll
                for (int jp = 0; jp < 4; jp++) {
                    uint32_t ad = kb + AT_KTILE +
                        (uint32_t)((16 * s2 + (lane & 15)) * AT_ROWB + (2 * jp + (lane >> 4)) * 16);
                    ldsm4t(vf[jp], ad);
                }
                #pragma unroll
                for (int jp = 0; jp < 4; jp++)
                    #pragma unroll
                    for (int mt = 0; mt < 2; mt++) {
                        mma16816(oacc[mt][2 * jp],     pf[mt], &vf[jp][0]);
                        mma16816(oacc[mt][2 * jp + 1], pf[mt], &vf[jp][2]);
                    }
                if (more && s2 == 1) load_kv_part(kvt + 1, ns, 1);
            }
        } else if (more) {
            load_kv_part(kvt + 1, ns, 0);
            load_kv_part(kvt + 1, ns, 1);
        }
        asm volatile("cp.async.commit_group;" ::: "memory");
    }
    __syncthreads();

    // epilogue: z single fp16, staged for coalesced 16B stores
    const uint32_t oh0 = sb;
    #pragma unroll
    for (int mt = 0; mt < 2; mt++) {
        const float i0 = 1.f / lrow[mt][0], i1 = 1.f / lrow[mt][1];
        const int rl = 32 * w + 16 * mt + g;
        #pragma unroll
        for (int j = 0; j < 8; j++) {
            const int cl = 8 * j + 2 * t;
            sts32(oh0 + (uint32_t)(rl * AT_ROWB + cl * 2),
                  pack2h(oacc[mt][j][0] * i0, oacc[mt][j][1] * i0));
            sts32(oh0 + (uint32_t)((rl + 8) * AT_ROWB + cl * 2),
                  pack2h(oacc[mt][j][2] * i1, oacc[mt][j][3] * i1));
        }
    }
    __syncthreads();
    const int b = bh >> 4, h = bh & 15;
    #pragma unroll
    for (int it = 0; it < 8; it++) {
        const int id = it * 128 + tid, r = id >> 3, s = id & 7;
        const size_t dst = ((size_t)b * P_SZ + q0 + r) * K_SZ + h * 64 + s * 8;
        uint4 vh4 = lds128(oh0 + (uint32_t)(r * AT_ROWB + s * 16));
        *(uint4*)(z + dst) = vh4;
    }
}

// ---------------------------------------------------------------------------
extern "C" void kernel_launch(void* const* d_in, const int* in_sizes, int n_in,
                              void* d_out, int out_size)
{
    (void)in_sizes; (void)n_in; (void)out_size;
    const float* x      = (const float*)d_in[0];
    const float* W_attn = (const float*)d_in[1];
    const float* b_attn = (const float*)d_in[2];
    const float* W_proj = (const float*)d_in[3];
    const float* b_proj = (const float*)d_in[4];
    float* out = (float*)d_out;

    __half *xh, *wa, *wp, *qh, *ql, *kk, *vv, *zz;
    cudaGetSymbolAddress((void**)&xh, g_xh);
    cudaGetSymbolAddress((void**)&wa, g_wa);
    cudaGetSymbolAddress((void**)&wp, g_wp);
    cudaGetSymbolAddress((void**)&qh, g_qh);
    cudaGetSymbolAddress((void**)&ql, g_ql);
    cudaGetSymbolAddress((void**)&kk, g_k);
    cudaGetSymbolAddress((void**)&vv, g_v);
    cudaGetSymbolAddress((void**)&zz, g_z);

    cudaFuncSetAttribute(gemm_mma_kernel<0>,
                         cudaFuncAttributeMaxDynamicSharedMemorySize, GT_SMEM);
    cudaFuncSetAttribute(gemm_mma_kernel<1>,
                         cudaFuncAttributeMaxDynamicSharedMemorySize, GT_SMEM);
    cudaFuncSetAttribute(attn_mma_kernel,
                         cudaFuncAttributeMaxDynamicSharedMemorySize, AT_SMEM);

    convert_kernel<<<(R_SZ * K_SZ / 4 + 255) / 256, 256>>>(x, xh, R_SZ * K_SZ / 4);
    tsingle_kernel<<<dim3(N3_SZ / 32, K_SZ / 32), 256>>>(W_attn, wa, K_SZ, N3_SZ);
    tsingle_kernel<<<dim3(M_SZ / 32, K_SZ / 32), 256>>>(W_proj, wp, K_SZ, M_SZ);

    gemm_mma_kernel<1><<<dim3(N3_SZ / 128, R_SZ / 128), 128, GT_SMEM>>>(
        xh, wa, b_attn, nullptr, N3_SZ, qh, ql, kk, vv);

    attn_mma_kernel<<<dim3(P_SZ / 128, BH_SZ), 128, AT_SMEM>>>(
        qh, ql, kk, vv, zz);

    gemm_mma_kernel<0><<<dim3(M_SZ / 128, R_SZ / 128), 128, GT_SMEM>>>(
        zz, wp, b_proj, out, M_SZ,
        nullptr, nullptr, nullptr, nullptr);
}

// round 15
// speedup vs baseline: 2.3143x; 1.0569x over previous
#include <cuda_runtime.h>
#include <cuda_fp16.h>
#include <cstdint>
#include <string.h>
#include <math.h>

#define B_SZ 2
#define P_SZ 2048
#define M_SZ 1024
#define H_SZ 16
#define D_SZ 64
#define N3_SZ 3072
#define R_SZ (B_SZ * P_SZ)      // 4096
#define K_SZ M_SZ               // 1024
#define BH_SZ (B_SZ * H_SZ)     // 32

// ---------------- scratch (__device__ globals) -----------------------------
__device__ __half g_xh [(size_t)R_SZ * K_SZ];
__device__ __half g_wa [(size_t)N3_SZ * K_SZ];
__device__ __half g_wp [(size_t)M_SZ * K_SZ];
__device__ __half g_qh[(size_t)BH_SZ * P_SZ * D_SZ];
__device__ __half g_ql[(size_t)BH_SZ * P_SZ * D_SZ];
__device__ __half g_k [(size_t)BH_SZ * P_SZ * D_SZ];
__device__ __half g_v [(size_t)BH_SZ * P_SZ * D_SZ];
__device__ __half g_z [(size_t)R_SZ * K_SZ];

// ---------------- PTX helpers (base ISA) -----------------------------------
__device__ __forceinline__ uint32_t smem_u32(const void* p) {
    uint32_t a;
    asm("{ .reg .u64 t; cvta.to.shared.u64 t, %1; cvt.u32.u64 %0, t; }" : "=r"(a) : "l"(p));
    return a;
}
__device__ __forceinline__ void ldsm4(uint32_t* r, uint32_t addr) {
    asm volatile("ldmatrix.sync.aligned.m8n8.x4.shared.b16 {%0,%1,%2,%3}, [%4];"
                 : "=r"(r[0]), "=r"(r[1]), "=r"(r[2]), "=r"(r[3]) : "r"(addr));
}
__device__ __forceinline__ void ldsm4t(uint32_t* r, uint32_t addr) {
    asm volatile("ldmatrix.sync.aligned.m8n8.x4.trans.shared.b16 {%0,%1,%2,%3}, [%4];"
                 : "=r"(r[0]), "=r"(r[1]), "=r"(r[2]), "=r"(r[3]) : "r"(addr));
}
__device__ __forceinline__ void mma16816(float* c, const uint32_t* a, const uint32_t* b) {
    asm volatile(
        "mma.sync.aligned.m16n8k16.row.col.f32.f16.f16.f32 "
        "{%0,%1,%2,%3}, {%4,%5,%6,%7}, {%8,%9}, {%0,%1,%2,%3};"
        : "+f"(c[0]), "+f"(c[1]), "+f"(c[2]), "+f"(c[3])
        : "r"(a[0]), "r"(a[1]), "r"(a[2]), "r"(a[3]), "r"(b[0]), "r"(b[1]));
}
__device__ __forceinline__ void cpasync16(uint32_t saddr, const void* gaddr) {
    asm volatile("cp.async.cg.shared.global [%0], [%1], 16;" :: "r"(saddr), "l"(gaddr) : "memory");
}
__device__ __forceinline__ void sts32(uint32_t addr, uint32_t v) {
    asm volatile("st.shared.b32 [%0], %1;" :: "r"(addr), "r"(v) : "memory");
}
__device__ __forceinline__ void sts64(uint32_t addr, float a, float b) {
    asm volatile("st.shared.v2.f32 [%0], {%1,%2};" :: "r"(addr), "f"(a), "f"(b) : "memory");
}
__device__ __forceinline__ uint4 lds128(uint32_t addr) {
    uint4 v;
    asm volatile("ld.shared.v4.b32 {%0,%1,%2,%3}, [%4];"
                 : "=r"(v.x), "=r"(v.y), "=r"(v.z), "=r"(v.w) : "r"(addr));
    return v;
}
__device__ __forceinline__ void split2h(float a, float b, uint32_t& hu, uint32_t& lu) {
    __half ha = __float2half_rn(a), hb = __float2half_rn(b);
    float ra = a - __half2float(ha), rb = b - __half2float(hb);
    __half2 H = __halves2half2(ha, hb);
    __half2 L = __floats2half2_rn(ra, rb);
    memcpy(&hu, &H, 4); memcpy(&lu, &L, 4);
}
__device__ __forceinline__ uint32_t pack2h(float a, float b) {
    __half2 H = __floats2half2_rn(a, b);
    uint32_t u; memcpy(&u, &H, 4); return u;
}

// ---------------- fp32 -> fp16 convert -------------------------------------
struct alignas(8) h16x4 { __half2 a, b; };

__global__ __launch_bounds__(256) void convert_kernel(
    const float* __restrict__ in, __half* __restrict__ out, int n4)
{
    int i = blockIdx.x * 256 + threadIdx.x;
    if (i >= n4) return;
    float4 v = ((const float4*)in)[i];
    h16x4 H;
    H.a = __floats2half2_rn(v.x, v.y);
    H.b = __floats2half2_rn(v.z, v.w);
    ((h16x4*)out)[i] = H;
}

__global__ __launch_bounds__(256) void tsingle_kernel(
    const float* __restrict__ W, __half* __restrict__ out, int K, int N)
{
    __shared__ float s[32][33];
    const int n0 = blockIdx.x * 32, k0 = blockIdx.y * 32;
    const int tx = threadIdx.x & 31, ty = threadIdx.x >> 5;
    #pragma unroll
    for (int i = 0; i < 4; i++)
        s[ty + 8 * i][tx] = W[(size_t)(k0 + ty + 8 * i) * N + n0 + tx];
    __syncthreads();
    #pragma unroll
    for (int i = 0; i < 4; i++) {
        int r = ty + 8 * i;
        out[(size_t)(n0 + r) * K + k0 + tx] = __float2half_rn(s[tx][r]);
    }
}

// ---------------- fp16 1-term mma GEMM, 3-stage pipeline -------------------
#define GK_CH   (K_SZ / 32)
#define GT_TILE 10240                  // 128 rows * 80 B
#define GT_STG  (2 * GT_TILE)          // A, B per stage
#define GT_SMEM 69632                  // 3 stages = 61440; epilogue caps at 69632

// Q pre-scale: 1/sqrt(64) * log2(e)
#define QSCALE (0.125f * 1.44269504088896f)

template<int MODE>
__global__ __launch_bounds__(128) void gemm_mma_kernel(
    const __half* __restrict__ A, const __half* __restrict__ B,
    const float* __restrict__ bias, float* __restrict__ C, int N,
    __half* __restrict__ qh, __half* __restrict__ ql,
    __half* __restrict__ kk, __half* __restrict__ vv)
{
    extern __shared__ char smraw[];
    const uint32_t sbase = smem_u32(smraw);

    const int tid = threadIdx.x;
    const int wid = tid >> 5, lane = tid & 31;
    const int wm = wid & 1, wn = wid >> 1;
    const int g = lane >> 2, t = lane & 3;
    const int row0 = blockIdx.y << 7;
    const int col0 = blockIdx.x << 7;

    const __half* srcs[2] = {A, B};

    auto load_part = [&](int c, int s, int arr) {
        const int k0 = c << 5;
        const __half* src = srcs[arr];
        const int rbase = (arr == 0) ? row0 : col0;
        const uint32_t tb = sbase + (uint32_t)s * GT_STG + (uint32_t)arr * GT_TILE;
        #pragma unroll
        for (int it = 0; it < 4; it++) {
            int id = it * 128 + tid, r = id >> 2, q = id & 3;
            cpasync16(tb + (uint32_t)(r * 80 + q * 16),
                      src + (size_t)(rbase + r) * K_SZ + k0 + q * 8);
        }
    };

    float acc[4][8][4] = {};
    const int a_row = lane & 15;
    const int a_cb  = (lane >> 4) << 4;
    const int b2_row = (lane & 7) + ((lane >> 4) << 3);
    const int b2_cb  = ((lane >> 3) & 1) << 4;

    // prologue: chunks 0 and 1 in flight (separate groups)
    load_part(0, 0, 0); load_part(0, 0, 1);
    asm volatile("cp.async.commit_group;" ::: "memory");
    load_part(1, 1, 0); load_part(1, 1, 1);
    asm volatile("cp.async.commit_group;" ::: "memory");

    int stage = 0;
    for (int c = 0; c < GK_CH; c++) {
        asm volatile("cp.async.wait_group 1;" ::: "memory");   // chunk c ready; c+1 may fly
        __syncthreads();

        const uint32_t stg = sbase + (uint32_t)stage * GT_STG;
        const uint32_t tA = stg, tB = stg + GT_TILE;
        const bool more = (c + 2 < GK_CH);
        const int ws = (stage + 2 >= 3) ? stage - 1 : stage + 2;   // (c+2) % 3

        #pragma unroll
        for (int ks = 0; ks < 2; ks++) {
            const int kb = ks << 5;
            uint32_t af[4][4], bf[4][4];
            #pragma unroll
            for (int mt = 0; mt < 4; mt++)
                ldsm4(af[mt], tA + (uint32_t)((wm * 64 + mt * 16 + a_row) * 80 + kb + a_cb));
            #pragma unroll
            for (int np = 0; np < 4; np++)
                ldsm4(bf[np], tB + (uint32_t)((wn * 64 + np * 16 + b2_row) * 80 + kb + b2_cb));
            if (more) load_part(c + 2, ws, ks);   // issue next-next chunk loads
            #pragma unroll
            for (int np = 0; np < 4; np++)
                #pragma unroll
                for (int mt = 0; mt < 4; mt++) {
                    mma16816(acc[mt][2 * np],     af[mt], &bf[np][0]);
                    mma16816(acc[mt][2 * np + 1], af[mt], &bf[np][2]);
                }
        }
        asm volatile("cp.async.commit_group;" ::: "memory");
        stage++; if (stage == 3) stage = 0;
    }
    asm volatile("cp.async.wait_group 0;" ::: "memory");
    __syncthreads();

    if (MODE == 1) {
        const int slice = col0 >> 10;
        const uint32_t hi0 = sbase, lo0 = sbase + 128 * 272;
        #pragma unroll
        for (int mt = 0; mt < 4; mt++) {
            const int rl = wm * 64 + mt * 16 + g;
            #pragma unroll
            for (int nt = 0; nt < 8; nt++) {
                const int cl = wn * 64 + nt * 8 + 2 * t;
                const int col = col0 + cl;
                const float b0 = bias[col], b1 = bias[col + 1];
                float v0 = acc[mt][nt][0] + b0, v1 = acc[mt][nt][1] + b1;
                float v2 = acc[mt][nt][2] + b0, v3 = acc[mt][nt][3] + b1;
                if (slice == 0) {
                    v0 *= QSCALE; v1 *= QSCALE; v2 *= QSCALE; v3 *= QSCALE;
                    uint32_t hu, lu;
                    split2h(v0, v1, hu, lu);
                    sts32(hi0 + (uint32_t)(rl * 272 + cl * 2), hu);
                    sts32(lo0 + (uint32_t)(rl * 272 + cl * 2), lu);
                    split2h(v2, v3, hu, lu);
                    sts32(hi0 + (uint32_t)((rl + 8) * 272 + cl * 2), hu);
                    sts32(lo0 + (uint32_t)((rl + 8) * 272 + cl * 2), lu);
                } else {
                    sts32(hi0 + (uint32_t)(rl * 272 + cl * 2), pack2h(v0, v1));
                    sts32(hi0 + (uint32_t)((rl + 8) * 272 + cl * 2), pack2h(v2, v3));
                }
            }
        }
        __syncthreads();
        #pragma unroll
        for (int it = 0; it < 16; it++) {
            const int id = it * 128 + tid, r = id >> 4, s = id & 15;
            const int col = col0 + s * 8;
            const int hh = (col >> 6) & 15, dd = col & 63;
            __half* oh = (slice == 0) ? qh : (slice == 1) ? kk : vv;
            const int row = row0 + r;
            const int ba = row >> 11, pa = row & 2047;
            const size_t oa = ((size_t)(ba * H_SZ + hh) * P_SZ + pa) * 64 + dd;
            uint4 vh4 = lds128(hi0 + (uint32_t)(r * 272 + s * 16));
            *(uint4*)(oh + oa) = vh4;
            if (slice == 0) {
                uint4 vl4 = lds128(lo0 + (uint32_t)(r * 272 + s * 16));
                *(uint4*)(ql + oa) = vl4;
            }
        }
    } else {
        #pragma unroll
        for (int mt = 0; mt < 4; mt++) {
            const int rl = wm * 64 + mt * 16 + g;
            #pragma unroll
            for (int nt = 0; nt < 8; nt++) {
                const int cl = wn * 64 + nt * 8 + 2 * t;
                const int col = col0 + cl;
                const float b0 = bias[col], b1 = bias[col + 1];
                sts64(sbase + (uint32_t)(rl * 528 + cl * 4),
                      acc[mt][nt][0] + b0, acc[mt][nt][1] + b1);
                sts64(sbase + (uint32_t)((rl + 8) * 528 + cl * 4),
                      acc[mt][nt][2] + b0, acc[mt][nt][3] + b1);
            }
        }
        __syncthreads();
        #pragma unroll
        for (int it = 0; it < 32; it++) {
            const int id = it * 128 + tid, r = id >> 5, s = id & 31;
            uint4 v = lds128(sbase + (uint32_t)(r * 528 + s * 16));
            *(uint4*)(C + (size_t)(row0 + r) * N + col0 + s * 4) = v;
        }
    }
}

// ---------------- fp16 flash attention: S 2-term, PV 1-term ----------------
#define AT_ROWB 144
#define AT_QTILE (128 * AT_ROWB)         // 18432
#define AT_KTILE (64 * AT_ROWB)          // 9216
#define AT_STG   (2 * AT_KTILE)          // 18432 (K, V)
#define AT_SMEM  (2 * AT_QTILE + AT_STG) // 55296

__global__ __launch_bounds__(128) void attn_mma_kernel(
    const __half* __restrict__ qh, const __half* __restrict__ ql,
    const __half* __restrict__ kk, const __half* __restrict__ vv,
    __half* __restrict__ z)
{
    extern __shared__ char smraw[];
    const uint32_t sb = smem_u32(smraw);
    const int tid = threadIdx.x, w = tid >> 5, lane = tid & 31;
    const int g = lane >> 2, t = lane & 3;
    const int qt = blockIdx.x, bh = blockIdx.y;
    const int q0 = qt << 7;
    const size_t hb = (size_t)bh * P_SZ * 64;

    const __half* kvsrc[2] = {kk + hb, vv + hb};
    auto stage_base = [&](int s) -> uint32_t {
        return (s == 0) ? sb + 2 * AT_QTILE : sb;
    };
    auto load_kv_part = [&](int kvt, int s, int a) {
        const uint32_t stg = stage_base(s);
        const size_t rb = (size_t)(kvt << 6) * 64;
        #pragma unroll
        for (int it = 0; it < 4; it++) {
            int id = it * 128 + tid, r = id >> 3, c = id & 7;
            cpasync16(stg + (uint32_t)(a * AT_KTILE + r * AT_ROWB + c * 16),
                      kvsrc[a] + rb + r * 64 + c * 8);
        }
    };

    {
        const __half* Qh = qh + hb + (size_t)q0 * 64;
        const __half* Ql = ql + hb + (size_t)q0 * 64;
        #pragma unroll
        for (int it = 0; it < 8; it++) {
            int id = it * 128 + tid, r = id >> 3, c = id & 7;
            cpasync16(sb + (uint32_t)(r * AT_ROWB + c * 16), Qh + r * 64 + c * 8);
            cpasync16(sb + AT_QTILE + (uint32_t)(r * AT_ROWB + c * 16), Ql + r * 64 + c * 8);
        }
    }
    load_kv_part(0, 0, 0);
    load_kv_part(0, 0, 1);
    asm volatile("cp.async.commit_group;" ::: "memory");
    asm volatile("cp.async.wait_group 0;" ::: "memory");
    __syncthreads();

    uint32_t qhf[2][4][4], qlf[2][4][4];
    const int arow = (lane & 7) + ((lane >> 3) & 1) * 8;
    const int achk = lane >> 4;
    #pragma unroll
    for (int mt = 0; mt < 2; mt++)
        #pragma unroll
        for (int ks = 0; ks < 4; ks++) {
            uint32_t ad = sb + (uint32_t)((32 * w + 16 * mt + arow) * AT_ROWB +
                                          (2 * ks + achk) * 16);
            ldsm4(qhf[mt][ks], ad);
            ldsm4(qlf[mt][ks], ad + AT_QTILE);
        }
    __syncthreads();

    float oacc[2][8][4] = {};
    float mrow[2][2], lrow[2][2];
    #pragma unroll
    for (int mt = 0; mt < 2; mt++) {
        mrow[mt][0] = -1e30f; mrow[mt][1] = -1e30f;
        lrow[mt][0] = 0.f;    lrow[mt][1] = 0.f;
    }
    const int wrow_min = q0 + 32 * w;
    const int wrow_max = wrow_min + 31;
    const int ntiles = 2 * qt + 2;

    for (int kvt = 0; kvt < ntiles; kvt++) {
        const int s = kvt & 1, ns = s ^ 1;
        if (kvt > 0) {
            asm volatile("cp.async.wait_group 0;" ::: "memory");
            __syncthreads();
        }
        const bool more = (kvt + 1 < ntiles);
        const int c_base = kvt << 6;
        if (c_base <= wrow_max) {
            const uint32_t kb = stage_base(s);

            float sacc[2][8][4] = {};
            uint32_t kf[2][2][4];
            #pragma unroll
            for (int cp = 0; cp < 2; cp++) {
                uint32_t ad = kb + (uint32_t)((lane & 7) * AT_ROWB + (4 * cp + (lane >> 3)) * 16);
                ldsm4(kf[0][cp], ad);
            }
            #pragma unroll
            for (int j = 0; j < 8; j++) {
                const int cur = j & 1, nxt = cur ^ 1;
                if (j < 7) {
                    #pragma unroll
                    for (int cp = 0; cp < 2; cp++) {
                        uint32_t ad = kb + (uint32_t)((8 * (j + 1) + (lane & 7)) * AT_ROWB +
                                                      (4 * cp + (lane >> 3)) * 16);
                        ldsm4(kf[nxt][cp], ad);
                    }
                }
                #pragma unroll
                for (int cp = 0; cp < 2; cp++)
                    #pragma unroll
                    for (int mt = 0; mt < 2; mt++) {
                        mma16816(sacc[mt][j], qhf[mt][2 * cp],     &kf[cur][cp][0]);
                        mma16816(sacc[mt][j], qhf[mt][2 * cp + 1], &kf[cur][cp][2]);
                    }
                #pragma unroll
                for (int cp = 0; cp < 2; cp++)
                    #pragma unroll
                    for (int mt = 0; mt < 2; mt++) {
                        mma16816(sacc[mt][j], qlf[mt][2 * cp],     &kf[cur][cp][0]);
                        mma16816(sacc[mt][j], qlf[mt][2 * cp + 1], &kf[cur][cp][2]);
                    }
            }
            if (more) load_kv_part(kvt + 1, ns, 0);

            if (c_base + 63 > wrow_min) {
                #pragma unroll
                for (int mt = 0; mt < 2; mt++) {
                    const int lr0 = wrow_min + 16 * mt + g;
                    #pragma unroll
                    for (int j = 0; j < 8; j++) {
                        const int c0 = c_base + 8 * j + 2 * t;
                        if (c0     > lr0)     sacc[mt][j][0] = -1e30f;
                        if (c0 + 1 > lr0)     sacc[mt][j][1] = -1e30f;
                        if (c0     > lr0 + 8) sacc[mt][j][2] = -1e30f;
                        if (c0 + 1 > lr0 + 8) sacc[mt][j][3] = -1e30f;
                    }
                }
            }

            #pragma unroll
            for (int mt = 0; mt < 2; mt++) {
                float mx0 = -1e30f, mx1 = -1e30f;
                #pragma unroll
                for (int j = 0; j < 8; j++) {
                    mx0 = fmaxf(mx0, fmaxf(sacc[mt][j][0], sacc[mt][j][1]));
                    mx1 = fmaxf(mx1, fmaxf(sacc[mt][j][2], sacc[mt][j][3]));
                }
                mx0 = fmaxf(mx0, __shfl_xor_sync(0xffffffffu, mx0, 1));
                mx0 = fmaxf(mx0, __shfl_xor_sync(0xffffffffu, mx0, 2));
                mx1 = fmaxf(mx1, __shfl_xor_sync(0xffffffffu, mx1, 1));
                mx1 = fmaxf(mx1, __shfl_xor_sync(0xffffffffu, mx1, 2));
                const float mn0 = fmaxf(mrow[mt][0], mx0), mn1 = fmaxf(mrow[mt][1], mx1);
                const float al0 = exp2f(mrow[mt][0] - mn0), al1 = exp2f(mrow[mt][1] - mn1);
                float sum0 = 0.f, sum1 = 0.f;
                #pragma unroll
                for (int j = 0; j < 8; j++) {
                    sacc[mt][j][0] = exp2f(sacc[mt][j][0] - mn0);
                    sacc[mt][j][1] = exp2f(sacc[mt][j][1] - mn0);
                    sacc[mt][j][2] = exp2f(sacc[mt][j][2] - mn1);
                    sacc[mt][j][3] = exp2f(sacc[mt][j][3] - mn1);
                    sum0 += sacc[mt][j][0] + sacc[mt][j][1];
                    sum1 += sacc[mt][j][2] + sacc[mt][j][3];
                }
                sum0 += __shfl_xor_sync(0xffffffffu, sum0, 1);
                sum0 += __shfl_xor_sync(0xffffffffu, sum0, 2);
                sum1 += __shfl_xor_sync(0xffffffffu, sum1, 1);
                sum1 += __shfl_xor_sync(0xffffffffu, sum1, 2);
                lrow[mt][0] = lrow[mt][0] * al0 + sum0; mrow[mt][0] = mn0;
                lrow[mt][1] = lrow[mt][1] * al1 + sum1; mrow[mt][1] = mn1;
                #pragma unroll
                for (int j = 0; j < 8; j++) {
                    oacc[mt][j][0] *= al0; oacc[mt][j][1] *= al0;
                    oacc[mt][j][2] *= al1; oacc[mt][j][3] *= al1;
                }
            }

            #pragma unroll
            for (int s2 = 0; s2 < 4; s2++) {
                uint32_t pf[2][4];
                #pragma unroll
                for (int mt = 0; mt < 2; mt++) {
                    pf[mt][0] = pack2h(sacc[mt][2 * s2][0],     sacc[mt][2 * s2][1]);
                    pf[mt][1] = pack2h(sacc[mt][2 * s2][2],     sacc[mt][2 * s2][3]);
                    pf[mt][2] = pack2h(sacc[mt][2 * s2 + 1][0], sacc[mt][2 * s2 + 1][1]);
                    pf[mt][3] = pack2h(sacc[mt][2 * s2 + 1][2], sacc[mt][2 * s2 + 1][3]);
                }
                uint32_t vf[4][4];
                #pragma unroll
                for (int jp = 0; jp < 4; jp++) {
                    uint32_t ad = kb + AT_KTILE +
                        (uint32_t)((16 * s2 + (lane & 15)) * AT_ROWB + (2 * jp + (lane >> 4)) * 16);
                    ldsm4t(vf[jp], ad);
                }
                #pragma unroll
                for (int jp = 0; jp < 4; jp++)
                    #pragma unroll
                    for (int mt = 0; mt < 2; mt++) {
                        mma16816(oacc[mt][2 * jp],     pf[mt], &vf[jp][0]);
                        mma16816(oacc[mt][2 * jp + 1], pf[mt], &vf[jp][2]);
                    }
                if (more && s2 == 1) load_kv_part(kvt + 1, ns, 1);
            }
        } else if (more) {
            load_kv_part(kvt + 1, ns, 0);
            load_kv_part(kvt + 1, ns, 1);
        }
        asm volatile("cp.async.commit_group;" ::: "memory");
    }
    __syncthreads();

    const uint32_t oh0 = sb;
    #pragma unroll
    for (int mt = 0; mt < 2; mt++) {
        const float i0 = 1.f / lrow[mt][0], i1 = 1.f / lrow[mt][1];
        const int rl = 32 * w + 16 * mt + g;
        #pragma unroll
        for (int j = 0; j < 8; j++) {
            const int cl = 8 * j + 2 * t;
            sts32(oh0 + (uint32_t)(rl * AT_ROWB + cl * 2),
                  pack2h(oacc[mt][j][0] * i0, oacc[mt][j][1] * i0));
            sts32(oh0 + (uint32_t)((rl + 8) * AT_ROWB + cl * 2),
                  pack2h(oacc[mt][j][2] * i1, oacc[mt][j][3] * i1));
        }
    }
    __syncthreads();
    const int b = bh >> 4, h = bh & 15;
    #pragma unroll
    for (int it = 0; it < 8; it++) {
        const int id = it * 128 + tid, r = id >> 3, s = id & 7;
        const size_t dst = ((size_t)b * P_SZ + q0 + r) * K_SZ + h * 64 + s * 8;
        uint4 vh4 = lds128(oh0 + (uint32_t)(r * AT_ROWB + s * 16));
        *(uint4*)(z + dst) = vh4;
    }
}

// ---------------------------------------------------------------------------
extern "C" void kernel_launch(void* const* d_in, const int* in_sizes, int n_in,
                              void* d_out, int out_size)
{
    (void)in_sizes; (void)n_in; (void)out_size;
    const float* x      = (const float*)d_in[0];
    const float* W_attn = (const float*)d_in[1];
    const float* b_attn = (const float*)d_in[2];
    const float* W_proj = (const float*)d_in[3];
    const float* b_proj = (const float*)d_in[4];
    float* out = (float*)d_out;

    __half *xh, *wa, *wp, *qh, *ql, *kk, *vv, *zz;
    cudaGetSymbolAddress((void**)&xh, g_xh);
    cudaGetSymbolAddress((void**)&wa, g_wa);
    cudaGetSymbolAddress((void**)&wp, g_wp);
    cudaGetSymbolAddress((void**)&qh, g_qh);
    cudaGetSymbolAddress((void**)&ql, g_ql);
    cudaGetSymbolAddress((void**)&kk, g_k);
    cudaGetSymbolAddress((void**)&vv, g_v);
    cudaGetSymbolAddress((void**)&zz, g_z);

    cudaFuncSetAttribute(gemm_mma_kernel<0>,
                         cudaFuncAttributeMaxDynamicSharedMemorySize, GT_SMEM);
    cudaFuncSetAttribute(gemm_mma_kernel<1>,
                         cudaFuncAttributeMaxDynamicSharedMemorySize, GT_SMEM);
    cudaFuncSetAttribute(attn_mma_kernel,
                         cudaFuncAttributeMaxDynamicSharedMemorySize, AT_SMEM);

    convert_kernel<<<(R_SZ * K_SZ / 4 + 255) / 256, 256>>>(x, xh, R_SZ * K_SZ / 4);
    tsingle_kernel<<<dim3(N3_SZ / 32, K_SZ / 32), 256>>>(W_attn, wa, K_SZ, N3_SZ);
    tsingle_kernel<<<dim3(M_SZ / 32, K_SZ / 32), 256>>>(W_proj, wp, K_SZ, M_SZ);

    gemm_mma_kernel<1><<<dim3(N3_SZ / 128, R_SZ / 128), 128, GT_SMEM>>>(
        xh, wa, b_attn, nullptr, N3_SZ, qh, ql, kk, vv);

    attn_mma_kernel<<<dim3(P_SZ / 128, BH_SZ), 128, AT_SMEM>>>(
        qh, ql, kk, vv, zz);

    gemm_mma_kernel<0><<<dim3(M_SZ / 128, R_SZ / 128), 128, GT_SMEM>>>(
        zz, wp, b_proj, out, M_SZ,
        nullptr, nullptr, nullptr, nullptr);
}